// round 7
// baseline (speedup 1.0000x reference)
#include <cuda_runtime.h>
#include <cuda_bf16.h>
#include <cstdint>
#include <math.h>

#define Bn 4
#define Sn 2048
#define Dn 1024
#define Hn 16
#define DHn 64
#define Mn (Bn * Sn)   // 8192

// ---------------------------------------------------------------------------
// Device scratch
// ---------------------------------------------------------------------------
__device__ float g_AO[Mn * Dn];

__device__ __nv_bfloat16 g_hA_hi[Mn * Dn];
__device__ __nv_bfloat16 g_hA_lo[Mn * Dn];
__device__ __nv_bfloat16 g_W_hi[4 * Dn * Dn];   // transposed [N,K], order q,k,v,o
__device__ __nv_bfloat16 g_W_lo[4 * Dn * Dn];

__device__ __nv_bfloat16 g_Qh[Mn * Dn];  // pre-scaled by 0.125*log2(e)
__device__ __nv_bfloat16 g_Ql[Mn * Dn];
__device__ __nv_bfloat16 g_Kh[Mn * Dn];
__device__ __nv_bfloat16 g_Kl[Mn * Dn];
__device__ __nv_bfloat16 g_Vh[Mn * Dn];
__device__ __nv_bfloat16 g_Vl[Mn * Dn];
__device__ __nv_bfloat16 g_AVh[Mn * Dn];
__device__ __nv_bfloat16 g_AVl[Mn * Dn];

// ---------------------------------------------------------------------------
__device__ __forceinline__ uint32_t smem_u32(const void* p) {
    uint32_t a;
    asm("{ .reg .u64 t; cvta.to.shared.u64 t, %1; cvt.u32.u64 %0, t; }"
        : "=r"(a) : "l"(p));
    return a;
}

__device__ __forceinline__ void ldm_x4(uint32_t* r, uint32_t addr) {
    asm volatile("ldmatrix.sync.aligned.m8n8.x4.shared.b16 {%0,%1,%2,%3}, [%4];"
                 : "=r"(r[0]), "=r"(r[1]), "=r"(r[2]), "=r"(r[3]) : "r"(addr));
}
__device__ __forceinline__ void ldm_x4t(uint32_t* r, uint32_t addr) {
    asm volatile("ldmatrix.sync.aligned.m8n8.x4.trans.shared.b16 {%0,%1,%2,%3}, [%4];"
                 : "=r"(r[0]), "=r"(r[1]), "=r"(r[2]), "=r"(r[3]) : "r"(addr));
}

__device__ __forceinline__ void mma_bf16(float* c, const uint32_t* a,
                                         uint32_t b0, uint32_t b1) {
    asm volatile(
        "mma.sync.aligned.m16n8k16.row.col.f32.bf16.bf16.f32 "
        "{%0,%1,%2,%3}, {%4,%5,%6,%7}, {%8,%9}, {%0,%1,%2,%3};"
        : "+f"(c[0]), "+f"(c[1]), "+f"(c[2]), "+f"(c[3])
        : "r"(a[0]), "r"(a[1]), "r"(a[2]), "r"(a[3]), "r"(b0), "r"(b1));
}

__device__ __forceinline__ uint32_t pack_bf16x2(float lo, float hi) {
    uint32_t d;
    asm("cvt.rn.bf16x2.f32 %0, %1, %2;" : "=r"(d) : "f"(hi), "f"(lo));
    return d;
}

__device__ __forceinline__ void cp16(uint32_t s, const void* g) {
    asm volatile("cp.async.cg.shared.global [%0], [%1], 16;" :: "r"(s), "l"(g));
}
#define CP_COMMIT() asm volatile("cp.async.commit_group;" ::: "memory")
#define CP_WAIT0()  asm volatile("cp.async.wait_group 0;" ::: "memory")
#define CP_WAIT1()  asm volatile("cp.async.wait_group 1;" ::: "memory")

// ---------------------------------------------------------------------------
// Split fp32 -> (hi, lo) bf16 pair, elementwise.
// ---------------------------------------------------------------------------
__global__ __launch_bounds__(256) void split_f32(
    const float* __restrict__ x, __nv_bfloat16* __restrict__ hi,
    __nv_bfloat16* __restrict__ lo)
{
    const int i = (blockIdx.x * 256 + threadIdx.x) * 4;
    float4 v = *(const float4*)(x + i);
    __nv_bfloat16 h0 = __float2bfloat16(v.x);
    __nv_bfloat16 h1 = __float2bfloat16(v.y);
    __nv_bfloat16 h2 = __float2bfloat16(v.z);
    __nv_bfloat16 h3 = __float2bfloat16(v.w);
    __nv_bfloat16 l0 = __float2bfloat16(v.x - __bfloat162float(h0));
    __nv_bfloat16 l1 = __float2bfloat16(v.y - __bfloat162float(h1));
    __nv_bfloat16 l2 = __float2bfloat16(v.z - __bfloat162float(h2));
    __nv_bfloat16 l3 = __float2bfloat16(v.w - __bfloat162float(h3));
    __nv_bfloat162* hp = (__nv_bfloat162*)(hi + i);
    __nv_bfloat162* lp = (__nv_bfloat162*)(lo + i);
    hp[0] = __nv_bfloat162(h0, h1); hp[1] = __nv_bfloat162(h2, h3);
    lp[0] = __nv_bfloat162(l0, l1); lp[1] = __nv_bfloat162(l2, l3);
}

// ---------------------------------------------------------------------------
// Split + transpose all 4 weights (blockIdx.z selects): fp32 [K,N] -> bf16 [N,K]
// ---------------------------------------------------------------------------
__global__ __launch_bounds__(256) void split_T4(
    const float* __restrict__ W0, const float* __restrict__ W1,
    const float* __restrict__ W2, const float* __restrict__ W3,
    __nv_bfloat16* __restrict__ hiT, __nv_bfloat16* __restrict__ loT)
{
    const int z = blockIdx.z;
    const float* W = (z == 0) ? W0 : (z == 1) ? W1 : (z == 2) ? W2 : W3;
    __nv_bfloat16* hi = hiT + (size_t)z * Dn * Dn;
    __nv_bfloat16* lo = loT + (size_t)z * Dn * Dn;

    __shared__ float t[32][33];
    const int tx = threadIdx.x, ty = threadIdx.y;
    const int bn = blockIdx.x * 32, bk = blockIdx.y * 32;
#pragma unroll
    for (int j = 0; j < 4; j++)
        t[ty + j * 8][tx] = W[(size_t)(bk + ty + j * 8) * Dn + bn + tx];
    __syncthreads();
#pragma unroll
    for (int j = 0; j < 4; j++) {
        float v = t[tx][ty + j * 8];
        __nv_bfloat16 h = __float2bfloat16(v);
        __nv_bfloat16 l = __float2bfloat16(v - __bfloat162float(h));
        size_t o = (size_t)(bn + ty + j * 8) * Dn + bk + tx;
        hi[o] = h;
        lo[o] = l;
    }
}

// ---------------------------------------------------------------------------
// GEMM mainloop (mma.sync bf16-split, cp.async double buffer, 2 CTAs/SM).
// EPI = 0: fp32 output C.  EPI = 1: hi/lo bf16 split output (scaled).
// 128x128 CTA tile, 8 warps (2M x 4N), 64x32 per warp, BK=32.
// ---------------------------------------------------------------------------
#define BK        32
#define NSTAGE    (Dn / BK)          // 32
#define ROW_B     80                 // bytes per smem row (32 bf16 + 8 pad)
#define ARR_SZ    (128 * ROW_B)      // 10240 bytes per array tile
#define BUF_SZ    (4 * ARR_SZ)
#define GEMM_SMEM (2 * BUF_SZ)       // 81920 -> 2 CTAs/SM

template <int EPI>
__device__ __forceinline__ void gemm_body(
    const __nv_bfloat16* __restrict__ Ahi, const __nv_bfloat16* __restrict__ Alo,
    const __nv_bfloat16* __restrict__ Bhi, const __nv_bfloat16* __restrict__ Blo,
    float* __restrict__ C,
    __nv_bfloat16* __restrict__ Chi, __nv_bfloat16* __restrict__ Clo, float scale)
{
    extern __shared__ char smem[];
    const uint32_t sb = smem_u32(smem);
    const int tid  = threadIdx.x;
    const int wid  = tid >> 5;
    const int lane = tid & 31;
    const int m0 = blockIdx.y * 128;
    const int n0 = blockIdx.x * 128;
    const int m0w = (wid & 1) * 64;
    const int n0w = (wid >> 1) * 32;

    const char* src[4] = {(const char*)Ahi, (const char*)Alo,
                          (const char*)Bhi, (const char*)Blo};

    const int r0c = tid >> 2;
    const int c16 = tid & 3;
    size_t goff[4][2];
#pragma unroll
    for (int arr = 0; arr < 4; arr++) {
        const int tb = (arr < 2) ? m0 : n0;
#pragma unroll
        for (int it = 0; it < 2; it++)
            goff[arr][it] = (size_t)(tb + r0c + it * 64) * 2048 + c16 * 16;
    }
    const uint32_t soff0 = r0c * ROW_B + c16 * 16;
    const uint32_t soff1 = (r0c + 64) * ROW_B + c16 * 16;

    float acc[4][4][4];
#pragma unroll
    for (int i = 0; i < 4; i++)
#pragma unroll
        for (int j = 0; j < 4; j++)
#pragma unroll
            for (int k = 0; k < 4; k++) acc[i][j][k] = 0.f;

    const int lrow = lane & 15;
    const int lch  = lane >> 4;
    const uint32_t a_lbase = (uint32_t)(m0w + lrow) * ROW_B + lch * 16;
    const uint32_t b_lbase = (uint32_t)(n0w + lrow) * ROW_B + lch * 16;

    // Preload stage 0 via cp.async
#pragma unroll
    for (int arr = 0; arr < 4; arr++) {
        cp16(sb + arr * ARR_SZ + soff0, src[arr] + goff[arr][0]);
        cp16(sb + arr * ARR_SZ + soff1, src[arr] + goff[arr][1]);
    }
    CP_COMMIT();
    CP_WAIT0();
    __syncthreads();

    for (int kc = 0; kc < NSTAGE; kc++) {
        const int cb = kc & 1;

        // Prefetch next stage into other buffer (overlaps with compute below)
        if (kc + 1 < NSTAGE) {
            const size_t kb = (size_t)(kc + 1) * 64;
            const uint32_t db = sb + (cb ^ 1) * BUF_SZ;
#pragma unroll
            for (int arr = 0; arr < 4; arr++) {
                cp16(db + arr * ARR_SZ + soff0, src[arr] + goff[arr][0] + kb);
                cp16(db + arr * ARR_SZ + soff1, src[arr] + goff[arr][1] + kb);
            }
            CP_COMMIT();
        }

        const uint32_t bufb = sb + cb * BUF_SZ;
#pragma unroll
        for (int ks = 0; ks < 2; ks++) {
#pragma unroll
            for (int t = 0; t < 3; t++) {
                const int aArr = (t == 2) ? 1 : 0;
                const int bArr = (t == 1) ? 3 : 2;
                uint32_t afr[4][4];
#pragma unroll
                for (int mi = 0; mi < 4; mi++)
                    ldm_x4(afr[mi], bufb + aArr * ARR_SZ + a_lbase
                                      + mi * (16 * ROW_B) + ks * 32);
                uint32_t bfr[2][4];
#pragma unroll
                for (int ni = 0; ni < 2; ni++)
                    ldm_x4(bfr[ni], bufb + bArr * ARR_SZ + b_lbase
                                      + ni * (16 * ROW_B) + ks * 32);
#pragma unroll
                for (int mi = 0; mi < 4; mi++) {
#pragma unroll
                    for (int ni = 0; ni < 2; ni++) {
                        mma_bf16(acc[mi][ni * 2 + 0], afr[mi], bfr[ni][0], bfr[ni][2]);
                        mma_bf16(acc[mi][ni * 2 + 1], afr[mi], bfr[ni][1], bfr[ni][3]);
                    }
                }
            }
        }

        CP_WAIT0();
        __syncthreads();
    }

    // Epilogue
    const int erow = lane >> 2;
    const int ecol = (lane & 3) * 2;
#pragma unroll
    for (int mi = 0; mi < 4; mi++) {
#pragma unroll
        for (int nj = 0; nj < 4; nj++) {
            size_t base0 = (size_t)(m0 + m0w + mi * 16 + erow) * Dn
                         + n0 + n0w + nj * 8 + ecol;
            if (EPI == 0) {
                *(float2*)(C + base0)          = make_float2(acc[mi][nj][0], acc[mi][nj][1]);
                *(float2*)(C + base0 + 8 * Dn) = make_float2(acc[mi][nj][2], acc[mi][nj][3]);
            } else {
#pragma unroll
                for (int half = 0; half < 2; half++) {
                    size_t b = base0 + half * 8 * Dn;
                    float v0 = acc[mi][nj][half * 2 + 0] * scale;
                    float v1 = acc[mi][nj][half * 2 + 1] * scale;
                    __nv_bfloat16 h0 = __float2bfloat16(v0);
                    __nv_bfloat16 h1 = __float2bfloat16(v1);
                    __nv_bfloat16 l0 = __float2bfloat16(v0 - __bfloat162float(h0));
                    __nv_bfloat16 l1 = __float2bfloat16(v1 - __bfloat162float(h1));
                    *(__nv_bfloat162*)(Chi + b) = __nv_bfloat162(h0, h1);
                    *(__nv_bfloat162*)(Clo + b) = __nv_bfloat162(l0, l1);
                }
            }
        }
    }
}

__global__ __launch_bounds__(256, 2) void gemm_mma(
    const __nv_bfloat16* __restrict__ Ahi, const __nv_bfloat16* __restrict__ Alo,
    const __nv_bfloat16* __restrict__ Bhi, const __nv_bfloat16* __restrict__ Blo,
    float* __restrict__ C)
{
    gemm_body<0>(Ahi, Alo, Bhi, Blo, C, nullptr, nullptr, 1.0f);
}

__global__ __launch_bounds__(256, 2) void gemm_mma_split(
    const __nv_bfloat16* __restrict__ Ahi, const __nv_bfloat16* __restrict__ Alo,
    const __nv_bfloat16* __restrict__ Bhi, const __nv_bfloat16* __restrict__ Blo,
    __nv_bfloat16* __restrict__ Chi, __nv_bfloat16* __restrict__ Clo, float scale)
{
    gemm_body<1>(Ahi, Alo, Bhi, Blo, nullptr, Chi, Clo, scale);
}

// ---------------------------------------------------------------------------
// Flash attention on mma.sync bf16 with hi/lo splits.
// Grid (16, 16, 4): 128 q-rows per CTA, 256 threads (8 warps x m16).
// K/V tiles (64 keys) in a 3-stage cp.async ring; one barrier per stage.
// Softmax in log2 domain (Q pre-scaled by 0.125*log2e) -> raw exp2f.
// ---------------------------------------------------------------------------
#define FROW 144
#define FARR (64 * FROW)          // 9216 (one 64x64 bf16 tile)
#define QARR (128 * FROW)         // 18432 (one 128x64 bf16 tile)
#define KVBUF (4 * FARR)          // Kh,Kl,Vh,Vl = 36864
#define FLASH_SMEM (2 * QARR + 3 * KVBUF)   // 147456

#define KV_PREFETCH(kt_, buf_) do {                                           \
    const uint32_t base_ = sb + 2 * QARR + (uint32_t)(buf_) * KVBUF;          \
    const size_t g0_ = (size_t)(bb * Sn + (kt_) * 64 + kr0) * Dn              \
                     + headoff + kch * 8;                                     \
    const size_t g1_ = g0_ + (size_t)32 * Dn;                                 \
    cp16(base_ + 0 * FARR + kso0, g_Kh + g0_);                                \
    cp16(base_ + 0 * FARR + kso1, g_Kh + g1_);                                \
    cp16(base_ + 1 * FARR + kso0, g_Kl + g0_);                                \
    cp16(base_ + 1 * FARR + kso1, g_Kl + g1_);                                \
    cp16(base_ + 2 * FARR + kso0, g_Vh + g0_);                                \
    cp16(base_ + 2 * FARR + kso1, g_Vh + g1_);                                \
    cp16(base_ + 3 * FARR + kso0, g_Vl + g0_);                                \
    cp16(base_ + 3 * FARR + kso1, g_Vl + g1_);                                \
    CP_COMMIT();                                                              \
} while (0)

__global__ __launch_bounds__(256) void flash_mma()
{
    extern __shared__ char sm[];
    const uint32_t sb = smem_u32(sm);
    const int tid = threadIdx.x;
    const int lane = tid & 31;
    const int w = tid >> 5;
    const int qt = blockIdx.x, hh = blockIdx.y, bb = blockIdx.z;

    const size_t headoff = (size_t)hh * 64;

    // K/V cp.async loader mapping
    const int kr0 = tid >> 3;           // rows 0..31
    const int kch = tid & 7;
    const uint32_t kso0 = (uint32_t)kr0 * FROW + kch * 16;
    const uint32_t kso1 = (uint32_t)(kr0 + 32) * FROW + kch * 16;

    // kick off KV stages 0 and 1
    KV_PREFETCH(0, 0);
    KV_PREFETCH(1, 1);

    // Load Q hi/lo tiles (128 x 64 bf16 each), plain stores (overlap with cp)
#pragma unroll
    for (int i = 0; i < 4; i++) {
        const int idx = tid + 256 * i;              // 0..1023
        const int r = idx >> 3, ch = idx & 7;
        const size_t g = (size_t)(bb * Sn + qt * 128 + r) * Dn + headoff + ch * 8;
        const uint32_t so = r * FROW + ch * 16;
        *(uint4*)(sm + so)        = *(const uint4*)(g_Qh + g);
        *(uint4*)(sm + QARR + so) = *(const uint4*)(g_Ql + g);
    }

    const int lrow = lane & 15;
    const int lch  = lane >> 4;
    const uint32_t aoff = (uint32_t)(w * 16 + lrow) * FROW + lch * 16;     // Q (A)
    uint32_t boff[4];
#pragma unroll
    for (int np = 0; np < 4; np++)
        boff[np] = (uint32_t)(np * 16 + lrow) * FROW + lch * 16;           // K (B)

    float o[8][4];
#pragma unroll
    for (int j = 0; j < 8; j++)
#pragma unroll
        for (int k = 0; k < 4; k++) o[j][k] = 0.f;
    float m0r = -1e30f, m1r = -1e30f, l0r = 0.f, l1r = 0.f;

    for (int kt = 0; kt < Sn / 64; kt++) {
        const int buf = kt % 3;
        if (kt + 1 < Sn / 64) { CP_WAIT1(); } else { CP_WAIT0(); }
        __syncthreads();                 // stage kt resident; prior compute done

        if (kt + 2 < Sn / 64)
            KV_PREFETCH(kt + 2, (kt + 2) % 3);

        const uint32_t kvb = sb + 2 * QARR + (uint32_t)buf * KVBUF;

        // ---- S = Q*K^T (3 split terms), n=64 keys ----
        float s[8][4];
#pragma unroll
        for (int j = 0; j < 8; j++)
#pragma unroll
            for (int k = 0; k < 4; k++) s[j][k] = 0.f;

#pragma unroll
        for (int ks = 0; ks < 4; ks++) {
            uint32_t qh[4], ql[4];
            ldm_x4(qh, sb + aoff + ks * 32);
            ldm_x4(ql, sb + QARR + aoff + ks * 32);
#pragma unroll
            for (int np = 0; np < 4; np++) {
                uint32_t kh[4], kl[4];
                ldm_x4(kh, kvb + 0 * FARR + boff[np] + ks * 32);
                ldm_x4(kl, kvb + 1 * FARR + boff[np] + ks * 32);
                mma_bf16(s[2 * np + 0], qh, kh[0], kh[2]);
                mma_bf16(s[2 * np + 1], qh, kh[1], kh[3]);
                mma_bf16(s[2 * np + 0], qh, kl[0], kl[2]);
                mma_bf16(s[2 * np + 1], qh, kl[1], kl[3]);
                mma_bf16(s[2 * np + 0], ql, kh[0], kh[2]);
                mma_bf16(s[2 * np + 1], ql, kh[1], kh[3]);
            }
        }

        // ---- Online softmax, log2 domain (rows lane/4 and lane/4+8) ----
        float mx0 = -1e30f, mx1 = -1e30f;
#pragma unroll
        for (int j = 0; j < 8; j++) {
            mx0 = fmaxf(mx0, fmaxf(s[j][0], s[j][1]));
            mx1 = fmaxf(mx1, fmaxf(s[j][2], s[j][3]));
        }
        mx0 = fmaxf(mx0, __shfl_xor_sync(0xffffffffu, mx0, 1));
        mx0 = fmaxf(mx0, __shfl_xor_sync(0xffffffffu, mx0, 2));
        mx1 = fmaxf(mx1, __shfl_xor_sync(0xffffffffu, mx1, 1));
        mx1 = fmaxf(mx1, __shfl_xor_sync(0xffffffffu, mx1, 2));

        const float mn0 = fmaxf(m0r, mx0);
        const float mn1 = fmaxf(m1r, mx1);
        const float a0 = exp2f(m0r - mn0);
        const float a1 = exp2f(m1r - mn1);
        m0r = mn0; m1r = mn1;

        uint32_t phi[8][2], plo[8][2];
        float sum0 = 0.f, sum1 = 0.f;
#pragma unroll
        for (int j = 0; j < 8; j++) {
            float p00 = exp2f(s[j][0] - mn0);
            float p01 = exp2f(s[j][1] - mn0);
            float p10 = exp2f(s[j][2] - mn1);
            float p11 = exp2f(s[j][3] - mn1);
            sum0 += p00 + p01;
            sum1 += p10 + p11;
            __nv_bfloat16 h00 = __float2bfloat16(p00);
            __nv_bfloat16 h01 = __float2bfloat16(p01);
            __nv_bfloat16 h10 = __float2bfloat16(p10);
            __nv_bfloat16 h11 = __float2bfloat16(p11);
            phi[j][0] = ((uint32_t)__bfloat16_as_ushort(h01) << 16)
                      |  (uint32_t)__bfloat16_as_ushort(h00);
            phi[j][1] = ((uint32_t)__bfloat16_as_ushort(h11) << 16)
                      |  (uint32_t)__bfloat16_as_ushort(h10);
            plo[j][0] = pack_bf16x2(p00 - __bfloat162float(h00),
                                    p01 - __bfloat162float(h01));
            plo[j][1] = pack_bf16x2(p10 - __bfloat162float(h10),
                                    p11 - __bfloat162float(h11));
        }
        sum0 += __shfl_xor_sync(0xffffffffu, sum0, 1);
        sum0 += __shfl_xor_sync(0xffffffffu, sum0, 2);
        sum1 += __shfl_xor_sync(0xffffffffu, sum1, 1);
        sum1 += __shfl_xor_sync(0xffffffffu, sum1, 2);
        l0r = l0r * a0 + sum0;
        l1r = l1r * a1 + sum1;

#pragma unroll
        for (int j = 0; j < 8; j++) {
            o[j][0] *= a0; o[j][1] *= a0;
            o[j][2] *= a1; o[j][3] *= a1;
        }

        // ---- O += P * V (3 split terms), V via ldmatrix.trans ----
#pragma unroll
        for (int ks = 0; ks < 4; ks++) {
            uint32_t ah[4] = {phi[2 * ks][0], phi[2 * ks][1],
                              phi[2 * ks + 1][0], phi[2 * ks + 1][1]};
            uint32_t al[4] = {plo[2 * ks][0], plo[2 * ks][1],
                              plo[2 * ks + 1][0], plo[2 * ks + 1][1]};
            const uint32_t vbase = (uint32_t)(ks * 16 + lrow) * FROW + lch * 16;
#pragma unroll
            for (int np = 0; np < 4; np++) {
                uint32_t vh[4], vl[4];
                ldm_x4t(vh, kvb + 2 * FARR + vbase + np * 32);
                ldm_x4t(vl, kvb + 3 * FARR + vbase + np * 32);
                mma_bf16(o[2 * np + 0], ah, vh[0], vh[1]);
                mma_bf16(o[2 * np + 1], ah, vh[2], vh[3]);
                mma_bf16(o[2 * np + 0], al, vh[0], vh[1]);
                mma_bf16(o[2 * np + 1], al, vh[2], vh[3]);
                mma_bf16(o[2 * np + 0], ah, vl[0], vl[1]);
                mma_bf16(o[2 * np + 1], ah, vl[2], vl[3]);
            }
        }
        // no trailing barrier: next iteration's top barrier protects the ring
    }

    // Epilogue: normalize, split to hi/lo bf16, write AV
    const float inv0 = 1.0f / l0r;
    const float inv1 = 1.0f / l1r;
    const size_t row0 = (size_t)(bb * Sn + qt * 128 + w * 16 + (lane >> 2));
    const size_t row1 = row0 + 8;
    const size_t colb = headoff + (lane & 3) * 2;
#pragma unroll
    for (int j = 0; j < 8; j++) {
        float v0 = o[j][0] * inv0, v1 = o[j][1] * inv0;
        float v2 = o[j][2] * inv1, v3 = o[j][3] * inv1;
        __nv_bfloat16 h0 = __float2bfloat16(v0);
        __nv_bfloat16 h1 = __float2bfloat16(v1);
        __nv_bfloat16 h2 = __float2bfloat16(v2);
        __nv_bfloat16 h3 = __float2bfloat16(v3);
        size_t b0 = row0 * Dn + colb + j * 8;
        size_t b1 = row1 * Dn + colb + j * 8;
        *(__nv_bfloat162*)(g_AVh + b0) = __nv_bfloat162(h0, h1);
        *(__nv_bfloat162*)(g_AVh + b1) = __nv_bfloat162(h2, h3);
        *(__nv_bfloat162*)(g_AVl + b0) =
            __nv_bfloat162(__float2bfloat16(v0 - __bfloat162float(h0)),
                           __float2bfloat16(v1 - __bfloat162float(h1)));
        *(__nv_bfloat162*)(g_AVl + b1) =
            __nv_bfloat162(__float2bfloat16(v2 - __bfloat162float(h2)),
                           __float2bfloat16(v3 - __bfloat162float(h3)));
    }
}

// ---------------------------------------------------------------------------
// Residual + LayerNorm
// ---------------------------------------------------------------------------
__global__ __launch_bounds__(256) void ln_residual(
    const float* __restrict__ h, const float* __restrict__ gamma,
    const float* __restrict__ beta, float* __restrict__ out)
{
    const int row = blockIdx.x;
    const int tid = threadIdx.x;

    const float4 hv = *(const float4*)(h + row * Dn + tid * 4);
    const float4 av = *(const float4*)(g_AO + row * Dn + tid * 4);
    float4 x = make_float4(hv.x + av.x, hv.y + av.y, hv.z + av.z, hv.w + av.w);

    float s  = x.x + x.y + x.z + x.w;
    float ss = x.x * x.x + x.y * x.y + x.z * x.z + x.w * x.w;
#pragma unroll
    for (int off = 16; off > 0; off >>= 1) {
        s  += __shfl_xor_sync(0xffffffffu, s, off);
        ss += __shfl_xor_sync(0xffffffffu, ss, off);
    }
    __shared__ float rs[8], rss[8];
    if ((tid & 31) == 0) { rs[tid >> 5] = s; rss[tid >> 5] = ss; }
    __syncthreads();
    s = 0.f; ss = 0.f;
#pragma unroll
    for (int w = 0; w < 8; w++) { s += rs[w]; ss += rss[w]; }

    const float mu  = s * (1.0f / Dn);
    const float var = ss * (1.0f / Dn) - mu * mu;
    const float inv = rsqrtf(var + 1e-5f);

    const float4 g4 = *(const float4*)(gamma + tid * 4);
    const float4 b4 = *(const float4*)(beta + tid * 4);
    float4 r;
    r.x = g4.x * (x.x - mu) * inv + b4.x;
    r.y = g4.y * (x.y - mu) * inv + b4.y;
    r.z = g4.z * (x.z - mu) * inv + b4.z;
    r.w = g4.w * (x.w - mu) * inv + b4.w;
    *(float4*)(out + row * Dn + tid * 4) = r;
}

// ---------------------------------------------------------------------------
extern "C" void kernel_launch(void* const* d_in, const int* in_sizes, int n_in,
                              void* d_out, int out_size)
{
    (void)in_sizes; (void)n_in; (void)out_size;
    const float* h     = (const float*)d_in[0];
    const float* Wq    = (const float*)d_in[1];
    const float* Wk    = (const float*)d_in[2];
    const float* Wv    = (const float*)d_in[3];
    const float* Wo    = (const float*)d_in[4];
    const float* gamma = (const float*)d_in[5];
    const float* beta  = (const float*)d_in[6];
    float* out = (float*)d_out;

    float* AOp;
    __nv_bfloat16 *hAhi, *hAlo, *Whi, *Wlo;
    __nv_bfloat16 *Qh, *Ql, *Kh, *Kl, *Vh, *Vl, *AVh, *AVl;
    cudaGetSymbolAddress((void**)&AOp,  g_AO);
    cudaGetSymbolAddress((void**)&hAhi, g_hA_hi);
    cudaGetSymbolAddress((void**)&hAlo, g_hA_lo);
    cudaGetSymbolAddress((void**)&Whi,  g_W_hi);
    cudaGetSymbolAddress((void**)&Wlo,  g_W_lo);
    cudaGetSymbolAddress((void**)&Qh,   g_Qh);
    cudaGetSymbolAddress((void**)&Ql,   g_Ql);
    cudaGetSymbolAddress((void**)&Kh,   g_Kh);
    cudaGetSymbolAddress((void**)&Kl,   g_Kl);
    cudaGetSymbolAddress((void**)&Vh,   g_Vh);
    cudaGetSymbolAddress((void**)&Vl,   g_Vl);
    cudaGetSymbolAddress((void**)&AVh,  g_AVh);
    cudaGetSymbolAddress((void**)&AVl,  g_AVl);

    cudaFuncSetAttribute(gemm_mma, cudaFuncAttributeMaxDynamicSharedMemorySize,
                         GEMM_SMEM);
    cudaFuncSetAttribute(gemm_mma_split, cudaFuncAttributeMaxDynamicSharedMemorySize,
                         GEMM_SMEM);
    cudaFuncSetAttribute(flash_mma, cudaFuncAttributeMaxDynamicSharedMemorySize,
                         FLASH_SMEM);

    // Split h and weights into bf16 hi/lo
    split_f32<<<Mn * Dn / 1024, 256>>>(h, hAhi, hAlo);
    split_T4<<<dim3(32, 32, 4), dim3(32, 8)>>>(Wq, Wk, Wv, Wo, Whi, Wlo);

    // Q/K/V projections -> hi/lo bf16 (Q pre-scaled by 1/8 * log2(e))
    const float QSCALE = 0.125f * 1.4426950408889634f;
    dim3 ggrid(Dn / 128, Mn / 128);
    gemm_mma_split<<<ggrid, 256, GEMM_SMEM>>>(hAhi, hAlo,
        Whi + 0 * (size_t)Dn * Dn, Wlo + 0 * (size_t)Dn * Dn, Qh, Ql, QSCALE);
    gemm_mma_split<<<ggrid, 256, GEMM_SMEM>>>(hAhi, hAlo,
        Whi + 1 * (size_t)Dn * Dn, Wlo + 1 * (size_t)Dn * Dn, Kh, Kl, 1.0f);
    gemm_mma_split<<<ggrid, 256, GEMM_SMEM>>>(hAhi, hAlo,
        Whi + 2 * (size_t)Dn * Dn, Wlo + 2 * (size_t)Dn * Dn, Vh, Vl, 1.0f);

    // Attention (tensorized flash, 3-stage KV pipeline)
    flash_mma<<<dim3(Sn / 128, Hn, Bn), 256, FLASH_SMEM>>>();

    // Output projection
    gemm_mma<<<ggrid, 256, GEMM_SMEM>>>(AVh, AVl,
        Whi + 3 * (size_t)Dn * Dn, Wlo + 3 * (size_t)Dn * Dn, AOp);

    ln_residual<<<Mn, 256>>>(h, gamma, beta, out);
}

// round 8
// speedup vs baseline: 1.0163x; 1.0163x over previous
#include <cuda_runtime.h>
#include <cuda_bf16.h>
#include <cstdint>
#include <math.h>

#define Bn 4
#define Sn 2048
#define Dn 1024
#define Hn 16
#define DHn 64
#define Mn (Bn * Sn)   // 8192

// ---------------------------------------------------------------------------
// Device scratch
// ---------------------------------------------------------------------------
__device__ float g_AO[Mn * Dn];

__device__ __nv_bfloat16 g_hA_hi[Mn * Dn];
__device__ __nv_bfloat16 g_hA_lo[Mn * Dn];
__device__ __nv_bfloat16 g_W_hi[4 * Dn * Dn];   // transposed [N,K], order q,k,v,o
__device__ __nv_bfloat16 g_W_lo[4 * Dn * Dn];

__device__ __nv_bfloat16 g_Qh[Mn * Dn];  // pre-scaled by 0.125*log2(e)
__device__ __nv_bfloat16 g_Ql[Mn * Dn];
__device__ __nv_bfloat16 g_Kh[Mn * Dn];
__device__ __nv_bfloat16 g_Kl[Mn * Dn];
__device__ __nv_bfloat16 g_Vh[Mn * Dn];
__device__ __nv_bfloat16 g_Vl[Mn * Dn];
__device__ __nv_bfloat16 g_AVh[Mn * Dn];
__device__ __nv_bfloat16 g_AVl[Mn * Dn];

// ---------------------------------------------------------------------------
__device__ __forceinline__ uint32_t smem_u32(const void* p) {
    uint32_t a;
    asm("{ .reg .u64 t; cvta.to.shared.u64 t, %1; cvt.u32.u64 %0, t; }"
        : "=r"(a) : "l"(p));
    return a;
}

__device__ __forceinline__ float fast_ex2(float x) {
    float r;
    asm("ex2.approx.ftz.f32 %0, %1;" : "=f"(r) : "f"(x));
    return r;
}

__device__ __forceinline__ void ldm_x4(uint32_t* r, uint32_t addr) {
    asm volatile("ldmatrix.sync.aligned.m8n8.x4.shared.b16 {%0,%1,%2,%3}, [%4];"
                 : "=r"(r[0]), "=r"(r[1]), "=r"(r[2]), "=r"(r[3]) : "r"(addr));
}
__device__ __forceinline__ void ldm_x4t(uint32_t* r, uint32_t addr) {
    asm volatile("ldmatrix.sync.aligned.m8n8.x4.trans.shared.b16 {%0,%1,%2,%3}, [%4];"
                 : "=r"(r[0]), "=r"(r[1]), "=r"(r[2]), "=r"(r[3]) : "r"(addr));
}

__device__ __forceinline__ void mma_bf16(float* c, const uint32_t* a,
                                         uint32_t b0, uint32_t b1) {
    asm volatile(
        "mma.sync.aligned.m16n8k16.row.col.f32.bf16.bf16.f32 "
        "{%0,%1,%2,%3}, {%4,%5,%6,%7}, {%8,%9}, {%0,%1,%2,%3};"
        : "+f"(c[0]), "+f"(c[1]), "+f"(c[2]), "+f"(c[3])
        : "r"(a[0]), "r"(a[1]), "r"(a[2]), "r"(a[3]), "r"(b0), "r"(b1));
}

__device__ __forceinline__ uint32_t pack_bf16x2(float lo, float hi) {
    uint32_t d;
    asm("cvt.rn.bf16x2.f32 %0, %1, %2;" : "=r"(d) : "f"(hi), "f"(lo));
    return d;
}

__device__ __forceinline__ void cp16(uint32_t s, const void* g) {
    asm volatile("cp.async.cg.shared.global [%0], [%1], 16;" :: "r"(s), "l"(g));
}
#define CP_COMMIT() asm volatile("cp.async.commit_group;" ::: "memory")
#define CP_WAIT0()  asm volatile("cp.async.wait_group 0;" ::: "memory")
#define CP_WAIT1()  asm volatile("cp.async.wait_group 1;" ::: "memory")

// ---------------------------------------------------------------------------
// Split fp32 -> (hi, lo) bf16 pair, elementwise.
// ---------------------------------------------------------------------------
__global__ __launch_bounds__(256) void split_f32(
    const float* __restrict__ x, __nv_bfloat16* __restrict__ hi,
    __nv_bfloat16* __restrict__ lo)
{
    const int i = (blockIdx.x * 256 + threadIdx.x) * 4;
    float4 v = *(const float4*)(x + i);
    __nv_bfloat16 h0 = __float2bfloat16(v.x);
    __nv_bfloat16 h1 = __float2bfloat16(v.y);
    __nv_bfloat16 h2 = __float2bfloat16(v.z);
    __nv_bfloat16 h3 = __float2bfloat16(v.w);
    __nv_bfloat16 l0 = __float2bfloat16(v.x - __bfloat162float(h0));
    __nv_bfloat16 l1 = __float2bfloat16(v.y - __bfloat162float(h1));
    __nv_bfloat16 l2 = __float2bfloat16(v.z - __bfloat162float(h2));
    __nv_bfloat16 l3 = __float2bfloat16(v.w - __bfloat162float(h3));
    __nv_bfloat162* hp = (__nv_bfloat162*)(hi + i);
    __nv_bfloat162* lp = (__nv_bfloat162*)(lo + i);
    hp[0] = __nv_bfloat162(h0, h1); hp[1] = __nv_bfloat162(h2, h3);
    lp[0] = __nv_bfloat162(l0, l1); lp[1] = __nv_bfloat162(l2, l3);
}

// ---------------------------------------------------------------------------
// Split + transpose all 4 weights (blockIdx.z selects): fp32 [K,N] -> bf16 [N,K]
// ---------------------------------------------------------------------------
__global__ __launch_bounds__(256) void split_T4(
    const float* __restrict__ W0, const float* __restrict__ W1,
    const float* __restrict__ W2, const float* __restrict__ W3,
    __nv_bfloat16* __restrict__ hiT, __nv_bfloat16* __restrict__ loT)
{
    const int z = blockIdx.z;
    const float* W = (z == 0) ? W0 : (z == 1) ? W1 : (z == 2) ? W2 : W3;
    __nv_bfloat16* hi = hiT + (size_t)z * Dn * Dn;
    __nv_bfloat16* lo = loT + (size_t)z * Dn * Dn;

    __shared__ float t[32][33];
    const int tx = threadIdx.x, ty = threadIdx.y;
    const int bn = blockIdx.x * 32, bk = blockIdx.y * 32;
#pragma unroll
    for (int j = 0; j < 4; j++)
        t[ty + j * 8][tx] = W[(size_t)(bk + ty + j * 8) * Dn + bn + tx];
    __syncthreads();
#pragma unroll
    for (int j = 0; j < 4; j++) {
        float v = t[tx][ty + j * 8];
        __nv_bfloat16 h = __float2bfloat16(v);
        __nv_bfloat16 l = __float2bfloat16(v - __bfloat162float(h));
        size_t o = (size_t)(bn + ty + j * 8) * Dn + bk + tx;
        hi[o] = h;
        lo[o] = l;
    }
}

// ---------------------------------------------------------------------------
// GEMM mainloop (mma.sync bf16-split, cp.async double buffer, 2 CTAs/SM).
// Fragment-hoisted: per k16-step load A_hi(4 ldm)+B_hi(2) -> term0,
// B_lo(2) -> term1 (A_hi reused), A_lo(4) -> term2 (B_hi reused).
// EPI = 0: fp32 output C.  EPI = 1: hi/lo bf16 split output (scaled).
// 128x128 CTA tile, 8 warps (2M x 4N), 64x32 per warp, BK=32.
// ---------------------------------------------------------------------------
#define BK        32
#define NSTAGE    (Dn / BK)          // 32
#define ROW_B     80                 // bytes per smem row (32 bf16 + 8 pad)
#define ARR_SZ    (128 * ROW_B)      // 10240 bytes per array tile
#define BUF_SZ    (4 * ARR_SZ)
#define GEMM_SMEM (2 * BUF_SZ)       // 81920 -> 2 CTAs/SM

template <int EPI>
__device__ __forceinline__ void gemm_body(
    const __nv_bfloat16* __restrict__ Ahi, const __nv_bfloat16* __restrict__ Alo,
    const __nv_bfloat16* __restrict__ Bhi, const __nv_bfloat16* __restrict__ Blo,
    float* __restrict__ C,
    __nv_bfloat16* __restrict__ Chi, __nv_bfloat16* __restrict__ Clo, float scale)
{
    extern __shared__ char smem[];
    const uint32_t sb = smem_u32(smem);
    const int tid  = threadIdx.x;
    const int wid  = tid >> 5;
    const int lane = tid & 31;
    const int m0 = blockIdx.y * 128;
    const int n0 = blockIdx.x * 128;
    const int m0w = (wid & 1) * 64;
    const int n0w = (wid >> 1) * 32;

    const char* src[4] = {(const char*)Ahi, (const char*)Alo,
                          (const char*)Bhi, (const char*)Blo};

    const int r0c = tid >> 2;
    const int c16 = tid & 3;
    size_t goff[4][2];
#pragma unroll
    for (int arr = 0; arr < 4; arr++) {
        const int tb = (arr < 2) ? m0 : n0;
#pragma unroll
        for (int it = 0; it < 2; it++)
            goff[arr][it] = (size_t)(tb + r0c + it * 64) * 2048 + c16 * 16;
    }
    const uint32_t soff0 = r0c * ROW_B + c16 * 16;
    const uint32_t soff1 = (r0c + 64) * ROW_B + c16 * 16;

    float acc[4][4][4];
#pragma unroll
    for (int i = 0; i < 4; i++)
#pragma unroll
        for (int j = 0; j < 4; j++)
#pragma unroll
            for (int k = 0; k < 4; k++) acc[i][j][k] = 0.f;

    const int lrow = lane & 15;
    const int lch  = lane >> 4;
    const uint32_t a_lbase = (uint32_t)(m0w + lrow) * ROW_B + lch * 16;
    const uint32_t b_lbase = (uint32_t)(n0w + lrow) * ROW_B + lch * 16;

    // Preload stage 0 via cp.async
#pragma unroll
    for (int arr = 0; arr < 4; arr++) {
        cp16(sb + arr * ARR_SZ + soff0, src[arr] + goff[arr][0]);
        cp16(sb + arr * ARR_SZ + soff1, src[arr] + goff[arr][1]);
    }
    CP_COMMIT();
    CP_WAIT0();
    __syncthreads();

    for (int kc = 0; kc < NSTAGE; kc++) {
        const int cb = kc & 1;

        // Prefetch next stage into other buffer (overlaps with compute below)
        if (kc + 1 < NSTAGE) {
            const size_t kb = (size_t)(kc + 1) * 64;
            const uint32_t db = sb + (cb ^ 1) * BUF_SZ;
#pragma unroll
            for (int arr = 0; arr < 4; arr++) {
                cp16(db + arr * ARR_SZ + soff0, src[arr] + goff[arr][0] + kb);
                cp16(db + arr * ARR_SZ + soff1, src[arr] + goff[arr][1] + kb);
            }
            CP_COMMIT();
        }

        const uint32_t bufb = sb + cb * BUF_SZ;
#pragma unroll
        for (int ks = 0; ks < 2; ks++) {
            // ---- load A_hi frags and B_hi frags ----
            uint32_t ah[4][4], bh[2][4];
#pragma unroll
            for (int mi = 0; mi < 4; mi++)
                ldm_x4(ah[mi], bufb + 0 * ARR_SZ + a_lbase
                                 + mi * (16 * ROW_B) + ks * 32);
#pragma unroll
            for (int ni = 0; ni < 2; ni++)
                ldm_x4(bh[ni], bufb + 2 * ARR_SZ + b_lbase
                                 + ni * (16 * ROW_B) + ks * 32);
            // term 0: A_hi x B_hi
#pragma unroll
            for (int mi = 0; mi < 4; mi++)
#pragma unroll
                for (int ni = 0; ni < 2; ni++) {
                    mma_bf16(acc[mi][ni * 2 + 0], ah[mi], bh[ni][0], bh[ni][2]);
                    mma_bf16(acc[mi][ni * 2 + 1], ah[mi], bh[ni][1], bh[ni][3]);
                }
            // term 1: A_hi x B_lo
            {
                uint32_t bl[2][4];
#pragma unroll
                for (int ni = 0; ni < 2; ni++)
                    ldm_x4(bl[ni], bufb + 3 * ARR_SZ + b_lbase
                                     + ni * (16 * ROW_B) + ks * 32);
#pragma unroll
                for (int mi = 0; mi < 4; mi++)
#pragma unroll
                    for (int ni = 0; ni < 2; ni++) {
                        mma_bf16(acc[mi][ni * 2 + 0], ah[mi], bl[ni][0], bl[ni][2]);
                        mma_bf16(acc[mi][ni * 2 + 1], ah[mi], bl[ni][1], bl[ni][3]);
                    }
            }
            // term 2: A_lo x B_hi (reuse bh)
            {
                uint32_t al[4][4];
#pragma unroll
                for (int mi = 0; mi < 4; mi++)
                    ldm_x4(al[mi], bufb + 1 * ARR_SZ + a_lbase
                                     + mi * (16 * ROW_B) + ks * 32);
#pragma unroll
                for (int mi = 0; mi < 4; mi++)
#pragma unroll
                    for (int ni = 0; ni < 2; ni++) {
                        mma_bf16(acc[mi][ni * 2 + 0], al[mi], bh[ni][0], bh[ni][2]);
                        mma_bf16(acc[mi][ni * 2 + 1], al[mi], bh[ni][1], bh[ni][3]);
                    }
            }
        }

        CP_WAIT0();
        __syncthreads();
    }

    // Epilogue
    const int erow = lane >> 2;
    const int ecol = (lane & 3) * 2;
#pragma unroll
    for (int mi = 0; mi < 4; mi++) {
#pragma unroll
        for (int nj = 0; nj < 4; nj++) {
            size_t base0 = (size_t)(m0 + m0w + mi * 16 + erow) * Dn
                         + n0 + n0w + nj * 8 + ecol;
            if (EPI == 0) {
                *(float2*)(C + base0)          = make_float2(acc[mi][nj][0], acc[mi][nj][1]);
                *(float2*)(C + base0 + 8 * Dn) = make_float2(acc[mi][nj][2], acc[mi][nj][3]);
            } else {
#pragma unroll
                for (int half = 0; half < 2; half++) {
                    size_t b = base0 + half * 8 * Dn;
                    float v0 = acc[mi][nj][half * 2 + 0] * scale;
                    float v1 = acc[mi][nj][half * 2 + 1] * scale;
                    __nv_bfloat16 h0 = __float2bfloat16(v0);
                    __nv_bfloat16 h1 = __float2bfloat16(v1);
                    __nv_bfloat16 l0 = __float2bfloat16(v0 - __bfloat162float(h0));
                    __nv_bfloat16 l1 = __float2bfloat16(v1 - __bfloat162float(h1));
                    *(__nv_bfloat162*)(Chi + b) = __nv_bfloat162(h0, h1);
                    *(__nv_bfloat162*)(Clo + b) = __nv_bfloat162(l0, l1);
                }
            }
        }
    }
}

__global__ __launch_bounds__(256, 2) void gemm_mma(
    const __nv_bfloat16* __restrict__ Ahi, const __nv_bfloat16* __restrict__ Alo,
    const __nv_bfloat16* __restrict__ Bhi, const __nv_bfloat16* __restrict__ Blo,
    float* __restrict__ C)
{
    gemm_body<0>(Ahi, Alo, Bhi, Blo, C, nullptr, nullptr, 1.0f);
}

__global__ __launch_bounds__(256, 2) void gemm_mma_split(
    const __nv_bfloat16* __restrict__ Ahi, const __nv_bfloat16* __restrict__ Alo,
    const __nv_bfloat16* __restrict__ Bhi, const __nv_bfloat16* __restrict__ Blo,
    __nv_bfloat16* __restrict__ Chi, __nv_bfloat16* __restrict__ Clo, float scale)
{
    gemm_body<1>(Ahi, Alo, Bhi, Blo, nullptr, Chi, Clo, scale);
}

// ---------------------------------------------------------------------------
// Flash attention on mma.sync bf16 with hi/lo splits.
// Grid (16, 16, 4): 128 q-rows per CTA, 256 threads (8 warps x m16).
// K/V tiles (64 keys) in a 3-stage cp.async ring; one barrier per stage.
// Softmax in log2 domain (Q pre-scaled by 0.125*log2e) -> MUFU ex2.approx.
// ---------------------------------------------------------------------------
#define FROW 144
#define FARR (64 * FROW)          // 9216 (one 64x64 bf16 tile)
#define QARR (128 * FROW)         // 18432 (one 128x64 bf16 tile)
#define KVBUF (4 * FARR)          // Kh,Kl,Vh,Vl = 36864
#define FLASH_SMEM (2 * QARR + 3 * KVBUF)   // 147456

#define KV_PREFETCH(kt_, buf_) do {                                           \
    const uint32_t base_ = sb + 2 * QARR + (uint32_t)(buf_) * KVBUF;          \
    const size_t g0_ = (size_t)(bb * Sn + (kt_) * 64 + kr0) * Dn              \
                     + headoff + kch * 8;                                     \
    const size_t g1_ = g0_ + (size_t)32 * Dn;                                 \
    cp16(base_ + 0 * FARR + kso0, g_Kh + g0_);                                \
    cp16(base_ + 0 * FARR + kso1, g_Kh + g1_);                                \
    cp16(base_ + 1 * FARR + kso0, g_Kl + g0_);                                \
    cp16(base_ + 1 * FARR + kso1, g_Kl + g1_);                                \
    cp16(base_ + 2 * FARR + kso0, g_Vh + g0_);                                \
    cp16(base_ + 2 * FARR + kso1, g_Vh + g1_);                                \
    cp16(base_ + 3 * FARR + kso0, g_Vl + g0_);                                \
    cp16(base_ + 3 * FARR + kso1, g_Vl + g1_);                                \
    CP_COMMIT();                                                              \
} while (0)

__global__ __launch_bounds__(256) void flash_mma()
{
    extern __shared__ char sm[];
    const uint32_t sb = smem_u32(sm);
    const int tid = threadIdx.x;
    const int lane = tid & 31;
    const int w = tid >> 5;
    const int qt = blockIdx.x, hh = blockIdx.y, bb = blockIdx.z;

    const size_t headoff = (size_t)hh * 64;

    // K/V cp.async loader mapping
    const int kr0 = tid >> 3;           // rows 0..31
    const int kch = tid & 7;
    const uint32_t kso0 = (uint32_t)kr0 * FROW + kch * 16;
    const uint32_t kso1 = (uint32_t)(kr0 + 32) * FROW + kch * 16;

    // kick off KV stages 0 and 1
    KV_PREFETCH(0, 0);
    KV_PREFETCH(1, 1);

    // Load Q hi/lo tiles (128 x 64 bf16 each), plain stores (overlap with cp)
#pragma unroll
    for (int i = 0; i < 4; i++) {
        const int idx = tid + 256 * i;              // 0..1023
        const int r = idx >> 3, ch = idx & 7;
        const size_t g = (size_t)(bb * Sn + qt * 128 + r) * Dn + headoff + ch * 8;
        const uint32_t so = r * FROW + ch * 16;
        *(uint4*)(sm + so)        = *(const uint4*)(g_Qh + g);
        *(uint4*)(sm + QARR + so) = *(const uint4*)(g_Ql + g);
    }

    const int lrow = lane & 15;
    const int lch  = lane >> 4;
    const uint32_t aoff = (uint32_t)(w * 16 + lrow) * FROW + lch * 16;     // Q (A)
    uint32_t boff[4];
#pragma unroll
    for (int np = 0; np < 4; np++)
        boff[np] = (uint32_t)(np * 16 + lrow) * FROW + lch * 16;           // K (B)

    float o[8][4];
#pragma unroll
    for (int j = 0; j < 8; j++)
#pragma unroll
        for (int k = 0; k < 4; k++) o[j][k] = 0.f;
    float m0r = -1e30f, m1r = -1e30f, l0r = 0.f, l1r = 0.f;

    for (int kt = 0; kt < Sn / 64; kt++) {
        const int buf = kt % 3;
        if (kt + 1 < Sn / 64) { CP_WAIT1(); } else { CP_WAIT0(); }
        __syncthreads();                 // stage kt resident; prior compute done

        if (kt + 2 < Sn / 64)
            KV_PREFETCH(kt + 2, (kt + 2) % 3);

        const uint32_t kvb = sb + 2 * QARR + (uint32_t)buf * KVBUF;

        // ---- S = Q*K^T (3 split terms), n=64 keys ----
        float s[8][4];
#pragma unroll
        for (int j = 0; j < 8; j++)
#pragma unroll
            for (int k = 0; k < 4; k++) s[j][k] = 0.f;

#pragma unroll
        for (int ks = 0; ks < 4; ks++) {
            uint32_t qh[4], ql[4];
            ldm_x4(qh, sb + aoff + ks * 32);
            ldm_x4(ql, sb + QARR + aoff + ks * 32);
#pragma unroll
            for (int np = 0; np < 4; np++) {
                uint32_t kh[4], kl[4];
                ldm_x4(kh, kvb + 0 * FARR + boff[np] + ks * 32);
                ldm_x4(kl, kvb + 1 * FARR + boff[np] + ks * 32);
                mma_bf16(s[2 * np + 0], qh, kh[0], kh[2]);
                mma_bf16(s[2 * np + 1], qh, kh[1], kh[3]);
                mma_bf16(s[2 * np + 0], qh, kl[0], kl[2]);
                mma_bf16(s[2 * np + 1], qh, kl[1], kl[3]);
                mma_bf16(s[2 * np + 0], ql, kh[0], kh[2]);
                mma_bf16(s[2 * np + 1], ql, kh[1], kh[3]);
            }
        }

        // ---- Online softmax, log2 domain (rows lane/4 and lane/4+8) ----
        float mx0 = -1e30f, mx1 = -1e30f;
#pragma unroll
        for (int j = 0; j < 8; j++) {
            mx0 = fmaxf(mx0, fmaxf(s[j][0], s[j][1]));
            mx1 = fmaxf(mx1, fmaxf(s[j][2], s[j][3]));
        }
        mx0 = fmaxf(mx0, __shfl_xor_sync(0xffffffffu, mx0, 1));
        mx0 = fmaxf(mx0, __shfl_xor_sync(0xffffffffu, mx0, 2));
        mx1 = fmaxf(mx1, __shfl_xor_sync(0xffffffffu, mx1, 1));
        mx1 = fmaxf(mx1, __shfl_xor_sync(0xffffffffu, mx1, 2));

        const float mn0 = fmaxf(m0r, mx0);
        const float mn1 = fmaxf(m1r, mx1);
        const float a0 = fast_ex2(m0r - mn0);
        const float a1 = fast_ex2(m1r - mn1);
        m0r = mn0; m1r = mn1;

        uint32_t phi[8][2], plo[8][2];
        float sum0 = 0.f, sum1 = 0.f;
#pragma unroll
        for (int j = 0; j < 8; j++) {
            float p00 = fast_ex2(s[j][0] - mn0);
            float p01 = fast_ex2(s[j][1] - mn0);
            float p10 = fast_ex2(s[j][2] - mn1);
            float p11 = fast_ex2(s[j][3] - mn1);
            sum0 += p00 + p01;
            sum1 += p10 + p11;
            __nv_bfloat16 h00 = __float2bfloat16(p00);
            __nv_bfloat16 h01 = __float2bfloat16(p01);
            __nv_bfloat16 h10 = __float2bfloat16(p10);
            __nv_bfloat16 h11 = __float2bfloat16(p11);
            phi[j][0] = ((uint32_t)__bfloat16_as_ushort(h01) << 16)
                      |  (uint32_t)__bfloat16_as_ushort(h00);
            phi[j][1] = ((uint32_t)__bfloat16_as_ushort(h11) << 16)
                      |  (uint32_t)__bfloat16_as_ushort(h10);
            plo[j][0] = pack_bf16x2(p00 - __bfloat162float(h00),
                                    p01 - __bfloat162float(h01));
            plo[j][1] = pack_bf16x2(p10 - __bfloat162float(h10),
                                    p11 - __bfloat162float(h11));
        }
        sum0 += __shfl_xor_sync(0xffffffffu, sum0, 1);
        sum0 += __shfl_xor_sync(0xffffffffu, sum0, 2);
        sum1 += __shfl_xor_sync(0xffffffffu, sum1, 1);
        sum1 += __shfl_xor_sync(0xffffffffu, sum1, 2);
        l0r = l0r * a0 + sum0;
        l1r = l1r * a1 + sum1;

#pragma unroll
        for (int j = 0; j < 8; j++) {
            o[j][0] *= a0; o[j][1] *= a0;
            o[j][2] *= a1; o[j][3] *= a1;
        }

        // ---- O += P * V (3 split terms), V via ldmatrix.trans ----
#pragma unroll
        for (int ks = 0; ks < 4; ks++) {
            uint32_t ah[4] = {phi[2 * ks][0], phi[2 * ks][1],
                              phi[2 * ks + 1][0], phi[2 * ks + 1][1]};
            uint32_t al[4] = {plo[2 * ks][0], plo[2 * ks][1],
                              plo[2 * ks + 1][0], plo[2 * ks + 1][1]};
            const uint32_t vbase = (uint32_t)(ks * 16 + lrow) * FROW + lch * 16;
#pragma unroll
            for (int np = 0; np < 4; np++) {
                uint32_t vh[4], vl[4];
                ldm_x4t(vh, kvb + 2 * FARR + vbase + np * 32);
                ldm_x4t(vl, kvb + 3 * FARR + vbase + np * 32);
                mma_bf16(o[2 * np + 0], ah, vh[0], vh[1]);
                mma_bf16(o[2 * np + 1], ah, vh[2], vh[3]);
                mma_bf16(o[2 * np + 0], al, vh[0], vh[1]);
                mma_bf16(o[2 * np + 1], al, vh[2], vh[3]);
                mma_bf16(o[2 * np + 0], ah, vl[0], vl[1]);
                mma_bf16(o[2 * np + 1], ah, vl[2], vl[3]);
            }
        }
        // no trailing barrier: next iteration's top barrier protects the ring
    }

    // Epilogue: normalize, split to hi/lo bf16, write AV
    const float inv0 = 1.0f / l0r;
    const float inv1 = 1.0f / l1r;
    const size_t row0 = (size_t)(bb * Sn + qt * 128 + w * 16 + (lane >> 2));
    const size_t row1 = row0 + 8;
    const size_t colb = headoff + (lane & 3) * 2;
#pragma unroll
    for (int j = 0; j < 8; j++) {
        float v0 = o[j][0] * inv0, v1 = o[j][1] * inv0;
        float v2 = o[j][2] * inv1, v3 = o[j][3] * inv1;
        __nv_bfloat16 h0 = __float2bfloat16(v0);
        __nv_bfloat16 h1 = __float2bfloat16(v1);
        __nv_bfloat16 h2 = __float2bfloat16(v2);
        __nv_bfloat16 h3 = __float2bfloat16(v3);
        size_t b0 = row0 * Dn + colb + j * 8;
        size_t b1 = row1 * Dn + colb + j * 8;
        *(__nv_bfloat162*)(g_AVh + b0) = __nv_bfloat162(h0, h1);
        *(__nv_bfloat162*)(g_AVh + b1) = __nv_bfloat162(h2, h3);
        *(__nv_bfloat162*)(g_AVl + b0) =
            __nv_bfloat162(__float2bfloat16(v0 - __bfloat162float(h0)),
                           __float2bfloat16(v1 - __bfloat162float(h1)));
        *(__nv_bfloat162*)(g_AVl + b1) =
            __nv_bfloat162(__float2bfloat16(v2 - __bfloat162float(h2)),
                           __float2bfloat16(v3 - __bfloat162float(h3)));
    }
}

// ---------------------------------------------------------------------------
// Residual + LayerNorm
// ---------------------------------------------------------------------------
__global__ __launch_bounds__(256) void ln_residual(
    const float* __restrict__ h, const float* __restrict__ gamma,
    const float* __restrict__ beta, float* __restrict__ out)
{
    const int row = blockIdx.x;
    const int tid = threadIdx.x;

    const float4 hv = *(const float4*)(h + row * Dn + tid * 4);
    const float4 av = *(const float4*)(g_AO + row * Dn + tid * 4);
    float4 x = make_float4(hv.x + av.x, hv.y + av.y, hv.z + av.z, hv.w + av.w);

    float s  = x.x + x.y + x.z + x.w;
    float ss = x.x * x.x + x.y * x.y + x.z * x.z + x.w * x.w;
#pragma unroll
    for (int off = 16; off > 0; off >>= 1) {
        s  += __shfl_xor_sync(0xffffffffu, s, off);
        ss += __shfl_xor_sync(0xffffffffu, ss, off);
    }
    __shared__ float rs[8], rss[8];
    if ((tid & 31) == 0) { rs[tid >> 5] = s; rss[tid >> 5] = ss; }
    __syncthreads();
    s = 0.f; ss = 0.f;
#pragma unroll
    for (int w = 0; w < 8; w++) { s += rs[w]; ss += rss[w]; }

    const float mu  = s * (1.0f / Dn);
    const float var = ss * (1.0f / Dn) - mu * mu;
    const float inv = rsqrtf(var + 1e-5f);

    const float4 g4 = *(const float4*)(gamma + tid * 4);
    const float4 b4 = *(const float4*)(beta + tid * 4);
    float4 r;
    r.x = g4.x * (x.x - mu) * inv + b4.x;
    r.y = g4.y * (x.y - mu) * inv + b4.y;
    r.z = g4.z * (x.z - mu) * inv + b4.z;
    r.w = g4.w * (x.w - mu) * inv + b4.w;
    *(float4*)(out + row * Dn + tid * 4) = r;
}

// ---------------------------------------------------------------------------
extern "C" void kernel_launch(void* const* d_in, const int* in_sizes, int n_in,
                              void* d_out, int out_size)
{
    (void)in_sizes; (void)n_in; (void)out_size;
    const float* h     = (const float*)d_in[0];
    const float* Wq    = (const float*)d_in[1];
    const float* Wk    = (const float*)d_in[2];
    const float* Wv    = (const float*)d_in[3];
    const float* Wo    = (const float*)d_in[4];
    const float* gamma = (const float*)d_in[5];
    const float* beta  = (const float*)d_in[6];
    float* out = (float*)d_out;

    float* AOp;
    __nv_bfloat16 *hAhi, *hAlo, *Whi, *Wlo;
    __nv_bfloat16 *Qh, *Ql, *Kh, *Kl, *Vh, *Vl, *AVh, *AVl;
    cudaGetSymbolAddress((void**)&AOp,  g_AO);
    cudaGetSymbolAddress((void**)&hAhi, g_hA_hi);
    cudaGetSymbolAddress((void**)&hAlo, g_hA_lo);
    cudaGetSymbolAddress((void**)&Whi,  g_W_hi);
    cudaGetSymbolAddress((void**)&Wlo,  g_W_lo);
    cudaGetSymbolAddress((void**)&Qh,   g_Qh);
    cudaGetSymbolAddress((void**)&Ql,   g_Ql);
    cudaGetSymbolAddress((void**)&Kh,   g_Kh);
    cudaGetSymbolAddress((void**)&Kl,   g_Kl);
    cudaGetSymbolAddress((void**)&Vh,   g_Vh);
    cudaGetSymbolAddress((void**)&Vl,   g_Vl);
    cudaGetSymbolAddress((void**)&AVh,  g_AVh);
    cudaGetSymbolAddress((void**)&AVl,  g_AVl);

    cudaFuncSetAttribute(gemm_mma, cudaFuncAttributeMaxDynamicSharedMemorySize,
                         GEMM_SMEM);
    cudaFuncSetAttribute(gemm_mma_split, cudaFuncAttributeMaxDynamicSharedMemorySize,
                         GEMM_SMEM);
    cudaFuncSetAttribute(flash_mma, cudaFuncAttributeMaxDynamicSharedMemorySize,
                         FLASH_SMEM);

    // Split h and weights into bf16 hi/lo
    split_f32<<<Mn * Dn / 1024, 256>>>(h, hAhi, hAlo);
    split_T4<<<dim3(32, 32, 4), dim3(32, 8)>>>(Wq, Wk, Wv, Wo, Whi, Wlo);

    // Q/K/V projections -> hi/lo bf16 (Q pre-scaled by 1/8 * log2(e))
    const float QSCALE = 0.125f * 1.4426950408889634f;
    dim3 ggrid(Dn / 128, Mn / 128);
    gemm_mma_split<<<ggrid, 256, GEMM_SMEM>>>(hAhi, hAlo,
        Whi + 0 * (size_t)Dn * Dn, Wlo + 0 * (size_t)Dn * Dn, Qh, Ql, QSCALE);
    gemm_mma_split<<<ggrid, 256, GEMM_SMEM>>>(hAhi, hAlo,
        Whi + 1 * (size_t)Dn * Dn, Wlo + 1 * (size_t)Dn * Dn, Kh, Kl, 1.0f);
    gemm_mma_split<<<ggrid, 256, GEMM_SMEM>>>(hAhi, hAlo,
        Whi + 2 * (size_t)Dn * Dn, Wlo + 2 * (size_t)Dn * Dn, Vh, Vl, 1.0f);

    // Attention (tensorized flash, 3-stage KV pipeline)
    flash_mma<<<dim3(Sn / 128, Hn, Bn), 256, FLASH_SMEM>>>();

    // Output projection
    gemm_mma<<<ggrid, 256, GEMM_SMEM>>>(AVh, AVl,
        Whi + 3 * (size_t)Dn * Dn, Wlo + 3 * (size_t)Dn * Dn, AOp);

    ln_residual<<<Mn, 256>>>(h, gamma, beta, out);
}

// round 9
// speedup vs baseline: 1.0925x; 1.0750x over previous
#include <cuda_runtime.h>
#include <cuda_bf16.h>
#include <cstdint>
#include <math.h>

#define Bn 4
#define Sn 2048
#define Dn 1024
#define Hn 16
#define DHn 64
#define Mn (Bn * Sn)   // 8192

// ---------------------------------------------------------------------------
// Device scratch
// ---------------------------------------------------------------------------
__device__ float g_AO[Mn * Dn];

__device__ __nv_bfloat16 g_hA_hi[Mn * Dn];
__device__ __nv_bfloat16 g_hA_lo[Mn * Dn];
__device__ __nv_bfloat16 g_W_hi[4 * Dn * Dn];   // transposed [N,K], order q,k,v,o
__device__ __nv_bfloat16 g_W_lo[4 * Dn * Dn];

__device__ __nv_bfloat16 g_Qh[Mn * Dn];  // pre-scaled by 0.125*log2(e)
__device__ __nv_bfloat16 g_Ql[Mn * Dn];
__device__ __nv_bfloat16 g_Kh[Mn * Dn];
__device__ __nv_bfloat16 g_Kl[Mn * Dn];
__device__ __nv_bfloat16 g_Vh[Mn * Dn];
__device__ __nv_bfloat16 g_Vl[Mn * Dn];
__device__ __nv_bfloat16 g_AVh[Mn * Dn];
__device__ __nv_bfloat16 g_AVl[Mn * Dn];

// ---------------------------------------------------------------------------
__device__ __forceinline__ uint32_t smem_u32(const void* p) {
    uint32_t a;
    asm("{ .reg .u64 t; cvta.to.shared.u64 t, %1; cvt.u32.u64 %0, t; }"
        : "=r"(a) : "l"(p));
    return a;
}

__device__ __forceinline__ float fast_ex2(float x) {
    float r;
    asm("ex2.approx.ftz.f32 %0, %1;" : "=f"(r) : "f"(x));
    return r;
}

__device__ __forceinline__ void ldm_x4(uint32_t* r, uint32_t addr) {
    asm volatile("ldmatrix.sync.aligned.m8n8.x4.shared.b16 {%0,%1,%2,%3}, [%4];"
                 : "=r"(r[0]), "=r"(r[1]), "=r"(r[2]), "=r"(r[3]) : "r"(addr));
}
__device__ __forceinline__ void ldm_x4t(uint32_t* r, uint32_t addr) {
    asm volatile("ldmatrix.sync.aligned.m8n8.x4.trans.shared.b16 {%0,%1,%2,%3}, [%4];"
                 : "=r"(r[0]), "=r"(r[1]), "=r"(r[2]), "=r"(r[3]) : "r"(addr));
}

__device__ __forceinline__ void mma_bf16(float* c, const uint32_t* a,
                                         uint32_t b0, uint32_t b1) {
    asm volatile(
        "mma.sync.aligned.m16n8k16.row.col.f32.bf16.bf16.f32 "
        "{%0,%1,%2,%3}, {%4,%5,%6,%7}, {%8,%9}, {%0,%1,%2,%3};"
        : "+f"(c[0]), "+f"(c[1]), "+f"(c[2]), "+f"(c[3])
        : "r"(a[0]), "r"(a[1]), "r"(a[2]), "r"(a[3]), "r"(b0), "r"(b1));
}

__device__ __forceinline__ uint32_t pack_bf16x2(float lo, float hi) {
    uint32_t d;
    asm("cvt.rn.bf16x2.f32 %0, %1, %2;" : "=r"(d) : "f"(hi), "f"(lo));
    return d;
}

__device__ __forceinline__ void cp16(uint32_t s, const void* g) {
    asm volatile("cp.async.cg.shared.global [%0], [%1], 16;" :: "r"(s), "l"(g));
}
#define CP_COMMIT() asm volatile("cp.async.commit_group;" ::: "memory")
#define CP_WAIT0()  asm volatile("cp.async.wait_group 0;" ::: "memory")

// ---------------------------------------------------------------------------
// Split fp32 -> (hi, lo) bf16 pair, elementwise.
// ---------------------------------------------------------------------------
__global__ __launch_bounds__(256) void split_f32(
    const float* __restrict__ x, __nv_bfloat16* __restrict__ hi,
    __nv_bfloat16* __restrict__ lo)
{
    const int i = (blockIdx.x * 256 + threadIdx.x) * 4;
    float4 v = *(const float4*)(x + i);
    __nv_bfloat16 h0 = __float2bfloat16(v.x);
    __nv_bfloat16 h1 = __float2bfloat16(v.y);
    __nv_bfloat16 h2 = __float2bfloat16(v.z);
    __nv_bfloat16 h3 = __float2bfloat16(v.w);
    __nv_bfloat16 l0 = __float2bfloat16(v.x - __bfloat162float(h0));
    __nv_bfloat16 l1 = __float2bfloat16(v.y - __bfloat162float(h1));
    __nv_bfloat16 l2 = __float2bfloat16(v.z - __bfloat162float(h2));
    __nv_bfloat16 l3 = __float2bfloat16(v.w - __bfloat162float(h3));
    __nv_bfloat162* hp = (__nv_bfloat162*)(hi + i);
    __nv_bfloat162* lp = (__nv_bfloat162*)(lo + i);
    hp[0] = __nv_bfloat162(h0, h1); hp[1] = __nv_bfloat162(h2, h3);
    lp[0] = __nv_bfloat162(l0, l1); lp[1] = __nv_bfloat162(l2, l3);
}

// ---------------------------------------------------------------------------
// Split + transpose all 4 weights (blockIdx.z selects): fp32 [K,N] -> bf16 [N,K]
// ---------------------------------------------------------------------------
__global__ __launch_bounds__(256) void split_T4(
    const float* __restrict__ W0, const float* __restrict__ W1,
    const float* __restrict__ W2, const float* __restrict__ W3,
    __nv_bfloat16* __restrict__ hiT, __nv_bfloat16* __restrict__ loT)
{
    const int z = blockIdx.z;
    const float* W = (z == 0) ? W0 : (z == 1) ? W1 : (z == 2) ? W2 : W3;
    __nv_bfloat16* hi = hiT + (size_t)z * Dn * Dn;
    __nv_bfloat16* lo = loT + (size_t)z * Dn * Dn;

    __shared__ float t[32][33];
    const int tx = threadIdx.x, ty = threadIdx.y;
    const int bn = blockIdx.x * 32, bk = blockIdx.y * 32;
#pragma unroll
    for (int j = 0; j < 4; j++)
        t[ty + j * 8][tx] = W[(size_t)(bk + ty + j * 8) * Dn + bn + tx];
    __syncthreads();
#pragma unroll
    for (int j = 0; j < 4; j++) {
        float v = t[tx][ty + j * 8];
        __nv_bfloat16 h = __float2bfloat16(v);
        __nv_bfloat16 l = __float2bfloat16(v - __bfloat162float(h));
        size_t o = (size_t)(bn + ty + j * 8) * Dn + bk + tx;
        hi[o] = h;
        lo[o] = l;
    }
}

// ---------------------------------------------------------------------------
// GEMM mainloop (mma.sync bf16-split, cp.async double buffer, 2 CTAs/SM).
// m0/n0 and output routing supplied by the wrapper.
// EPI = 0: fp32 output C.  EPI = 1: hi/lo bf16 split output (scaled).
// 128x128 CTA tile, 8 warps (2M x 4N), 64x32 per warp, BK=32.
// ---------------------------------------------------------------------------
#define BK        32
#define NSTAGE    (Dn / BK)          // 32
#define ROW_B     80                 // bytes per smem row (32 bf16 + 8 pad)
#define ARR_SZ    (128 * ROW_B)      // 10240 bytes per array tile
#define BUF_SZ    (4 * ARR_SZ)
#define GEMM_SMEM (2 * BUF_SZ)       // 81920 -> 2 CTAs/SM

template <int EPI>
__device__ __forceinline__ void gemm_body(
    const __nv_bfloat16* __restrict__ Ahi, const __nv_bfloat16* __restrict__ Alo,
    const __nv_bfloat16* __restrict__ Bhi, const __nv_bfloat16* __restrict__ Blo,
    float* __restrict__ C,
    __nv_bfloat16* __restrict__ Chi, __nv_bfloat16* __restrict__ Clo, float scale,
    int m0, int n0)
{
    extern __shared__ char smem[];
    const uint32_t sb = smem_u32(smem);
    const int tid  = threadIdx.x;
    const int wid  = tid >> 5;
    const int lane = tid & 31;
    const int m0w = (wid & 1) * 64;
    const int n0w = (wid >> 1) * 32;

    const char* src[4] = {(const char*)Ahi, (const char*)Alo,
                          (const char*)Bhi, (const char*)Blo};

    const int r0c = tid >> 2;
    const int c16 = tid & 3;
    size_t goff[4][2];
#pragma unroll
    for (int arr = 0; arr < 4; arr++) {
        const int tb = (arr < 2) ? m0 : n0;
#pragma unroll
        for (int it = 0; it < 2; it++)
            goff[arr][it] = (size_t)(tb + r0c + it * 64) * 2048 + c16 * 16;
    }
    const uint32_t soff0 = r0c * ROW_B + c16 * 16;
    const uint32_t soff1 = (r0c + 64) * ROW_B + c16 * 16;

    float acc[4][4][4];
#pragma unroll
    for (int i = 0; i < 4; i++)
#pragma unroll
        for (int j = 0; j < 4; j++)
#pragma unroll
            for (int k = 0; k < 4; k++) acc[i][j][k] = 0.f;

    const int lrow = lane & 15;
    const int lch  = lane >> 4;
    const uint32_t a_lbase = (uint32_t)(m0w + lrow) * ROW_B + lch * 16;
    const uint32_t b_lbase = (uint32_t)(n0w + lrow) * ROW_B + lch * 16;

    // Preload stage 0 via cp.async
#pragma unroll
    for (int arr = 0; arr < 4; arr++) {
        cp16(sb + arr * ARR_SZ + soff0, src[arr] + goff[arr][0]);
        cp16(sb + arr * ARR_SZ + soff1, src[arr] + goff[arr][1]);
    }
    CP_COMMIT();
    CP_WAIT0();
    __syncthreads();

    for (int kc = 0; kc < NSTAGE; kc++) {
        const int cb = kc & 1;

        // Prefetch next stage into other buffer (overlaps with compute below)
        if (kc + 1 < NSTAGE) {
            const size_t kb = (size_t)(kc + 1) * 64;
            const uint32_t db = sb + (cb ^ 1) * BUF_SZ;
#pragma unroll
            for (int arr = 0; arr < 4; arr++) {
                cp16(db + arr * ARR_SZ + soff0, src[arr] + goff[arr][0] + kb);
                cp16(db + arr * ARR_SZ + soff1, src[arr] + goff[arr][1] + kb);
            }
            CP_COMMIT();
        }

        const uint32_t bufb = sb + cb * BUF_SZ;
#pragma unroll
        for (int ks = 0; ks < 2; ks++) {
            uint32_t ah[4][4], bh[2][4];
#pragma unroll
            for (int mi = 0; mi < 4; mi++)
                ldm_x4(ah[mi], bufb + 0 * ARR_SZ + a_lbase
                                 + mi * (16 * ROW_B) + ks * 32);
#pragma unroll
            for (int ni = 0; ni < 2; ni++)
                ldm_x4(bh[ni], bufb + 2 * ARR_SZ + b_lbase
                                 + ni * (16 * ROW_B) + ks * 32);
            // term 0: A_hi x B_hi
#pragma unroll
            for (int mi = 0; mi < 4; mi++)
#pragma unroll
                for (int ni = 0; ni < 2; ni++) {
                    mma_bf16(acc[mi][ni * 2 + 0], ah[mi], bh[ni][0], bh[ni][2]);
                    mma_bf16(acc[mi][ni * 2 + 1], ah[mi], bh[ni][1], bh[ni][3]);
                }
            // term 1: A_hi x B_lo
            {
                uint32_t bl[2][4];
#pragma unroll
                for (int ni = 0; ni < 2; ni++)
                    ldm_x4(bl[ni], bufb + 3 * ARR_SZ + b_lbase
                                     + ni * (16 * ROW_B) + ks * 32);
#pragma unroll
                for (int mi = 0; mi < 4; mi++)
#pragma unroll
                    for (int ni = 0; ni < 2; ni++) {
                        mma_bf16(acc[mi][ni * 2 + 0], ah[mi], bl[ni][0], bl[ni][2]);
                        mma_bf16(acc[mi][ni * 2 + 1], ah[mi], bl[ni][1], bl[ni][3]);
                    }
            }
            // term 2: A_lo x B_hi (reuse bh)
            {
                uint32_t al[4][4];
#pragma unroll
                for (int mi = 0; mi < 4; mi++)
                    ldm_x4(al[mi], bufb + 1 * ARR_SZ + a_lbase
                                     + mi * (16 * ROW_B) + ks * 32);
#pragma unroll
                for (int mi = 0; mi < 4; mi++)
#pragma unroll
                    for (int ni = 0; ni < 2; ni++) {
                        mma_bf16(acc[mi][ni * 2 + 0], al[mi], bh[ni][0], bh[ni][2]);
                        mma_bf16(acc[mi][ni * 2 + 1], al[mi], bh[ni][1], bh[ni][3]);
                    }
            }
        }

        CP_WAIT0();
        __syncthreads();
    }

    // Epilogue
    const int erow = lane >> 2;
    const int ecol = (lane & 3) * 2;
#pragma unroll
    for (int mi = 0; mi < 4; mi++) {
#pragma unroll
        for (int nj = 0; nj < 4; nj++) {
            size_t base0 = (size_t)(m0 + m0w + mi * 16 + erow) * Dn
                         + n0 + n0w + nj * 8 + ecol;
            if (EPI == 0) {
                *(float2*)(C + base0)          = make_float2(acc[mi][nj][0], acc[mi][nj][1]);
                *(float2*)(C + base0 + 8 * Dn) = make_float2(acc[mi][nj][2], acc[mi][nj][3]);
            } else {
#pragma unroll
                for (int half = 0; half < 2; half++) {
                    size_t b = base0 + half * 8 * Dn;
                    float v0 = acc[mi][nj][half * 2 + 0] * scale;
                    float v1 = acc[mi][nj][half * 2 + 1] * scale;
                    __nv_bfloat16 h0 = __float2bfloat16(v0);
                    __nv_bfloat16 h1 = __float2bfloat16(v1);
                    __nv_bfloat16 l0 = __float2bfloat16(v0 - __bfloat162float(h0));
                    __nv_bfloat16 l1 = __float2bfloat16(v1 - __bfloat162float(h1));
                    *(__nv_bfloat162*)(Chi + b) = __nv_bfloat162(h0, h1);
                    *(__nv_bfloat162*)(Clo + b) = __nv_bfloat162(l0, l1);
                }
            }
        }
    }
}

// Fused Q/K/V projection: grid (24, 64); blockIdx.x selects weight + outputs.
__global__ __launch_bounds__(256, 2) void gemm_qkv(
    const __nv_bfloat16* __restrict__ Ahi, const __nv_bfloat16* __restrict__ Alo,
    const __nv_bfloat16* __restrict__ Whi, const __nv_bfloat16* __restrict__ Wlo,
    __nv_bfloat16* __restrict__ Qh, __nv_bfloat16* __restrict__ Ql,
    __nv_bfloat16* __restrict__ Kh, __nv_bfloat16* __restrict__ Kl,
    __nv_bfloat16* __restrict__ Vh, __nv_bfloat16* __restrict__ Vl,
    float qscale)
{
    const int ng   = blockIdx.x * 128;       // 0..3071
    const int wsel = ng >> 10;               // 0=Q, 1=K, 2=V
    const int n0   = ng & 1023;
    const __nv_bfloat16* Bhi = Whi + (size_t)wsel * Dn * Dn;
    const __nv_bfloat16* Blo = Wlo + (size_t)wsel * Dn * Dn;
    __nv_bfloat16 *Chi, *Clo;
    float sc;
    if (wsel == 0)      { Chi = Qh; Clo = Ql; sc = qscale; }
    else if (wsel == 1) { Chi = Kh; Clo = Kl; sc = 1.0f; }
    else                { Chi = Vh; Clo = Vl; sc = 1.0f; }
    gemm_body<1>(Ahi, Alo, Bhi, Blo, nullptr, Chi, Clo, sc,
                 blockIdx.y * 128, n0);
}

// O projection: fp32 output
__global__ __launch_bounds__(256, 2) void gemm_mma(
    const __nv_bfloat16* __restrict__ Ahi, const __nv_bfloat16* __restrict__ Alo,
    const __nv_bfloat16* __restrict__ Bhi, const __nv_bfloat16* __restrict__ Blo,
    float* __restrict__ C)
{
    gemm_body<0>(Ahi, Alo, Bhi, Blo, C, nullptr, nullptr, 1.0f,
                 blockIdx.y * 128, blockIdx.x * 128);
}

// ---------------------------------------------------------------------------
// Flash attention on mma.sync bf16 with hi/lo splits.
// Grid (16, 16, 4): 128 q-rows per CTA, 256 threads (8 warps x m16).
// K/V tiles (64 keys) double-buffered via cp.async (R6-proven loop shape).
// Softmax in log2 domain (Q pre-scaled by 0.125*log2e) -> MUFU ex2.approx.
// ---------------------------------------------------------------------------
#define FROW 144
#define FARR (64 * FROW)          // 9216 (one 64x64 bf16 tile)
#define QARR (128 * FROW)         // 18432 (one 128x64 bf16 tile)
#define KVBUF (4 * FARR)          // Kh,Kl,Vh,Vl = 36864
#define FLASH_SMEM (2 * QARR + 2 * KVBUF)   // 110592

#define KV_PREFETCH(kt_, buf_) do {                                           \
    const uint32_t base_ = sb + 2 * QARR + (uint32_t)(buf_) * KVBUF;          \
    const size_t g0_ = (size_t)(bb * Sn + (kt_) * 64 + kr0) * Dn              \
                     + headoff + kch * 8;                                     \
    const size_t g1_ = g0_ + (size_t)32 * Dn;                                 \
    cp16(base_ + 0 * FARR + kso0, g_Kh + g0_);                                \
    cp16(base_ + 0 * FARR + kso1, g_Kh + g1_);                                \
    cp16(base_ + 1 * FARR + kso0, g_Kl + g0_);                                \
    cp16(base_ + 1 * FARR + kso1, g_Kl + g1_);                                \
    cp16(base_ + 2 * FARR + kso0, g_Vh + g0_);                                \
    cp16(base_ + 2 * FARR + kso1, g_Vh + g1_);                                \
    cp16(base_ + 3 * FARR + kso0, g_Vl + g0_);                                \
    cp16(base_ + 3 * FARR + kso1, g_Vl + g1_);                                \
    CP_COMMIT();                                                              \
} while (0)

__global__ __launch_bounds__(256) void flash_mma()
{
    extern __shared__ char sm[];
    const uint32_t sb = smem_u32(sm);
    const int tid = threadIdx.x;
    const int lane = tid & 31;
    const int w = tid >> 5;
    const int qt = blockIdx.x, hh = blockIdx.y, bb = blockIdx.z;

    const size_t headoff = (size_t)hh * 64;

    // K/V cp.async loader mapping
    const int kr0 = tid >> 3;           // rows 0..31
    const int kch = tid & 7;
    const uint32_t kso0 = (uint32_t)kr0 * FROW + kch * 16;
    const uint32_t kso1 = (uint32_t)(kr0 + 32) * FROW + kch * 16;

    // kick off KV stage 0
    KV_PREFETCH(0, 0);

    // Load Q hi/lo tiles (128 x 64 bf16 each), plain stores (overlap with cp)
#pragma unroll
    for (int i = 0; i < 4; i++) {
        const int idx = tid + 256 * i;              // 0..1023
        const int r = idx >> 3, ch = idx & 7;
        const size_t g = (size_t)(bb * Sn + qt * 128 + r) * Dn + headoff + ch * 8;
        const uint32_t so = r * FROW + ch * 16;
        *(uint4*)(sm + so)        = *(const uint4*)(g_Qh + g);
        *(uint4*)(sm + QARR + so) = *(const uint4*)(g_Ql + g);
    }

    const int lrow = lane & 15;
    const int lch  = lane >> 4;
    const uint32_t aoff = (uint32_t)(w * 16 + lrow) * FROW + lch * 16;     // Q (A)
    uint32_t boff[4];
#pragma unroll
    for (int np = 0; np < 4; np++)
        boff[np] = (uint32_t)(np * 16 + lrow) * FROW + lch * 16;           // K (B)

    float o[8][4];
#pragma unroll
    for (int j = 0; j < 8; j++)
#pragma unroll
        for (int k = 0; k < 4; k++) o[j][k] = 0.f;
    float m0r = -1e30f, m1r = -1e30f, l0r = 0.f, l1r = 0.f;

    for (int kt = 0; kt < Sn / 64; kt++) {
        const int buf = kt & 1;
        CP_WAIT0();
        __syncthreads();

        // prefetch next tile into the other buffer (overlaps compute)
        if (kt + 1 < Sn / 64)
            KV_PREFETCH(kt + 1, buf ^ 1);

        const uint32_t kvb = sb + 2 * QARR + (uint32_t)buf * KVBUF;

        // ---- S = Q*K^T (3 split terms), n=64 keys ----
        float s[8][4];
#pragma unroll
        for (int j = 0; j < 8; j++)
#pragma unroll
            for (int k = 0; k < 4; k++) s[j][k] = 0.f;

#pragma unroll
        for (int ks = 0; ks < 4; ks++) {
            uint32_t qh[4], ql[4];
            ldm_x4(qh, sb + aoff + ks * 32);
            ldm_x4(ql, sb + QARR + aoff + ks * 32);
#pragma unroll
            for (int np = 0; np < 4; np++) {
                uint32_t kh[4], kl[4];
                ldm_x4(kh, kvb + 0 * FARR + boff[np] + ks * 32);
                ldm_x4(kl, kvb + 1 * FARR + boff[np] + ks * 32);
                mma_bf16(s[2 * np + 0], qh, kh[0], kh[2]);
                mma_bf16(s[2 * np + 1], qh, kh[1], kh[3]);
                mma_bf16(s[2 * np + 0], qh, kl[0], kl[2]);
                mma_bf16(s[2 * np + 1], qh, kl[1], kl[3]);
                mma_bf16(s[2 * np + 0], ql, kh[0], kh[2]);
                mma_bf16(s[2 * np + 1], ql, kh[1], kh[3]);
            }
        }

        // ---- Online softmax, log2 domain (rows lane/4 and lane/4+8) ----
        float mx0 = -1e30f, mx1 = -1e30f;
#pragma unroll
        for (int j = 0; j < 8; j++) {
            mx0 = fmaxf(mx0, fmaxf(s[j][0], s[j][1]));
            mx1 = fmaxf(mx1, fmaxf(s[j][2], s[j][3]));
        }
        mx0 = fmaxf(mx0, __shfl_xor_sync(0xffffffffu, mx0, 1));
        mx0 = fmaxf(mx0, __shfl_xor_sync(0xffffffffu, mx0, 2));
        mx1 = fmaxf(mx1, __shfl_xor_sync(0xffffffffu, mx1, 1));
        mx1 = fmaxf(mx1, __shfl_xor_sync(0xffffffffu, mx1, 2));

        const float mn0 = fmaxf(m0r, mx0);
        const float mn1 = fmaxf(m1r, mx1);
        const float a0 = fast_ex2(m0r - mn0);
        const float a1 = fast_ex2(m1r - mn1);
        m0r = mn0; m1r = mn1;

        uint32_t phi[8][2], plo[8][2];
        float sum0 = 0.f, sum1 = 0.f;
#pragma unroll
        for (int j = 0; j < 8; j++) {
            float p00 = fast_ex2(s[j][0] - mn0);
            float p01 = fast_ex2(s[j][1] - mn0);
            float p10 = fast_ex2(s[j][2] - mn1);
            float p11 = fast_ex2(s[j][3] - mn1);
            sum0 += p00 + p01;
            sum1 += p10 + p11;
            __nv_bfloat16 h00 = __float2bfloat16(p00);
            __nv_bfloat16 h01 = __float2bfloat16(p01);
            __nv_bfloat16 h10 = __float2bfloat16(p10);
            __nv_bfloat16 h11 = __float2bfloat16(p11);
            phi[j][0] = ((uint32_t)__bfloat16_as_ushort(h01) << 16)
                      |  (uint32_t)__bfloat16_as_ushort(h00);
            phi[j][1] = ((uint32_t)__bfloat16_as_ushort(h11) << 16)
                      |  (uint32_t)__bfloat16_as_ushort(h10);
            plo[j][0] = pack_bf16x2(p00 - __bfloat162float(h00),
                                    p01 - __bfloat162float(h01));
            plo[j][1] = pack_bf16x2(p10 - __bfloat162float(h10),
                                    p11 - __bfloat162float(h11));
        }
        sum0 += __shfl_xor_sync(0xffffffffu, sum0, 1);
        sum0 += __shfl_xor_sync(0xffffffffu, sum0, 2);
        sum1 += __shfl_xor_sync(0xffffffffu, sum1, 1);
        sum1 += __shfl_xor_sync(0xffffffffu, sum1, 2);
        l0r = l0r * a0 + sum0;
        l1r = l1r * a1 + sum1;

#pragma unroll
        for (int j = 0; j < 8; j++) {
            o[j][0] *= a0; o[j][1] *= a0;
            o[j][2] *= a1; o[j][3] *= a1;
        }

        // ---- O += P * V (3 split terms), V via ldmatrix.trans ----
#pragma unroll
        for (int ks = 0; ks < 4; ks++) {
            uint32_t ah[4] = {phi[2 * ks][0], phi[2 * ks][1],
                              phi[2 * ks + 1][0], phi[2 * ks + 1][1]};
            uint32_t al[4] = {plo[2 * ks][0], plo[2 * ks][1],
                              plo[2 * ks + 1][0], plo[2 * ks + 1][1]};
            const uint32_t vbase = (uint32_t)(ks * 16 + lrow) * FROW + lch * 16;
#pragma unroll
            for (int np = 0; np < 4; np++) {
                uint32_t vh[4], vl[4];
                ldm_x4t(vh, kvb + 2 * FARR + vbase + np * 32);
                ldm_x4t(vl, kvb + 3 * FARR + vbase + np * 32);
                mma_bf16(o[2 * np + 0], ah, vh[0], vh[1]);
                mma_bf16(o[2 * np + 1], ah, vh[2], vh[3]);
                mma_bf16(o[2 * np + 0], al, vh[0], vh[1]);
                mma_bf16(o[2 * np + 1], al, vh[2], vh[3]);
                mma_bf16(o[2 * np + 0], ah, vl[0], vl[1]);
                mma_bf16(o[2 * np + 1], ah, vl[2], vl[3]);
            }
        }
        __syncthreads();   // all warps done reading buf before next prefetch lands
    }

    // Epilogue: normalize, split to hi/lo bf16, write AV
    const float inv0 = 1.0f / l0r;
    const float inv1 = 1.0f / l1r;
    const size_t row0 = (size_t)(bb * Sn + qt * 128 + w * 16 + (lane >> 2));
    const size_t row1 = row0 + 8;
    const size_t colb = headoff + (lane & 3) * 2;
#pragma unroll
    for (int j = 0; j < 8; j++) {
        float v0 = o[j][0] * inv0, v1 = o[j][1] * inv0;
        float v2 = o[j][2] * inv1, v3 = o[j][3] * inv1;
        __nv_bfloat16 h0 = __float2bfloat16(v0);
        __nv_bfloat16 h1 = __float2bfloat16(v1);
        __nv_bfloat16 h2 = __float2bfloat16(v2);
        __nv_bfloat16 h3 = __float2bfloat16(v3);
        size_t b0 = row0 * Dn + colb + j * 8;
        size_t b1 = row1 * Dn + colb + j * 8;
        *(__nv_bfloat162*)(g_AVh + b0) = __nv_bfloat162(h0, h1);
        *(__nv_bfloat162*)(g_AVh + b1) = __nv_bfloat162(h2, h3);
        *(__nv_bfloat162*)(g_AVl + b0) =
            __nv_bfloat162(__float2bfloat16(v0 - __bfloat162float(h0)),
                           __float2bfloat16(v1 - __bfloat162float(h1)));
        *(__nv_bfloat162*)(g_AVl + b1) =
            __nv_bfloat162(__float2bfloat16(v2 - __bfloat162float(h2)),
                           __float2bfloat16(v3 - __bfloat162float(h3)));
    }
}

// ---------------------------------------------------------------------------
// Residual + LayerNorm
// ---------------------------------------------------------------------------
__global__ __launch_bounds__(256) void ln_residual(
    const float* __restrict__ h, const float* __restrict__ gamma,
    const float* __restrict__ beta, float* __restrict__ out)
{
    const int row = blockIdx.x;
    const int tid = threadIdx.x;

    const float4 hv = *(const float4*)(h + row * Dn + tid * 4);
    const float4 av = *(const float4*)(g_AO + row * Dn + tid * 4);
    float4 x = make_float4(hv.x + av.x, hv.y + av.y, hv.z + av.z, hv.w + av.w);

    float s  = x.x + x.y + x.z + x.w;
    float ss = x.x * x.x + x.y * x.y + x.z * x.z + x.w * x.w;
#pragma unroll
    for (int off = 16; off > 0; off >>= 1) {
        s  += __shfl_xor_sync(0xffffffffu, s, off);
        ss += __shfl_xor_sync(0xffffffffu, ss, off);
    }
    __shared__ float rs[8], rss[8];
    if ((tid & 31) == 0) { rs[tid >> 5] = s; rss[tid >> 5] = ss; }
    __syncthreads();
    s = 0.f; ss = 0.f;
#pragma unroll
    for (int w = 0; w < 8; w++) { s += rs[w]; ss += rss[w]; }

    const float mu  = s * (1.0f / Dn);
    const float var = ss * (1.0f / Dn) - mu * mu;
    const float inv = rsqrtf(var + 1e-5f);

    const float4 g4 = *(const float4*)(gamma + tid * 4);
    const float4 b4 = *(const float4*)(beta + tid * 4);
    float4 r;
    r.x = g4.x * (x.x - mu) * inv + b4.x;
    r.y = g4.y * (x.y - mu) * inv + b4.y;
    r.z = g4.z * (x.z - mu) * inv + b4.z;
    r.w = g4.w * (x.w - mu) * inv + b4.w;
    *(float4*)(out + row * Dn + tid * 4) = r;
}

// ---------------------------------------------------------------------------
extern "C" void kernel_launch(void* const* d_in, const int* in_sizes, int n_in,
                              void* d_out, int out_size)
{
    (void)in_sizes; (void)n_in; (void)out_size;
    const float* h     = (const float*)d_in[0];
    const float* Wq    = (const float*)d_in[1];
    const float* Wk    = (const float*)d_in[2];
    const float* Wv    = (const float*)d_in[3];
    const float* Wo    = (const float*)d_in[4];
    const float* gamma = (const float*)d_in[5];
    const float* beta  = (const float*)d_in[6];
    float* out = (float*)d_out;

    float* AOp;
    __nv_bfloat16 *hAhi, *hAlo, *Whi, *Wlo;
    __nv_bfloat16 *Qh, *Ql, *Kh, *Kl, *Vh, *Vl, *AVh, *AVl;
    cudaGetSymbolAddress((void**)&AOp,  g_AO);
    cudaGetSymbolAddress((void**)&hAhi, g_hA_hi);
    cudaGetSymbolAddress((void**)&hAlo, g_hA_lo);
    cudaGetSymbolAddress((void**)&Whi,  g_W_hi);
    cudaGetSymbolAddress((void**)&Wlo,  g_W_lo);
    cudaGetSymbolAddress((void**)&Qh,   g_Qh);
    cudaGetSymbolAddress((void**)&Ql,   g_Ql);
    cudaGetSymbolAddress((void**)&Kh,   g_Kh);
    cudaGetSymbolAddress((void**)&Kl,   g_Kl);
    cudaGetSymbolAddress((void**)&Vh,   g_Vh);
    cudaGetSymbolAddress((void**)&Vl,   g_Vl);
    cudaGetSymbolAddress((void**)&AVh,  g_AVh);
    cudaGetSymbolAddress((void**)&AVl,  g_AVl);

    cudaFuncSetAttribute(gemm_mma, cudaFuncAttributeMaxDynamicSharedMemorySize,
                         GEMM_SMEM);
    cudaFuncSetAttribute(gemm_qkv, cudaFuncAttributeMaxDynamicSharedMemorySize,
                         GEMM_SMEM);
    cudaFuncSetAttribute(flash_mma, cudaFuncAttributeMaxDynamicSharedMemorySize,
                         FLASH_SMEM);

    // Split h and weights into bf16 hi/lo
    split_f32<<<Mn * Dn / 1024, 256>>>(h, hAhi, hAlo);
    split_T4<<<dim3(32, 32, 4), dim3(32, 8)>>>(Wq, Wk, Wv, Wo, Whi, Wlo);

    // Fused Q/K/V projections (Q pre-scaled by 1/8 * log2(e))
    const float QSCALE = 0.125f * 1.4426950408889634f;
    gemm_qkv<<<dim3(24, Mn / 128), 256, GEMM_SMEM>>>(
        hAhi, hAlo, Whi, Wlo, Qh, Ql, Kh, Kl, Vh, Vl, QSCALE);

    // Attention (tensorized flash, double-buffered KV)
    flash_mma<<<dim3(Sn / 128, Hn, Bn), 256, FLASH_SMEM>>>();

    // Output projection
    gemm_mma<<<dim3(Dn / 128, Mn / 128), 256, GEMM_SMEM>>>(AVh, AVl,
        Whi + 3 * (size_t)Dn * Dn, Wlo + 3 * (size_t)Dn * Dn, AOp);

    ln_residual<<<Mn, 256>>>(h, gamma, beta, out);
}

// round 10
// speedup vs baseline: 1.2522x; 1.1461x over previous
#include <cuda_runtime.h>
#include <cuda_bf16.h>
#include <cuda_fp16.h>
#include <cstdint>
#include <math.h>

#define Bn 4
#define Sn 2048
#define Dn 1024
#define Hn 16
#define DHn 64
#define Mn (Bn * Sn)   // 8192

// ---------------------------------------------------------------------------
// Device scratch
// ---------------------------------------------------------------------------
__device__ float g_AO[Mn * Dn];

__device__ __nv_bfloat16 g_hA_hi[Mn * Dn];
__device__ __nv_bfloat16 g_hA_lo[Mn * Dn];
__device__ __nv_bfloat16 g_W_hi[4 * Dn * Dn];   // transposed [N,K], order q,k,v,o
__device__ __nv_bfloat16 g_W_lo[4 * Dn * Dn];

__device__ __nv_bfloat16 g_Qh[Mn * Dn];  // pre-scaled by 0.125*log2(e)
__device__ __nv_bfloat16 g_Ql[Mn * Dn];
__device__ __nv_bfloat16 g_Kh[Mn * Dn];
__device__ __nv_bfloat16 g_Kl[Mn * Dn];
__device__ __half        g_Vf[Mn * Dn];  // V in single fp16
__device__ __nv_bfloat16 g_AVh[Mn * Dn];
__device__ __nv_bfloat16 g_AVl[Mn * Dn];

// ---------------------------------------------------------------------------
__device__ __forceinline__ uint32_t smem_u32(const void* p) {
    uint32_t a;
    asm("{ .reg .u64 t; cvta.to.shared.u64 t, %1; cvt.u32.u64 %0, t; }"
        : "=r"(a) : "l"(p));
    return a;
}

__device__ __forceinline__ float fast_ex2(float x) {
    float r;
    asm("ex2.approx.ftz.f32 %0, %1;" : "=f"(r) : "f"(x));
    return r;
}

__device__ __forceinline__ void ldm_x4(uint32_t* r, uint32_t addr) {
    asm volatile("ldmatrix.sync.aligned.m8n8.x4.shared.b16 {%0,%1,%2,%3}, [%4];"
                 : "=r"(r[0]), "=r"(r[1]), "=r"(r[2]), "=r"(r[3]) : "r"(addr));
}
__device__ __forceinline__ void ldm_x4t(uint32_t* r, uint32_t addr) {
    asm volatile("ldmatrix.sync.aligned.m8n8.x4.trans.shared.b16 {%0,%1,%2,%3}, [%4];"
                 : "=r"(r[0]), "=r"(r[1]), "=r"(r[2]), "=r"(r[3]) : "r"(addr));
}

__device__ __forceinline__ void mma_bf16(float* c, const uint32_t* a,
                                         uint32_t b0, uint32_t b1) {
    asm volatile(
        "mma.sync.aligned.m16n8k16.row.col.f32.bf16.bf16.f32 "
        "{%0,%1,%2,%3}, {%4,%5,%6,%7}, {%8,%9}, {%0,%1,%2,%3};"
        : "+f"(c[0]), "+f"(c[1]), "+f"(c[2]), "+f"(c[3])
        : "r"(a[0]), "r"(a[1]), "r"(a[2]), "r"(a[3]), "r"(b0), "r"(b1));
}

__device__ __forceinline__ void mma_fp16(float* c, const uint32_t* a,
                                         uint32_t b0, uint32_t b1) {
    asm volatile(
        "mma.sync.aligned.m16n8k16.row.col.f32.f16.f16.f32 "
        "{%0,%1,%2,%3}, {%4,%5,%6,%7}, {%8,%9}, {%0,%1,%2,%3};"
        : "+f"(c[0]), "+f"(c[1]), "+f"(c[2]), "+f"(c[3])
        : "r"(a[0]), "r"(a[1]), "r"(a[2]), "r"(a[3]), "r"(b0), "r"(b1));
}

__device__ __forceinline__ void cp16(uint32_t s, const void* g) {
    asm volatile("cp.async.cg.shared.global [%0], [%1], 16;" :: "r"(s), "l"(g));
}
#define CP_COMMIT() asm volatile("cp.async.commit_group;" ::: "memory")
#define CP_WAIT0()  asm volatile("cp.async.wait_group 0;" ::: "memory")

// ---------------------------------------------------------------------------
// Split fp32 -> (hi, lo) bf16 pair, elementwise.
// ---------------------------------------------------------------------------
__global__ __launch_bounds__(256) void split_f32(
    const float* __restrict__ x, __nv_bfloat16* __restrict__ hi,
    __nv_bfloat16* __restrict__ lo)
{
    const int i = (blockIdx.x * 256 + threadIdx.x) * 4;
    float4 v = *(const float4*)(x + i);
    __nv_bfloat16 h0 = __float2bfloat16(v.x);
    __nv_bfloat16 h1 = __float2bfloat16(v.y);
    __nv_bfloat16 h2 = __float2bfloat16(v.z);
    __nv_bfloat16 h3 = __float2bfloat16(v.w);
    __nv_bfloat16 l0 = __float2bfloat16(v.x - __bfloat162float(h0));
    __nv_bfloat16 l1 = __float2bfloat16(v.y - __bfloat162float(h1));
    __nv_bfloat16 l2 = __float2bfloat16(v.z - __bfloat162float(h2));
    __nv_bfloat16 l3 = __float2bfloat16(v.w - __bfloat162float(h3));
    __nv_bfloat162* hp = (__nv_bfloat162*)(hi + i);
    __nv_bfloat162* lp = (__nv_bfloat162*)(lo + i);
    hp[0] = __nv_bfloat162(h0, h1); hp[1] = __nv_bfloat162(h2, h3);
    lp[0] = __nv_bfloat162(l0, l1); lp[1] = __nv_bfloat162(l2, l3);
}

// ---------------------------------------------------------------------------
// Split + transpose all 4 weights (blockIdx.z selects): fp32 [K,N] -> bf16 [N,K]
// ---------------------------------------------------------------------------
__global__ __launch_bounds__(256) void split_T4(
    const float* __restrict__ W0, const float* __restrict__ W1,
    const float* __restrict__ W2, const float* __restrict__ W3,
    __nv_bfloat16* __restrict__ hiT, __nv_bfloat16* __restrict__ loT)
{
    const int z = blockIdx.z;
    const float* W = (z == 0) ? W0 : (z == 1) ? W1 : (z == 2) ? W2 : W3;
    __nv_bfloat16* hi = hiT + (size_t)z * Dn * Dn;
    __nv_bfloat16* lo = loT + (size_t)z * Dn * Dn;

    __shared__ float t[32][33];
    const int tx = threadIdx.x, ty = threadIdx.y;
    const int bn = blockIdx.x * 32, bk = blockIdx.y * 32;
#pragma unroll
    for (int j = 0; j < 4; j++)
        t[ty + j * 8][tx] = W[(size_t)(bk + ty + j * 8) * Dn + bn + tx];
    __syncthreads();
#pragma unroll
    for (int j = 0; j < 4; j++) {
        float v = t[tx][ty + j * 8];
        __nv_bfloat16 h = __float2bfloat16(v);
        __nv_bfloat16 l = __float2bfloat16(v - __bfloat162float(h));
        size_t o = (size_t)(bn + ty + j * 8) * Dn + bk + tx;
        hi[o] = h;
        lo[o] = l;
    }
}

// ---------------------------------------------------------------------------
// GEMM mainloop (mma.sync bf16-split, cp.async double buffer, 2 CTAs/SM).
// EPI = 0: fp32 output.  EPI = 1: bf16 hi/lo split (scaled).  EPI = 2: fp16.
// 128x128 CTA tile, 8 warps (2M x 4N), 64x32 per warp, BK=32.
// ---------------------------------------------------------------------------
#define BK        32
#define NSTAGE    (Dn / BK)          // 32
#define ROW_B     80                 // bytes per smem row (32 bf16 + 8 pad)
#define ARR_SZ    (128 * ROW_B)      // 10240 bytes per array tile
#define BUF_SZ    (4 * ARR_SZ)
#define GEMM_SMEM (2 * BUF_SZ)       // 81920 -> 2 CTAs/SM

template <int EPI>
__device__ __forceinline__ void gemm_body(
    const __nv_bfloat16* __restrict__ Ahi, const __nv_bfloat16* __restrict__ Alo,
    const __nv_bfloat16* __restrict__ Bhi, const __nv_bfloat16* __restrict__ Blo,
    float* __restrict__ C,
    __nv_bfloat16* __restrict__ Chi, __nv_bfloat16* __restrict__ Clo, float scale,
    int m0, int n0)
{
    extern __shared__ char smem[];
    const uint32_t sb = smem_u32(smem);
    const int tid  = threadIdx.x;
    const int wid  = tid >> 5;
    const int lane = tid & 31;
    const int m0w = (wid & 1) * 64;
    const int n0w = (wid >> 1) * 32;

    const char* src[4] = {(const char*)Ahi, (const char*)Alo,
                          (const char*)Bhi, (const char*)Blo};

    const int r0c = tid >> 2;
    const int c16 = tid & 3;
    size_t goff[4][2];
#pragma unroll
    for (int arr = 0; arr < 4; arr++) {
        const int tb = (arr < 2) ? m0 : n0;
#pragma unroll
        for (int it = 0; it < 2; it++)
            goff[arr][it] = (size_t)(tb + r0c + it * 64) * 2048 + c16 * 16;
    }
    const uint32_t soff0 = r0c * ROW_B + c16 * 16;
    const uint32_t soff1 = (r0c + 64) * ROW_B + c16 * 16;

    float acc[4][4][4];
#pragma unroll
    for (int i = 0; i < 4; i++)
#pragma unroll
        for (int j = 0; j < 4; j++)
#pragma unroll
            for (int k = 0; k < 4; k++) acc[i][j][k] = 0.f;

    const int lrow = lane & 15;
    const int lch  = lane >> 4;
    const uint32_t a_lbase = (uint32_t)(m0w + lrow) * ROW_B + lch * 16;
    const uint32_t b_lbase = (uint32_t)(n0w + lrow) * ROW_B + lch * 16;

    // Preload stage 0 via cp.async
#pragma unroll
    for (int arr = 0; arr < 4; arr++) {
        cp16(sb + arr * ARR_SZ + soff0, src[arr] + goff[arr][0]);
        cp16(sb + arr * ARR_SZ + soff1, src[arr] + goff[arr][1]);
    }
    CP_COMMIT();
    CP_WAIT0();
    __syncthreads();

    for (int kc = 0; kc < NSTAGE; kc++) {
        const int cb = kc & 1;

        if (kc + 1 < NSTAGE) {
            const size_t kb = (size_t)(kc + 1) * 64;
            const uint32_t db = sb + (cb ^ 1) * BUF_SZ;
#pragma unroll
            for (int arr = 0; arr < 4; arr++) {
                cp16(db + arr * ARR_SZ + soff0, src[arr] + goff[arr][0] + kb);
                cp16(db + arr * ARR_SZ + soff1, src[arr] + goff[arr][1] + kb);
            }
            CP_COMMIT();
        }

        const uint32_t bufb = sb + cb * BUF_SZ;
#pragma unroll
        for (int ks = 0; ks < 2; ks++) {
            uint32_t ah[4][4], bh[2][4];
#pragma unroll
            for (int mi = 0; mi < 4; mi++)
                ldm_x4(ah[mi], bufb + 0 * ARR_SZ + a_lbase
                                 + mi * (16 * ROW_B) + ks * 32);
#pragma unroll
            for (int ni = 0; ni < 2; ni++)
                ldm_x4(bh[ni], bufb + 2 * ARR_SZ + b_lbase
                                 + ni * (16 * ROW_B) + ks * 32);
#pragma unroll
            for (int mi = 0; mi < 4; mi++)
#pragma unroll
                for (int ni = 0; ni < 2; ni++) {
                    mma_bf16(acc[mi][ni * 2 + 0], ah[mi], bh[ni][0], bh[ni][2]);
                    mma_bf16(acc[mi][ni * 2 + 1], ah[mi], bh[ni][1], bh[ni][3]);
                }
            {
                uint32_t bl[2][4];
#pragma unroll
                for (int ni = 0; ni < 2; ni++)
                    ldm_x4(bl[ni], bufb + 3 * ARR_SZ + b_lbase
                                     + ni * (16 * ROW_B) + ks * 32);
#pragma unroll
                for (int mi = 0; mi < 4; mi++)
#pragma unroll
                    for (int ni = 0; ni < 2; ni++) {
                        mma_bf16(acc[mi][ni * 2 + 0], ah[mi], bl[ni][0], bl[ni][2]);
                        mma_bf16(acc[mi][ni * 2 + 1], ah[mi], bl[ni][1], bl[ni][3]);
                    }
            }
            {
                uint32_t al[4][4];
#pragma unroll
                for (int mi = 0; mi < 4; mi++)
                    ldm_x4(al[mi], bufb + 1 * ARR_SZ + a_lbase
                                     + mi * (16 * ROW_B) + ks * 32);
#pragma unroll
                for (int mi = 0; mi < 4; mi++)
#pragma unroll
                    for (int ni = 0; ni < 2; ni++) {
                        mma_bf16(acc[mi][ni * 2 + 0], al[mi], bh[ni][0], bh[ni][2]);
                        mma_bf16(acc[mi][ni * 2 + 1], al[mi], bh[ni][1], bh[ni][3]);
                    }
            }
        }

        CP_WAIT0();
        __syncthreads();
    }

    // Epilogue
    const int erow = lane >> 2;
    const int ecol = (lane & 3) * 2;
#pragma unroll
    for (int mi = 0; mi < 4; mi++) {
#pragma unroll
        for (int nj = 0; nj < 4; nj++) {
            size_t base0 = (size_t)(m0 + m0w + mi * 16 + erow) * Dn
                         + n0 + n0w + nj * 8 + ecol;
            if (EPI == 0) {
                *(float2*)(C + base0)          = make_float2(acc[mi][nj][0], acc[mi][nj][1]);
                *(float2*)(C + base0 + 8 * Dn) = make_float2(acc[mi][nj][2], acc[mi][nj][3]);
            } else if (EPI == 1) {
#pragma unroll
                for (int half = 0; half < 2; half++) {
                    size_t b = base0 + half * 8 * Dn;
                    float v0 = acc[mi][nj][half * 2 + 0] * scale;
                    float v1 = acc[mi][nj][half * 2 + 1] * scale;
                    __nv_bfloat16 h0 = __float2bfloat16(v0);
                    __nv_bfloat16 h1 = __float2bfloat16(v1);
                    __nv_bfloat16 l0 = __float2bfloat16(v0 - __bfloat162float(h0));
                    __nv_bfloat16 l1 = __float2bfloat16(v1 - __bfloat162float(h1));
                    *(__nv_bfloat162*)(Chi + b) = __nv_bfloat162(h0, h1);
                    *(__nv_bfloat162*)(Clo + b) = __nv_bfloat162(l0, l1);
                }
            } else {
                __half* Ch = (__half*)Chi;
#pragma unroll
                for (int half = 0; half < 2; half++) {
                    size_t b = base0 + half * 8 * Dn;
                    __half h0 = __float2half_rn(acc[mi][nj][half * 2 + 0]);
                    __half h1 = __float2half_rn(acc[mi][nj][half * 2 + 1]);
                    *(__half2*)(Ch + b) = __halves2half2(h0, h1);
                }
            }
        }
    }
}

// Fused Q/K/V projection: grid (24, 64); blockIdx.x selects weight + outputs.
__global__ __launch_bounds__(256, 2) void gemm_qkv(
    const __nv_bfloat16* __restrict__ Ahi, const __nv_bfloat16* __restrict__ Alo,
    const __nv_bfloat16* __restrict__ Whi, const __nv_bfloat16* __restrict__ Wlo,
    __nv_bfloat16* __restrict__ Qh, __nv_bfloat16* __restrict__ Ql,
    __nv_bfloat16* __restrict__ Kh, __nv_bfloat16* __restrict__ Kl,
    __half* __restrict__ Vf, float qscale)
{
    const int ng   = blockIdx.x * 128;       // 0..3071
    const int wsel = ng >> 10;               // 0=Q, 1=K, 2=V
    const int n0   = ng & 1023;
    const int m0   = blockIdx.y * 128;
    const __nv_bfloat16* Bhi = Whi + (size_t)wsel * Dn * Dn;
    const __nv_bfloat16* Blo = Wlo + (size_t)wsel * Dn * Dn;
    if (wsel == 0)
        gemm_body<1>(Ahi, Alo, Bhi, Blo, nullptr, Qh, Ql, qscale, m0, n0);
    else if (wsel == 1)
        gemm_body<1>(Ahi, Alo, Bhi, Blo, nullptr, Kh, Kl, 1.0f, m0, n0);
    else
        gemm_body<2>(Ahi, Alo, Bhi, Blo, nullptr,
                     (__nv_bfloat16*)Vf, nullptr, 1.0f, m0, n0);
}

// O projection: fp32 output
__global__ __launch_bounds__(256, 2) void gemm_mma(
    const __nv_bfloat16* __restrict__ Ahi, const __nv_bfloat16* __restrict__ Alo,
    const __nv_bfloat16* __restrict__ Bhi, const __nv_bfloat16* __restrict__ Blo,
    float* __restrict__ C)
{
    gemm_body<0>(Ahi, Alo, Bhi, Blo, C, nullptr, nullptr, 1.0f,
                 blockIdx.y * 128, blockIdx.x * 128);
}

// ---------------------------------------------------------------------------
// Flash attention: QK^T = 3-term bf16 split; P*V = single fp16 MMA.
// Grid (16, 16, 4): 128 q-rows per CTA, 256 threads (8 warps x m16).
// K (bf16 hi/lo) + V (fp16) tiles double-buffered via cp.async.
// Softmax in log2 domain -> MUFU ex2; l summed from fp16-rounded p.
// ---------------------------------------------------------------------------
#define FROW 144
#define FARR (64 * FROW)          // 9216 (one 64-row tile, 128B data/row)
#define QARR (128 * FROW)         // 18432
#define KVBUF (3 * FARR)          // Kh, Kl, Vf = 27648
#define FLASH_SMEM (2 * QARR + 2 * KVBUF)   // 92160

#define KV_PREFETCH(kt_, buf_) do {                                           \
    const uint32_t base_ = sb + 2 * QARR + (uint32_t)(buf_) * KVBUF;          \
    const size_t g0_ = (size_t)(bb * Sn + (kt_) * 64 + kr0) * Dn              \
                     + headoff + kch * 8;                                     \
    const size_t g1_ = g0_ + (size_t)32 * Dn;                                 \
    cp16(base_ + 0 * FARR + kso0, g_Kh + g0_);                                \
    cp16(base_ + 0 * FARR + kso1, g_Kh + g1_);                                \
    cp16(base_ + 1 * FARR + kso0, g_Kl + g0_);                                \
    cp16(base_ + 1 * FARR + kso1, g_Kl + g1_);                                \
    cp16(base_ + 2 * FARR + kso0, g_Vf + g0_);                                \
    cp16(base_ + 2 * FARR + kso1, g_Vf + g1_);                                \
    CP_COMMIT();                                                              \
} while (0)

__global__ __launch_bounds__(256) void flash_mma()
{
    extern __shared__ char sm[];
    const uint32_t sb = smem_u32(sm);
    const int tid = threadIdx.x;
    const int lane = tid & 31;
    const int w = tid >> 5;
    const int qt = blockIdx.x, hh = blockIdx.y, bb = blockIdx.z;

    const size_t headoff = (size_t)hh * 64;

    const int kr0 = tid >> 3;           // rows 0..31
    const int kch = tid & 7;
    const uint32_t kso0 = (uint32_t)kr0 * FROW + kch * 16;
    const uint32_t kso1 = (uint32_t)(kr0 + 32) * FROW + kch * 16;

    KV_PREFETCH(0, 0);

    // Load Q hi/lo tiles (128 x 64 bf16 each)
#pragma unroll
    for (int i = 0; i < 4; i++) {
        const int idx = tid + 256 * i;
        const int r = idx >> 3, ch = idx & 7;
        const size_t g = (size_t)(bb * Sn + qt * 128 + r) * Dn + headoff + ch * 8;
        const uint32_t so = r * FROW + ch * 16;
        *(uint4*)(sm + so)        = *(const uint4*)(g_Qh + g);
        *(uint4*)(sm + QARR + so) = *(const uint4*)(g_Ql + g);
    }

    const int lrow = lane & 15;
    const int lch  = lane >> 4;
    const uint32_t aoff = (uint32_t)(w * 16 + lrow) * FROW + lch * 16;
    uint32_t boff[4];
#pragma unroll
    for (int np = 0; np < 4; np++)
        boff[np] = (uint32_t)(np * 16 + lrow) * FROW + lch * 16;

    float o[8][4];
#pragma unroll
    for (int j = 0; j < 8; j++)
#pragma unroll
        for (int k = 0; k < 4; k++) o[j][k] = 0.f;
    float m0r = -1e30f, m1r = -1e30f, l0r = 0.f, l1r = 0.f;

    for (int kt = 0; kt < Sn / 64; kt++) {
        const int buf = kt & 1;
        CP_WAIT0();
        __syncthreads();

        if (kt + 1 < Sn / 64)
            KV_PREFETCH(kt + 1, buf ^ 1);

        const uint32_t kvb = sb + 2 * QARR + (uint32_t)buf * KVBUF;

        // ---- S = Q*K^T (3 split terms), n=64 keys ----
        float s[8][4];
#pragma unroll
        for (int j = 0; j < 8; j++)
#pragma unroll
            for (int k = 0; k < 4; k++) s[j][k] = 0.f;

#pragma unroll
        for (int ks = 0; ks < 4; ks++) {
            uint32_t qh[4], ql[4];
            ldm_x4(qh, sb + aoff + ks * 32);
            ldm_x4(ql, sb + QARR + aoff + ks * 32);
#pragma unroll
            for (int np = 0; np < 4; np++) {
                uint32_t kh[4], kl[4];
                ldm_x4(kh, kvb + 0 * FARR + boff[np] + ks * 32);
                ldm_x4(kl, kvb + 1 * FARR + boff[np] + ks * 32);
                mma_bf16(s[2 * np + 0], qh, kh[0], kh[2]);
                mma_bf16(s[2 * np + 1], qh, kh[1], kh[3]);
                mma_bf16(s[2 * np + 0], qh, kl[0], kl[2]);
                mma_bf16(s[2 * np + 1], qh, kl[1], kl[3]);
                mma_bf16(s[2 * np + 0], ql, kh[0], kh[2]);
                mma_bf16(s[2 * np + 1], ql, kh[1], kh[3]);
            }
        }

        // ---- Online softmax, log2 domain (rows lane/4 and lane/4+8) ----
        float mx0 = -1e30f, mx1 = -1e30f;
#pragma unroll
        for (int j = 0; j < 8; j++) {
            mx0 = fmaxf(mx0, fmaxf(s[j][0], s[j][1]));
            mx1 = fmaxf(mx1, fmaxf(s[j][2], s[j][3]));
        }
        mx0 = fmaxf(mx0, __shfl_xor_sync(0xffffffffu, mx0, 1));
        mx0 = fmaxf(mx0, __shfl_xor_sync(0xffffffffu, mx0, 2));
        mx1 = fmaxf(mx1, __shfl_xor_sync(0xffffffffu, mx1, 1));
        mx1 = fmaxf(mx1, __shfl_xor_sync(0xffffffffu, mx1, 2));

        const float mn0 = fmaxf(m0r, mx0);
        const float mn1 = fmaxf(m1r, mx1);
        const float a0 = fast_ex2(m0r - mn0);
        const float a1 = fast_ex2(m1r - mn1);
        m0r = mn0; m1r = mn1;

        uint32_t pf[8][2];
        float sum0 = 0.f, sum1 = 0.f;
#pragma unroll
        for (int j = 0; j < 8; j++) {
            float p00 = fast_ex2(s[j][0] - mn0);
            float p01 = fast_ex2(s[j][1] - mn0);
            float p10 = fast_ex2(s[j][2] - mn1);
            float p11 = fast_ex2(s[j][3] - mn1);
            __half h00 = __float2half_rn(p00);
            __half h01 = __float2half_rn(p01);
            __half h10 = __float2half_rn(p10);
            __half h11 = __float2half_rn(p11);
            // sum the ROUNDED values so l matches the fp16 P used in PV
            sum0 += __half2float(h00) + __half2float(h01);
            sum1 += __half2float(h10) + __half2float(h11);
            pf[j][0] = ((uint32_t)__half_as_ushort(h01) << 16)
                     |  (uint32_t)__half_as_ushort(h00);
            pf[j][1] = ((uint32_t)__half_as_ushort(h11) << 16)
                     |  (uint32_t)__half_as_ushort(h10);
        }
        sum0 += __shfl_xor_sync(0xffffffffu, sum0, 1);
        sum0 += __shfl_xor_sync(0xffffffffu, sum0, 2);
        sum1 += __shfl_xor_sync(0xffffffffu, sum1, 1);
        sum1 += __shfl_xor_sync(0xffffffffu, sum1, 2);
        l0r = l0r * a0 + sum0;
        l1r = l1r * a1 + sum1;

#pragma unroll
        for (int j = 0; j < 8; j++) {
            o[j][0] *= a0; o[j][1] *= a0;
            o[j][2] *= a1; o[j][3] *= a1;
        }

        // ---- O += P * V (single fp16 term), V via ldmatrix.trans ----
#pragma unroll
        for (int ks = 0; ks < 4; ks++) {
            uint32_t ap[4] = {pf[2 * ks][0], pf[2 * ks][1],
                              pf[2 * ks + 1][0], pf[2 * ks + 1][1]};
            const uint32_t vbase = (uint32_t)(ks * 16 + lrow) * FROW + lch * 16;
#pragma unroll
            for (int np = 0; np < 4; np++) {
                uint32_t vf[4];
                ldm_x4t(vf, kvb + 2 * FARR + vbase + np * 32);
                mma_fp16(o[2 * np + 0], ap, vf[0], vf[1]);
                mma_fp16(o[2 * np + 1], ap, vf[2], vf[3]);
            }
        }
        __syncthreads();
    }

    // Epilogue: normalize, split to hi/lo bf16, write AV
    const float inv0 = 1.0f / l0r;
    const float inv1 = 1.0f / l1r;
    const size_t row0 = (size_t)(bb * Sn + qt * 128 + w * 16 + (lane >> 2));
    const size_t row1 = row0 + 8;
    const size_t colb = headoff + (lane & 3) * 2;
#pragma unroll
    for (int j = 0; j < 8; j++) {
        float v0 = o[j][0] * inv0, v1 = o[j][1] * inv0;
        float v2 = o[j][2] * inv1, v3 = o[j][3] * inv1;
        __nv_bfloat16 h0 = __float2bfloat16(v0);
        __nv_bfloat16 h1 = __float2bfloat16(v1);
        __nv_bfloat16 h2 = __float2bfloat16(v2);
        __nv_bfloat16 h3 = __float2bfloat16(v3);
        size_t b0 = row0 * Dn + colb + j * 8;
        size_t b1 = row1 * Dn + colb + j * 8;
        *(__nv_bfloat162*)(g_AVh + b0) = __nv_bfloat162(h0, h1);
        *(__nv_bfloat162*)(g_AVh + b1) = __nv_bfloat162(h2, h3);
        *(__nv_bfloat162*)(g_AVl + b0) =
            __nv_bfloat162(__float2bfloat16(v0 - __bfloat162float(h0)),
                           __float2bfloat16(v1 - __bfloat162float(h1)));
        *(__nv_bfloat162*)(g_AVl + b1) =
            __nv_bfloat162(__float2bfloat16(v2 - __bfloat162float(h2)),
                           __float2bfloat16(v3 - __bfloat162float(h3)));
    }
}

// ---------------------------------------------------------------------------
// Residual + LayerNorm
// ---------------------------------------------------------------------------
__global__ __launch_bounds__(256) void ln_residual(
    const float* __restrict__ h, const float* __restrict__ gamma,
    const float* __restrict__ beta, float* __restrict__ out)
{
    const int row = blockIdx.x;
    const int tid = threadIdx.x;

    const float4 hv = *(const float4*)(h + row * Dn + tid * 4);
    const float4 av = *(const float4*)(g_AO + row * Dn + tid * 4);
    float4 x = make_float4(hv.x + av.x, hv.y + av.y, hv.z + av.z, hv.w + av.w);

    float s  = x.x + x.y + x.z + x.w;
    float ss = x.x * x.x + x.y * x.y + x.z * x.z + x.w * x.w;
#pragma unroll
    for (int off = 16; off > 0; off >>= 1) {
        s  += __shfl_xor_sync(0xffffffffu, s, off);
        ss += __shfl_xor_sync(0xffffffffu, ss, off);
    }
    __shared__ float rs[8], rss[8];
    if ((tid & 31) == 0) { rs[tid >> 5] = s; rss[tid >> 5] = ss; }
    __syncthreads();
    s = 0.f; ss = 0.f;
#pragma unroll
    for (int w = 0; w < 8; w++) { s += rs[w]; ss += rss[w]; }

    const float mu  = s * (1.0f / Dn);
    const float var = ss * (1.0f / Dn) - mu * mu;
    const float inv = rsqrtf(var + 1e-5f);

    const float4 g4 = *(const float4*)(gamma + tid * 4);
    const float4 b4 = *(const float4*)(beta + tid * 4);
    float4 r;
    r.x = g4.x * (x.x - mu) * inv + b4.x;
    r.y = g4.y * (x.y - mu) * inv + b4.y;
    r.z = g4.z * (x.z - mu) * inv + b4.z;
    r.w = g4.w * (x.w - mu) * inv + b4.w;
    *(float4*)(out + row * Dn + tid * 4) = r;
}

// ---------------------------------------------------------------------------
extern "C" void kernel_launch(void* const* d_in, const int* in_sizes, int n_in,
                              void* d_out, int out_size)
{
    (void)in_sizes; (void)n_in; (void)out_size;
    const float* h     = (const float*)d_in[0];
    const float* Wq    = (const float*)d_in[1];
    const float* Wk    = (const float*)d_in[2];
    const float* Wv    = (const float*)d_in[3];
    const float* Wo    = (const float*)d_in[4];
    const float* gamma = (const float*)d_in[5];
    const float* beta  = (const float*)d_in[6];
    float* out = (float*)d_out;

    float* AOp;
    __nv_bfloat16 *hAhi, *hAlo, *Whi, *Wlo;
    __nv_bfloat16 *Qh, *Ql, *Kh, *Kl, *AVh, *AVl;
    __half* Vf;
    cudaGetSymbolAddress((void**)&AOp,  g_AO);
    cudaGetSymbolAddress((void**)&hAhi, g_hA_hi);
    cudaGetSymbolAddress((void**)&hAlo, g_hA_lo);
    cudaGetSymbolAddress((void**)&Whi,  g_W_hi);
    cudaGetSymbolAddress((void**)&Wlo,  g_W_lo);
    cudaGetSymbolAddress((void**)&Qh,   g_Qh);
    cudaGetSymbolAddress((void**)&Ql,   g_Ql);
    cudaGetSymbolAddress((void**)&Kh,   g_Kh);
    cudaGetSymbolAddress((void**)&Kl,   g_Kl);
    cudaGetSymbolAddress((void**)&Vf,   g_Vf);
    cudaGetSymbolAddress((void**)&AVh,  g_AVh);
    cudaGetSymbolAddress((void**)&AVl,  g_AVl);

    cudaFuncSetAttribute(gemm_mma, cudaFuncAttributeMaxDynamicSharedMemorySize,
                         GEMM_SMEM);
    cudaFuncSetAttribute(gemm_qkv, cudaFuncAttributeMaxDynamicSharedMemorySize,
                         GEMM_SMEM);
    cudaFuncSetAttribute(flash_mma, cudaFuncAttributeMaxDynamicSharedMemorySize,
                         FLASH_SMEM);

    // Split h and weights into bf16 hi/lo
    split_f32<<<Mn * Dn / 1024, 256>>>(h, hAhi, hAlo);
    split_T4<<<dim3(32, 32, 4), dim3(32, 8)>>>(Wq, Wk, Wv, Wo, Whi, Wlo);

    // Fused Q/K/V projections (Q pre-scaled by 1/8 * log2(e); V -> fp16)
    const float QSCALE = 0.125f * 1.4426950408889634f;
    gemm_qkv<<<dim3(24, Mn / 128), 256, GEMM_SMEM>>>(
        hAhi, hAlo, Whi, Wlo, Qh, Ql, Kh, Kl, Vf, QSCALE);

    // Attention (tensorized flash, fp16 PV)
    flash_mma<<<dim3(Sn / 128, Hn, Bn), 256, FLASH_SMEM>>>();

    // Output projection
    gemm_mma<<<dim3(Dn / 128, Mn / 128), 256, GEMM_SMEM>>>(AVh, AVl,
        Whi + 3 * (size_t)Dn * Dn, Wlo + 3 * (size_t)Dn * Dn, AOp);

    ln_residual<<<Mn, 256>>>(h, gamma, beta, out);
}

// round 11
// speedup vs baseline: 1.3684x; 1.0928x over previous
#include <cuda_runtime.h>
#include <cuda_bf16.h>
#include <cuda_fp16.h>
#include <cstdint>
#include <math.h>

#define Bn 4
#define Sn 2048
#define Dn 1024
#define Hn 16
#define DHn 64
#define Mn (Bn * Sn)   // 8192

// ---------------------------------------------------------------------------
// Device scratch
// ---------------------------------------------------------------------------
__device__ float g_AO[Mn * Dn];

__device__ __nv_bfloat16 g_hA_hi[Mn * Dn];
__device__ __nv_bfloat16 g_hA_lo[Mn * Dn];
__device__ __half        g_hF_hi[Mn * Dn];   // fp16 split of h (for V gemm)
__device__ __half        g_hF_lo[Mn * Dn];
__device__ __nv_bfloat16 g_W_hi[2 * Dn * Dn];   // bf16 [N,K]: q, k
__device__ __nv_bfloat16 g_W_lo[2 * Dn * Dn];
__device__ __half        g_Wf[2 * Dn * Dn];     // fp16 [N,K]: v, o

__device__ __nv_bfloat16 g_Qh[Mn * Dn];  // pre-scaled by 0.125*log2(e)
__device__ __nv_bfloat16 g_Ql[Mn * Dn];
__device__ __nv_bfloat16 g_Kh[Mn * Dn];
__device__ __nv_bfloat16 g_Kl[Mn * Dn];
__device__ __half        g_Vf[Mn * Dn];  // V in single fp16
__device__ __half        g_AVfh[Mn * Dn];   // AV fp16 hi/lo split
__device__ __half        g_AVfl[Mn * Dn];

// ---------------------------------------------------------------------------
__device__ __forceinline__ uint32_t smem_u32(const void* p) {
    uint32_t a;
    asm("{ .reg .u64 t; cvta.to.shared.u64 t, %1; cvt.u32.u64 %0, t; }"
        : "=r"(a) : "l"(p));
    return a;
}

__device__ __forceinline__ float fast_ex2(float x) {
    float r;
    asm("ex2.approx.ftz.f32 %0, %1;" : "=f"(r) : "f"(x));
    return r;
}

__device__ __forceinline__ void ldm_x4(uint32_t* r, uint32_t addr) {
    asm volatile("ldmatrix.sync.aligned.m8n8.x4.shared.b16 {%0,%1,%2,%3}, [%4];"
                 : "=r"(r[0]), "=r"(r[1]), "=r"(r[2]), "=r"(r[3]) : "r"(addr));
}
__device__ __forceinline__ void ldm_x4t(uint32_t* r, uint32_t addr) {
    asm volatile("ldmatrix.sync.aligned.m8n8.x4.trans.shared.b16 {%0,%1,%2,%3}, [%4];"
                 : "=r"(r[0]), "=r"(r[1]), "=r"(r[2]), "=r"(r[3]) : "r"(addr));
}

__device__ __forceinline__ void mma_bf16(float* c, const uint32_t* a,
                                         uint32_t b0, uint32_t b1) {
    asm volatile(
        "mma.sync.aligned.m16n8k16.row.col.f32.bf16.bf16.f32 "
        "{%0,%1,%2,%3}, {%4,%5,%6,%7}, {%8,%9}, {%0,%1,%2,%3};"
        : "+f"(c[0]), "+f"(c[1]), "+f"(c[2]), "+f"(c[3])
        : "r"(a[0]), "r"(a[1]), "r"(a[2]), "r"(a[3]), "r"(b0), "r"(b1));
}

__device__ __forceinline__ void mma_fp16(float* c, const uint32_t* a,
                                         uint32_t b0, uint32_t b1) {
    asm volatile(
        "mma.sync.aligned.m16n8k16.row.col.f32.f16.f16.f32 "
        "{%0,%1,%2,%3}, {%4,%5,%6,%7}, {%8,%9}, {%0,%1,%2,%3};"
        : "+f"(c[0]), "+f"(c[1]), "+f"(c[2]), "+f"(c[3])
        : "r"(a[0]), "r"(a[1]), "r"(a[2]), "r"(a[3]), "r"(b0), "r"(b1));
}

__device__ __forceinline__ void cp16(uint32_t s, const void* g) {
    asm volatile("cp.async.cg.shared.global [%0], [%1], 16;" :: "r"(s), "l"(g));
}
#define CP_COMMIT() asm volatile("cp.async.commit_group;" ::: "memory")
#define CP_WAIT0()  asm volatile("cp.async.wait_group 0;" ::: "memory")

// ---------------------------------------------------------------------------
// Split fp32 h -> bf16 (hi,lo) AND fp16 (hi,lo)
// ---------------------------------------------------------------------------
__global__ __launch_bounds__(256) void split_h(
    const float* __restrict__ x,
    __nv_bfloat16* __restrict__ bhi, __nv_bfloat16* __restrict__ blo,
    __half* __restrict__ fhi, __half* __restrict__ flo)
{
    const int i = (blockIdx.x * 256 + threadIdx.x) * 4;
    float4 v = *(const float4*)(x + i);
    float vv[4] = {v.x, v.y, v.z, v.w};
    __nv_bfloat16 bh[4], bl[4];
    __half fh[4], fl[4];
#pragma unroll
    for (int k = 0; k < 4; k++) {
        bh[k] = __float2bfloat16(vv[k]);
        bl[k] = __float2bfloat16(vv[k] - __bfloat162float(bh[k]));
        fh[k] = __float2half_rn(vv[k]);
        fl[k] = __float2half_rn(vv[k] - __half2float(fh[k]));
    }
    __nv_bfloat162* bhp = (__nv_bfloat162*)(bhi + i);
    __nv_bfloat162* blp = (__nv_bfloat162*)(blo + i);
    bhp[0] = __nv_bfloat162(bh[0], bh[1]); bhp[1] = __nv_bfloat162(bh[2], bh[3]);
    blp[0] = __nv_bfloat162(bl[0], bl[1]); blp[1] = __nv_bfloat162(bl[2], bl[3]);
    __half2* fhp = (__half2*)(fhi + i);
    __half2* flp = (__half2*)(flo + i);
    fhp[0] = __halves2half2(fh[0], fh[1]); fhp[1] = __halves2half2(fh[2], fh[3]);
    flp[0] = __halves2half2(fl[0], fl[1]); flp[1] = __halves2half2(fl[2], fl[3]);
}

// ---------------------------------------------------------------------------
// Split + transpose weights: z=0,1 (Wq,Wk) -> bf16 hi/lo [N,K];
//                            z=2,3 (Wv,Wo) -> fp16 single [N,K].
// ---------------------------------------------------------------------------
__global__ __launch_bounds__(256) void split_T4(
    const float* __restrict__ W0, const float* __restrict__ W1,
    const float* __restrict__ W2, const float* __restrict__ W3,
    __nv_bfloat16* __restrict__ hiT, __nv_bfloat16* __restrict__ loT,
    __half* __restrict__ fT)
{
    const int z = blockIdx.z;
    const float* W = (z == 0) ? W0 : (z == 1) ? W1 : (z == 2) ? W2 : W3;

    __shared__ float t[32][33];
    const int tx = threadIdx.x, ty = threadIdx.y;
    const int bn = blockIdx.x * 32, bk = blockIdx.y * 32;
#pragma unroll
    for (int j = 0; j < 4; j++)
        t[ty + j * 8][tx] = W[(size_t)(bk + ty + j * 8) * Dn + bn + tx];
    __syncthreads();
#pragma unroll
    for (int j = 0; j < 4; j++) {
        float v = t[tx][ty + j * 8];
        size_t o = (size_t)(bn + ty + j * 8) * Dn + bk + tx;
        if (z < 2) {
            __nv_bfloat16 h = __float2bfloat16(v);
            __nv_bfloat16 l = __float2bfloat16(v - __bfloat162float(h));
            hiT[(size_t)z * Dn * Dn + o] = h;
            loT[(size_t)z * Dn * Dn + o] = l;
        } else {
            fT[(size_t)(z - 2) * Dn * Dn + o] = __float2half_rn(v);
        }
    }
}

// ---------------------------------------------------------------------------
// Shared constants for both GEMM bodies.
// ---------------------------------------------------------------------------
#define BK        32
#define NSTAGE    (Dn / BK)          // 32
#define ROW_B     80                 // bytes per smem row (32 elems + 8 pad)
#define ARR_SZ    (128 * ROW_B)      // 10240 bytes per array tile
#define BUF_SZ    (4 * ARR_SZ)
#define GEMM_SMEM (2 * BUF_SZ)       // 81920 -> 2 CTAs/SM

// ---------------------------------------------------------------------------
// bf16 3-term GEMM body (Q/K projections). EPI=1: bf16 hi/lo split out (scaled).
// ---------------------------------------------------------------------------
__device__ __forceinline__ void gemm_bf16_body(
    const __nv_bfloat16* __restrict__ Ahi, const __nv_bfloat16* __restrict__ Alo,
    const __nv_bfloat16* __restrict__ Bhi, const __nv_bfloat16* __restrict__ Blo,
    __nv_bfloat16* __restrict__ Chi, __nv_bfloat16* __restrict__ Clo, float scale,
    int m0, int n0)
{
    extern __shared__ char smem[];
    const uint32_t sb = smem_u32(smem);
    const int tid  = threadIdx.x;
    const int wid  = tid >> 5;
    const int lane = tid & 31;
    const int m0w = (wid & 1) * 64;
    const int n0w = (wid >> 1) * 32;

    const char* src[4] = {(const char*)Ahi, (const char*)Alo,
                          (const char*)Bhi, (const char*)Blo};

    const int r0c = tid >> 2;
    const int c16 = tid & 3;
    size_t goff[4][2];
#pragma unroll
    for (int arr = 0; arr < 4; arr++) {
        const int tb = (arr < 2) ? m0 : n0;
#pragma unroll
        for (int it = 0; it < 2; it++)
            goff[arr][it] = (size_t)(tb + r0c + it * 64) * 2048 + c16 * 16;
    }
    const uint32_t soff0 = r0c * ROW_B + c16 * 16;
    const uint32_t soff1 = (r0c + 64) * ROW_B + c16 * 16;

    float acc[4][4][4];
#pragma unroll
    for (int i = 0; i < 4; i++)
#pragma unroll
        for (int j = 0; j < 4; j++)
#pragma unroll
            for (int k = 0; k < 4; k++) acc[i][j][k] = 0.f;

    const int lrow = lane & 15;
    const int lch  = lane >> 4;
    const uint32_t a_lbase = (uint32_t)(m0w + lrow) * ROW_B + lch * 16;
    const uint32_t b_lbase = (uint32_t)(n0w + lrow) * ROW_B + lch * 16;

#pragma unroll
    for (int arr = 0; arr < 4; arr++) {
        cp16(sb + arr * ARR_SZ + soff0, src[arr] + goff[arr][0]);
        cp16(sb + arr * ARR_SZ + soff1, src[arr] + goff[arr][1]);
    }
    CP_COMMIT();
    CP_WAIT0();
    __syncthreads();

    for (int kc = 0; kc < NSTAGE; kc++) {
        const int cb = kc & 1;
        if (kc + 1 < NSTAGE) {
            const size_t kb = (size_t)(kc + 1) * 64;
            const uint32_t db = sb + (cb ^ 1) * BUF_SZ;
#pragma unroll
            for (int arr = 0; arr < 4; arr++) {
                cp16(db + arr * ARR_SZ + soff0, src[arr] + goff[arr][0] + kb);
                cp16(db + arr * ARR_SZ + soff1, src[arr] + goff[arr][1] + kb);
            }
            CP_COMMIT();
        }

        const uint32_t bufb = sb + cb * BUF_SZ;
#pragma unroll
        for (int ks = 0; ks < 2; ks++) {
            uint32_t ah[4][4], bh[2][4];
#pragma unroll
            for (int mi = 0; mi < 4; mi++)
                ldm_x4(ah[mi], bufb + 0 * ARR_SZ + a_lbase
                                 + mi * (16 * ROW_B) + ks * 32);
#pragma unroll
            for (int ni = 0; ni < 2; ni++)
                ldm_x4(bh[ni], bufb + 2 * ARR_SZ + b_lbase
                                 + ni * (16 * ROW_B) + ks * 32);
#pragma unroll
            for (int mi = 0; mi < 4; mi++)
#pragma unroll
                for (int ni = 0; ni < 2; ni++) {
                    mma_bf16(acc[mi][ni * 2 + 0], ah[mi], bh[ni][0], bh[ni][2]);
                    mma_bf16(acc[mi][ni * 2 + 1], ah[mi], bh[ni][1], bh[ni][3]);
                }
            {
                uint32_t bl[2][4];
#pragma unroll
                for (int ni = 0; ni < 2; ni++)
                    ldm_x4(bl[ni], bufb + 3 * ARR_SZ + b_lbase
                                     + ni * (16 * ROW_B) + ks * 32);
#pragma unroll
                for (int mi = 0; mi < 4; mi++)
#pragma unroll
                    for (int ni = 0; ni < 2; ni++) {
                        mma_bf16(acc[mi][ni * 2 + 0], ah[mi], bl[ni][0], bl[ni][2]);
                        mma_bf16(acc[mi][ni * 2 + 1], ah[mi], bl[ni][1], bl[ni][3]);
                    }
            }
            {
                uint32_t al[4][4];
#pragma unroll
                for (int mi = 0; mi < 4; mi++)
                    ldm_x4(al[mi], bufb + 1 * ARR_SZ + a_lbase
                                     + mi * (16 * ROW_B) + ks * 32);
#pragma unroll
                for (int mi = 0; mi < 4; mi++)
#pragma unroll
                    for (int ni = 0; ni < 2; ni++) {
                        mma_bf16(acc[mi][ni * 2 + 0], al[mi], bh[ni][0], bh[ni][2]);
                        mma_bf16(acc[mi][ni * 2 + 1], al[mi], bh[ni][1], bh[ni][3]);
                    }
            }
        }

        CP_WAIT0();
        __syncthreads();
    }

    const int erow = lane >> 2;
    const int ecol = (lane & 3) * 2;
#pragma unroll
    for (int mi = 0; mi < 4; mi++) {
#pragma unroll
        for (int nj = 0; nj < 4; nj++) {
            size_t base0 = (size_t)(m0 + m0w + mi * 16 + erow) * Dn
                         + n0 + n0w + nj * 8 + ecol;
#pragma unroll
            for (int half = 0; half < 2; half++) {
                size_t b = base0 + half * 8 * Dn;
                float v0 = acc[mi][nj][half * 2 + 0] * scale;
                float v1 = acc[mi][nj][half * 2 + 1] * scale;
                __nv_bfloat16 h0 = __float2bfloat16(v0);
                __nv_bfloat16 h1 = __float2bfloat16(v1);
                __nv_bfloat16 l0 = __float2bfloat16(v0 - __bfloat162float(h0));
                __nv_bfloat16 l1 = __float2bfloat16(v1 - __bfloat162float(h1));
                *(__nv_bfloat162*)(Chi + b) = __nv_bfloat162(h0, h1);
                *(__nv_bfloat162*)(Clo + b) = __nv_bfloat162(l0, l1);
            }
        }
    }
}

// ---------------------------------------------------------------------------
// fp16 2-term GEMM body (V and O projections).
// EPI = 0: fp32 output C.  EPI = 2: fp16 single output Cf.
// A = fp16 hi/lo pair (exact split), B = fp16 single.
// ---------------------------------------------------------------------------
template <int EPI>
__device__ __forceinline__ void gemm_fp16_body(
    const __half* __restrict__ Ahi, const __half* __restrict__ Alo,
    const __half* __restrict__ Bf,
    float* __restrict__ C, __half* __restrict__ Cf,
    int m0, int n0)
{
    extern __shared__ char smem[];
    const uint32_t sb = smem_u32(smem);
    const int tid  = threadIdx.x;
    const int wid  = tid >> 5;
    const int lane = tid & 31;
    const int m0w = (wid & 1) * 64;
    const int n0w = (wid >> 1) * 32;

    const char* src[3] = {(const char*)Ahi, (const char*)Alo, (const char*)Bf};

    const int r0c = tid >> 2;
    const int c16 = tid & 3;
    size_t goff[3][2];
#pragma unroll
    for (int arr = 0; arr < 3; arr++) {
        const int tb = (arr < 2) ? m0 : n0;
#pragma unroll
        for (int it = 0; it < 2; it++)
            goff[arr][it] = (size_t)(tb + r0c + it * 64) * 2048 + c16 * 16;
    }
    const uint32_t soff0 = r0c * ROW_B + c16 * 16;
    const uint32_t soff1 = (r0c + 64) * ROW_B + c16 * 16;

    float acc[4][4][4];
#pragma unroll
    for (int i = 0; i < 4; i++)
#pragma unroll
        for (int j = 0; j < 4; j++)
#pragma unroll
            for (int k = 0; k < 4; k++) acc[i][j][k] = 0.f;

    const int lrow = lane & 15;
    const int lch  = lane >> 4;
    const uint32_t a_lbase = (uint32_t)(m0w + lrow) * ROW_B + lch * 16;
    const uint32_t b_lbase = (uint32_t)(n0w + lrow) * ROW_B + lch * 16;

#pragma unroll
    for (int arr = 0; arr < 3; arr++) {
        cp16(sb + arr * ARR_SZ + soff0, src[arr] + goff[arr][0]);
        cp16(sb + arr * ARR_SZ + soff1, src[arr] + goff[arr][1]);
    }
    CP_COMMIT();
    CP_WAIT0();
    __syncthreads();

    for (int kc = 0; kc < NSTAGE; kc++) {
        const int cb = kc & 1;
        if (kc + 1 < NSTAGE) {
            const size_t kb = (size_t)(kc + 1) * 64;
            const uint32_t db = sb + (cb ^ 1) * BUF_SZ;
#pragma unroll
            for (int arr = 0; arr < 3; arr++) {
                cp16(db + arr * ARR_SZ + soff0, src[arr] + goff[arr][0] + kb);
                cp16(db + arr * ARR_SZ + soff1, src[arr] + goff[arr][1] + kb);
            }
            CP_COMMIT();
        }

        const uint32_t bufb = sb + cb * BUF_SZ;
#pragma unroll
        for (int ks = 0; ks < 2; ks++) {
            uint32_t ah[4][4], bf_[2][4];
#pragma unroll
            for (int mi = 0; mi < 4; mi++)
                ldm_x4(ah[mi], bufb + 0 * ARR_SZ + a_lbase
                                 + mi * (16 * ROW_B) + ks * 32);
#pragma unroll
            for (int ni = 0; ni < 2; ni++)
                ldm_x4(bf_[ni], bufb + 2 * ARR_SZ + b_lbase
                                  + ni * (16 * ROW_B) + ks * 32);
            // term 0: A_hi x B
#pragma unroll
            for (int mi = 0; mi < 4; mi++)
#pragma unroll
                for (int ni = 0; ni < 2; ni++) {
                    mma_fp16(acc[mi][ni * 2 + 0], ah[mi], bf_[ni][0], bf_[ni][2]);
                    mma_fp16(acc[mi][ni * 2 + 1], ah[mi], bf_[ni][1], bf_[ni][3]);
                }
            // term 1: A_lo x B (reuse bf_)
            {
                uint32_t al[4][4];
#pragma unroll
                for (int mi = 0; mi < 4; mi++)
                    ldm_x4(al[mi], bufb + 1 * ARR_SZ + a_lbase
                                     + mi * (16 * ROW_B) + ks * 32);
#pragma unroll
                for (int mi = 0; mi < 4; mi++)
#pragma unroll
                    for (int ni = 0; ni < 2; ni++) {
                        mma_fp16(acc[mi][ni * 2 + 0], al[mi], bf_[ni][0], bf_[ni][2]);
                        mma_fp16(acc[mi][ni * 2 + 1], al[mi], bf_[ni][1], bf_[ni][3]);
                    }
            }
        }

        CP_WAIT0();
        __syncthreads();
    }

    const int erow = lane >> 2;
    const int ecol = (lane & 3) * 2;
#pragma unroll
    for (int mi = 0; mi < 4; mi++) {
#pragma unroll
        for (int nj = 0; nj < 4; nj++) {
            size_t base0 = (size_t)(m0 + m0w + mi * 16 + erow) * Dn
                         + n0 + n0w + nj * 8 + ecol;
            if (EPI == 0) {
                *(float2*)(C + base0)          = make_float2(acc[mi][nj][0], acc[mi][nj][1]);
                *(float2*)(C + base0 + 8 * Dn) = make_float2(acc[mi][nj][2], acc[mi][nj][3]);
            } else {
#pragma unroll
                for (int half = 0; half < 2; half++) {
                    size_t b = base0 + half * 8 * Dn;
                    __half h0 = __float2half_rn(acc[mi][nj][half * 2 + 0]);
                    __half h1 = __float2half_rn(acc[mi][nj][half * 2 + 1]);
                    *(__half2*)(Cf + b) = __halves2half2(h0, h1);
                }
            }
        }
    }
}

// Fused Q/K/V projection: grid (24, 64); blockIdx.x selects weight + outputs.
__global__ __launch_bounds__(256, 2) void gemm_qkv(
    const __nv_bfloat16* __restrict__ Ahi, const __nv_bfloat16* __restrict__ Alo,
    const __half* __restrict__ Fhi, const __half* __restrict__ Flo,
    const __nv_bfloat16* __restrict__ Whi, const __nv_bfloat16* __restrict__ Wlo,
    const __half* __restrict__ Wf,
    __nv_bfloat16* __restrict__ Qh, __nv_bfloat16* __restrict__ Ql,
    __nv_bfloat16* __restrict__ Kh, __nv_bfloat16* __restrict__ Kl,
    __half* __restrict__ Vf, float qscale)
{
    const int ng   = blockIdx.x * 128;       // 0..3071
    const int wsel = ng >> 10;               // 0=Q, 1=K, 2=V
    const int n0   = ng & 1023;
    const int m0   = blockIdx.y * 128;
    if (wsel == 0)
        gemm_bf16_body(Ahi, Alo, Whi, Wlo, Qh, Ql, qscale, m0, n0);
    else if (wsel == 1)
        gemm_bf16_body(Ahi, Alo, Whi + (size_t)Dn * Dn, Wlo + (size_t)Dn * Dn,
                       Kh, Kl, 1.0f, m0, n0);
    else
        gemm_fp16_body<2>(Fhi, Flo, Wf, nullptr, Vf, m0, n0);
}

// O projection: fp16 2-term, fp32 output
__global__ __launch_bounds__(256, 2) void gemm_o(
    const __half* __restrict__ AVhi, const __half* __restrict__ AVlo,
    const __half* __restrict__ Wof, float* __restrict__ C)
{
    gemm_fp16_body<0>(AVhi, AVlo, Wof, C, nullptr,
                      blockIdx.y * 128, blockIdx.x * 128);
}

// ---------------------------------------------------------------------------
// Flash attention: QK^T = 3-term bf16 split; P*V = single fp16 MMA.
// Grid (16, 16, 4): 128 q-rows per CTA, 256 threads (8 warps x m16).
// K (bf16 hi/lo) + V (fp16) tiles double-buffered via cp.async.
// Softmax in log2 domain -> MUFU ex2; l summed from fp16-rounded p.
// Epilogue: AV written as fp16 hi/lo (exact split) for the O projection.
// ---------------------------------------------------------------------------
#define FROW 144
#define FARR (64 * FROW)          // 9216
#define QARR (128 * FROW)         // 18432
#define KVBUF (3 * FARR)          // Kh, Kl, Vf = 27648
#define FLASH_SMEM (2 * QARR + 2 * KVBUF)   // 92160

#define KV_PREFETCH(kt_, buf_) do {                                           \
    const uint32_t base_ = sb + 2 * QARR + (uint32_t)(buf_) * KVBUF;          \
    const size_t g0_ = (size_t)(bb * Sn + (kt_) * 64 + kr0) * Dn              \
                     + headoff + kch * 8;                                     \
    const size_t g1_ = g0_ + (size_t)32 * Dn;                                 \
    cp16(base_ + 0 * FARR + kso0, g_Kh + g0_);                                \
    cp16(base_ + 0 * FARR + kso1, g_Kh + g1_);                                \
    cp16(base_ + 1 * FARR + kso0, g_Kl + g0_);                                \
    cp16(base_ + 1 * FARR + kso1, g_Kl + g1_);                                \
    cp16(base_ + 2 * FARR + kso0, g_Vf + g0_);                                \
    cp16(base_ + 2 * FARR + kso1, g_Vf + g1_);                                \
    CP_COMMIT();                                                              \
} while (0)

__global__ __launch_bounds__(256) void flash_mma()
{
    extern __shared__ char sm[];
    const uint32_t sb = smem_u32(sm);
    const int tid = threadIdx.x;
    const int lane = tid & 31;
    const int w = tid >> 5;
    const int qt = blockIdx.x, hh = blockIdx.y, bb = blockIdx.z;

    const size_t headoff = (size_t)hh * 64;

    const int kr0 = tid >> 3;
    const int kch = tid & 7;
    const uint32_t kso0 = (uint32_t)kr0 * FROW + kch * 16;
    const uint32_t kso1 = (uint32_t)(kr0 + 32) * FROW + kch * 16;

    KV_PREFETCH(0, 0);

#pragma unroll
    for (int i = 0; i < 4; i++) {
        const int idx = tid + 256 * i;
        const int r = idx >> 3, ch = idx & 7;
        const size_t g = (size_t)(bb * Sn + qt * 128 + r) * Dn + headoff + ch * 8;
        const uint32_t so = r * FROW + ch * 16;
        *(uint4*)(sm + so)        = *(const uint4*)(g_Qh + g);
        *(uint4*)(sm + QARR + so) = *(const uint4*)(g_Ql + g);
    }

    const int lrow = lane & 15;
    const int lch  = lane >> 4;
    const uint32_t aoff = (uint32_t)(w * 16 + lrow) * FROW + lch * 16;
    uint32_t boff[4];
#pragma unroll
    for (int np = 0; np < 4; np++)
        boff[np] = (uint32_t)(np * 16 + lrow) * FROW + lch * 16;

    float o[8][4];
#pragma unroll
    for (int j = 0; j < 8; j++)
#pragma unroll
        for (int k = 0; k < 4; k++) o[j][k] = 0.f;
    float m0r = -1e30f, m1r = -1e30f, l0r = 0.f, l1r = 0.f;

    for (int kt = 0; kt < Sn / 64; kt++) {
        const int buf = kt & 1;
        CP_WAIT0();
        __syncthreads();

        if (kt + 1 < Sn / 64)
            KV_PREFETCH(kt + 1, buf ^ 1);

        const uint32_t kvb = sb + 2 * QARR + (uint32_t)buf * KVBUF;

        float s[8][4];
#pragma unroll
        for (int j = 0; j < 8; j++)
#pragma unroll
            for (int k = 0; k < 4; k++) s[j][k] = 0.f;

#pragma unroll
        for (int ks = 0; ks < 4; ks++) {
            uint32_t qh[4], ql[4];
            ldm_x4(qh, sb + aoff + ks * 32);
            ldm_x4(ql, sb + QARR + aoff + ks * 32);
#pragma unroll
            for (int np = 0; np < 4; np++) {
                uint32_t kh[4], kl[4];
                ldm_x4(kh, kvb + 0 * FARR + boff[np] + ks * 32);
                ldm_x4(kl, kvb + 1 * FARR + boff[np] + ks * 32);
                mma_bf16(s[2 * np + 0], qh, kh[0], kh[2]);
                mma_bf16(s[2 * np + 1], qh, kh[1], kh[3]);
                mma_bf16(s[2 * np + 0], qh, kl[0], kl[2]);
                mma_bf16(s[2 * np + 1], qh, kl[1], kl[3]);
                mma_bf16(s[2 * np + 0], ql, kh[0], kh[2]);
                mma_bf16(s[2 * np + 1], ql, kh[1], kh[3]);
            }
        }

        float mx0 = -1e30f, mx1 = -1e30f;
#pragma unroll
        for (int j = 0; j < 8; j++) {
            mx0 = fmaxf(mx0, fmaxf(s[j][0], s[j][1]));
            mx1 = fmaxf(mx1, fmaxf(s[j][2], s[j][3]));
        }
        mx0 = fmaxf(mx0, __shfl_xor_sync(0xffffffffu, mx0, 1));
        mx0 = fmaxf(mx0, __shfl_xor_sync(0xffffffffu, mx0, 2));
        mx1 = fmaxf(mx1, __shfl_xor_sync(0xffffffffu, mx1, 1));
        mx1 = fmaxf(mx1, __shfl_xor_sync(0xffffffffu, mx1, 2));

        const float mn0 = fmaxf(m0r, mx0);
        const float mn1 = fmaxf(m1r, mx1);
        const float a0 = fast_ex2(m0r - mn0);
        const float a1 = fast_ex2(m1r - mn1);
        m0r = mn0; m1r = mn1;

        uint32_t pf[8][2];
        float sum0 = 0.f, sum1 = 0.f;
#pragma unroll
        for (int j = 0; j < 8; j++) {
            float p00 = fast_ex2(s[j][0] - mn0);
            float p01 = fast_ex2(s[j][1] - mn0);
            float p10 = fast_ex2(s[j][2] - mn1);
            float p11 = fast_ex2(s[j][3] - mn1);
            __half h00 = __float2half_rn(p00);
            __half h01 = __float2half_rn(p01);
            __half h10 = __float2half_rn(p10);
            __half h11 = __float2half_rn(p11);
            sum0 += __half2float(h00) + __half2float(h01);
            sum1 += __half2float(h10) + __half2float(h11);
            pf[j][0] = ((uint32_t)__half_as_ushort(h01) << 16)
                     |  (uint32_t)__half_as_ushort(h00);
            pf[j][1] = ((uint32_t)__half_as_ushort(h11) << 16)
                     |  (uint32_t)__half_as_ushort(h10);
        }
        sum0 += __shfl_xor_sync(0xffffffffu, sum0, 1);
        sum0 += __shfl_xor_sync(0xffffffffu, sum0, 2);
        sum1 += __shfl_xor_sync(0xffffffffu, sum1, 1);
        sum1 += __shfl_xor_sync(0xffffffffu, sum1, 2);
        l0r = l0r * a0 + sum0;
        l1r = l1r * a1 + sum1;

#pragma unroll
        for (int j = 0; j < 8; j++) {
            o[j][0] *= a0; o[j][1] *= a0;
            o[j][2] *= a1; o[j][3] *= a1;
        }

#pragma unroll
        for (int ks = 0; ks < 4; ks++) {
            uint32_t ap[4] = {pf[2 * ks][0], pf[2 * ks][1],
                              pf[2 * ks + 1][0], pf[2 * ks + 1][1]};
            const uint32_t vbase = (uint32_t)(ks * 16 + lrow) * FROW + lch * 16;
#pragma unroll
            for (int np = 0; np < 4; np++) {
                uint32_t vf[4];
                ldm_x4t(vf, kvb + 2 * FARR + vbase + np * 32);
                mma_fp16(o[2 * np + 0], ap, vf[0], vf[1]);
                mma_fp16(o[2 * np + 1], ap, vf[2], vf[3]);
            }
        }
        __syncthreads();
    }

    // Epilogue: normalize, split to fp16 hi/lo, write AV
    const float inv0 = 1.0f / l0r;
    const float inv1 = 1.0f / l1r;
    const size_t row0 = (size_t)(bb * Sn + qt * 128 + w * 16 + (lane >> 2));
    const size_t row1 = row0 + 8;
    const size_t colb = headoff + (lane & 3) * 2;
#pragma unroll
    for (int j = 0; j < 8; j++) {
        float v0 = o[j][0] * inv0, v1 = o[j][1] * inv0;
        float v2 = o[j][2] * inv1, v3 = o[j][3] * inv1;
        __half h0 = __float2half_rn(v0);
        __half h1 = __float2half_rn(v1);
        __half h2 = __float2half_rn(v2);
        __half h3 = __float2half_rn(v3);
        size_t b0 = row0 * Dn + colb + j * 8;
        size_t b1 = row1 * Dn + colb + j * 8;
        *(__half2*)(g_AVfh + b0) = __halves2half2(h0, h1);
        *(__half2*)(g_AVfh + b1) = __halves2half2(h2, h3);
        *(__half2*)(g_AVfl + b0) =
            __halves2half2(__float2half_rn(v0 - __half2float(h0)),
                           __float2half_rn(v1 - __half2float(h1)));
        *(__half2*)(g_AVfl + b1) =
            __halves2half2(__float2half_rn(v2 - __half2float(h2)),
                           __float2half_rn(v3 - __half2float(h3)));
    }
}

// ---------------------------------------------------------------------------
// Residual + LayerNorm
// ---------------------------------------------------------------------------
__global__ __launch_bounds__(256) void ln_residual(
    const float* __restrict__ h, const float* __restrict__ gamma,
    const float* __restrict__ beta, float* __restrict__ out)
{
    const int row = blockIdx.x;
    const int tid = threadIdx.x;

    const float4 hv = *(const float4*)(h + row * Dn + tid * 4);
    const float4 av = *(const float4*)(g_AO + row * Dn + tid * 4);
    float4 x = make_float4(hv.x + av.x, hv.y + av.y, hv.z + av.z, hv.w + av.w);

    float s  = x.x + x.y + x.z + x.w;
    float ss = x.x * x.x + x.y * x.y + x.z * x.z + x.w * x.w;
#pragma unroll
    for (int off = 16; off > 0; off >>= 1) {
        s  += __shfl_xor_sync(0xffffffffu, s, off);
        ss += __shfl_xor_sync(0xffffffffu, ss, off);
    }
    __shared__ float rs[8], rss[8];
    if ((tid & 31) == 0) { rs[tid >> 5] = s; rss[tid >> 5] = ss; }
    __syncthreads();
    s = 0.f; ss = 0.f;
#pragma unroll
    for (int w = 0; w < 8; w++) { s += rs[w]; ss += rss[w]; }

    const float mu  = s * (1.0f / Dn);
    const float var = ss * (1.0f / Dn) - mu * mu;
    const float inv = rsqrtf(var + 1e-5f);

    const float4 g4 = *(const float4*)(gamma + tid * 4);
    const float4 b4 = *(const float4*)(beta + tid * 4);
    float4 r;
    r.x = g4.x * (x.x - mu) * inv + b4.x;
    r.y = g4.y * (x.y - mu) * inv + b4.y;
    r.z = g4.z * (x.z - mu) * inv + b4.z;
    r.w = g4.w * (x.w - mu) * inv + b4.w;
    *(float4*)(out + row * Dn + tid * 4) = r;
}

// ---------------------------------------------------------------------------
extern "C" void kernel_launch(void* const* d_in, const int* in_sizes, int n_in,
                              void* d_out, int out_size)
{
    (void)in_sizes; (void)n_in; (void)out_size;
    const float* h     = (const float*)d_in[0];
    const float* Wq    = (const float*)d_in[1];
    const float* Wk    = (const float*)d_in[2];
    const float* Wv    = (const float*)d_in[3];
    const float* Wo    = (const float*)d_in[4];
    const float* gamma = (const float*)d_in[5];
    const float* beta  = (const float*)d_in[6];
    float* out = (float*)d_out;

    float* AOp;
    __nv_bfloat16 *hAhi, *hAlo, *Whi, *Wlo, *Qh, *Ql, *Kh, *Kl;
    __half *hFhi, *hFlo, *Wf, *Vf, *AVfh, *AVfl;
    cudaGetSymbolAddress((void**)&AOp,  g_AO);
    cudaGetSymbolAddress((void**)&hAhi, g_hA_hi);
    cudaGetSymbolAddress((void**)&hAlo, g_hA_lo);
    cudaGetSymbolAddress((void**)&hFhi, g_hF_hi);
    cudaGetSymbolAddress((void**)&hFlo, g_hF_lo);
    cudaGetSymbolAddress((void**)&Whi,  g_W_hi);
    cudaGetSymbolAddress((void**)&Wlo,  g_W_lo);
    cudaGetSymbolAddress((void**)&Wf,   g_Wf);
    cudaGetSymbolAddress((void**)&Qh,   g_Qh);
    cudaGetSymbolAddress((void**)&Ql,   g_Ql);
    cudaGetSymbolAddress((void**)&Kh,   g_Kh);
    cudaGetSymbolAddress((void**)&Kl,   g_Kl);
    cudaGetSymbolAddress((void**)&Vf,   g_Vf);
    cudaGetSymbolAddress((void**)&AVfh, g_AVfh);
    cudaGetSymbolAddress((void**)&AVfl, g_AVfl);

    cudaFuncSetAttribute(gemm_qkv, cudaFuncAttributeMaxDynamicSharedMemorySize,
                         GEMM_SMEM);
    cudaFuncSetAttribute(gemm_o, cudaFuncAttributeMaxDynamicSharedMemorySize,
                         GEMM_SMEM);
    cudaFuncSetAttribute(flash_mma, cudaFuncAttributeMaxDynamicSharedMemorySize,
                         FLASH_SMEM);

    // Split h (bf16 + fp16 pairs) and weights
    split_h<<<Mn * Dn / 1024, 256>>>(h, hAhi, hAlo, hFhi, hFlo);
    split_T4<<<dim3(32, 32, 4), dim3(32, 8)>>>(Wq, Wk, Wv, Wo, Whi, Wlo, Wf);

    // Fused Q/K/V projections (Q pre-scaled by 1/8 * log2(e); V 2-term fp16)
    const float QSCALE = 0.125f * 1.4426950408889634f;
    gemm_qkv<<<dim3(24, Mn / 128), 256, GEMM_SMEM>>>(
        hAhi, hAlo, hFhi, hFlo, Whi, Wlo, Wf, Qh, Ql, Kh, Kl, Vf, QSCALE);

    // Attention (tensorized flash, fp16 PV, fp16 hi/lo AV out)
    flash_mma<<<dim3(Sn / 128, Hn, Bn), 256, FLASH_SMEM>>>();

    // Output projection (2-term fp16)
    gemm_o<<<dim3(Dn / 128, Mn / 128), 256, GEMM_SMEM>>>(
        AVfh, AVfl, Wf + (size_t)Dn * Dn, AOp);

    ln_residual<<<Mn, 256>>>(h, gamma, beta, out);
}

// round 12
// speedup vs baseline: 1.4090x; 1.0297x over previous
#include <cuda_runtime.h>
#include <cuda_bf16.h>
#include <cuda_fp16.h>
#include <cstdint>
#include <math.h>

#define Bn 4
#define Sn 2048
#define Dn 1024
#define Hn 16
#define DHn 64
#define Mn (Bn * Sn)   // 8192

// ---------------------------------------------------------------------------
// Device scratch
// ---------------------------------------------------------------------------
__device__ float g_AO[Mn * Dn];

__device__ __nv_bfloat16 g_hA_hi[Mn * Dn];
__device__ __nv_bfloat16 g_hA_lo[Mn * Dn];
__device__ __half        g_hF_hi[Mn * Dn];   // fp16 split of h (for V gemm)
__device__ __half        g_hF_lo[Mn * Dn];
__device__ __nv_bfloat16 g_W_hi[2 * Dn * Dn];   // bf16 [N,K]: q, k
__device__ __nv_bfloat16 g_W_lo[2 * Dn * Dn];
__device__ __half        g_Wf[2 * Dn * Dn];     // fp16 [N,K]: v, o

__device__ __nv_bfloat16 g_Qh[Mn * Dn];  // pre-scaled by 0.125*log2(e)
__device__ __nv_bfloat16 g_Ql[Mn * Dn];
__device__ __nv_bfloat16 g_Kh[Mn * Dn];
__device__ __nv_bfloat16 g_Kl[Mn * Dn];
__device__ __half        g_Vf[Mn * Dn];  // V in single fp16
__device__ __half        g_AVfh[Mn * Dn];   // AV fp16 hi/lo split
__device__ __half        g_AVfl[Mn * Dn];

// ---------------------------------------------------------------------------
__device__ __forceinline__ uint32_t smem_u32(const void* p) {
    uint32_t a;
    asm("{ .reg .u64 t; cvta.to.shared.u64 t, %1; cvt.u32.u64 %0, t; }"
        : "=r"(a) : "l"(p));
    return a;
}

__device__ __forceinline__ float fast_ex2(float x) {
    float r;
    asm("ex2.approx.ftz.f32 %0, %1;" : "=f"(r) : "f"(x));
    return r;
}

// pack two floats into fp16x2 in ONE instruction (lo -> low half)
__device__ __forceinline__ uint32_t pack_f16x2(float lo, float hi) {
    uint32_t d;
    asm("cvt.rn.f16x2.f32 %0, %1, %2;" : "=r"(d) : "f"(hi), "f"(lo));
    return d;
}

__device__ __forceinline__ void ldm_x4(uint32_t* r, uint32_t addr) {
    asm volatile("ldmatrix.sync.aligned.m8n8.x4.shared.b16 {%0,%1,%2,%3}, [%4];"
                 : "=r"(r[0]), "=r"(r[1]), "=r"(r[2]), "=r"(r[3]) : "r"(addr));
}
__device__ __forceinline__ void ldm_x4t(uint32_t* r, uint32_t addr) {
    asm volatile("ldmatrix.sync.aligned.m8n8.x4.trans.shared.b16 {%0,%1,%2,%3}, [%4];"
                 : "=r"(r[0]), "=r"(r[1]), "=r"(r[2]), "=r"(r[3]) : "r"(addr));
}

__device__ __forceinline__ void mma_bf16(float* c, const uint32_t* a,
                                         uint32_t b0, uint32_t b1) {
    asm volatile(
        "mma.sync.aligned.m16n8k16.row.col.f32.bf16.bf16.f32 "
        "{%0,%1,%2,%3}, {%4,%5,%6,%7}, {%8,%9}, {%0,%1,%2,%3};"
        : "+f"(c[0]), "+f"(c[1]), "+f"(c[2]), "+f"(c[3])
        : "r"(a[0]), "r"(a[1]), "r"(a[2]), "r"(a[3]), "r"(b0), "r"(b1));
}

__device__ __forceinline__ void mma_fp16(float* c, const uint32_t* a,
                                         uint32_t b0, uint32_t b1) {
    asm volatile(
        "mma.sync.aligned.m16n8k16.row.col.f32.f16.f16.f32 "
        "{%0,%1,%2,%3}, {%4,%5,%6,%7}, {%8,%9}, {%0,%1,%2,%3};"
        : "+f"(c[0]), "+f"(c[1]), "+f"(c[2]), "+f"(c[3])
        : "r"(a[0]), "r"(a[1]), "r"(a[2]), "r"(a[3]), "r"(b0), "r"(b1));
}

__device__ __forceinline__ void cp16(uint32_t s, const void* g) {
    asm volatile("cp.async.cg.shared.global [%0], [%1], 16;" :: "r"(s), "l"(g));
}
#define CP_COMMIT() asm volatile("cp.async.commit_group;" ::: "memory")
#define CP_WAIT0()  asm volatile("cp.async.wait_group 0;" ::: "memory")
#define CP_WAIT1()  asm volatile("cp.async.wait_group 1;" ::: "memory")

// ---------------------------------------------------------------------------
// Split fp32 h -> bf16 (hi,lo) AND fp16 (hi,lo)
// ---------------------------------------------------------------------------
__global__ __launch_bounds__(256) void split_h(
    const float* __restrict__ x,
    __nv_bfloat16* __restrict__ bhi, __nv_bfloat16* __restrict__ blo,
    __half* __restrict__ fhi, __half* __restrict__ flo)
{
    const int i = (blockIdx.x * 256 + threadIdx.x) * 4;
    float4 v = *(const float4*)(x + i);
    float vv[4] = {v.x, v.y, v.z, v.w};
    __nv_bfloat16 bh[4], bl[4];
    __half fh[4], fl[4];
#pragma unroll
    for (int k = 0; k < 4; k++) {
        bh[k] = __float2bfloat16(vv[k]);
        bl[k] = __float2bfloat16(vv[k] - __bfloat162float(bh[k]));
        fh[k] = __float2half_rn(vv[k]);
        fl[k] = __float2half_rn(vv[k] - __half2float(fh[k]));
    }
    __nv_bfloat162* bhp = (__nv_bfloat162*)(bhi + i);
    __nv_bfloat162* blp = (__nv_bfloat162*)(blo + i);
    bhp[0] = __nv_bfloat162(bh[0], bh[1]); bhp[1] = __nv_bfloat162(bh[2], bh[3]);
    blp[0] = __nv_bfloat162(bl[0], bl[1]); blp[1] = __nv_bfloat162(bl[2], bl[3]);
    __half2* fhp = (__half2*)(fhi + i);
    __half2* flp = (__half2*)(flo + i);
    fhp[0] = __halves2half2(fh[0], fh[1]); fhp[1] = __halves2half2(fh[2], fh[3]);
    flp[0] = __halves2half2(fl[0], fl[1]); flp[1] = __halves2half2(fl[2], fl[3]);
}

// ---------------------------------------------------------------------------
// Split + transpose weights: z=0,1 (Wq,Wk) -> bf16 hi/lo [N,K];
//                            z=2,3 (Wv,Wo) -> fp16 single [N,K].
// ---------------------------------------------------------------------------
__global__ __launch_bounds__(256) void split_T4(
    const float* __restrict__ W0, const float* __restrict__ W1,
    const float* __restrict__ W2, const float* __restrict__ W3,
    __nv_bfloat16* __restrict__ hiT, __nv_bfloat16* __restrict__ loT,
    __half* __restrict__ fT)
{
    const int z = blockIdx.z;
    const float* W = (z == 0) ? W0 : (z == 1) ? W1 : (z == 2) ? W2 : W3;

    __shared__ float t[32][33];
    const int tx = threadIdx.x, ty = threadIdx.y;
    const int bn = blockIdx.x * 32, bk = blockIdx.y * 32;
#pragma unroll
    for (int j = 0; j < 4; j++)
        t[ty + j * 8][tx] = W[(size_t)(bk + ty + j * 8) * Dn + bn + tx];
    __syncthreads();
#pragma unroll
    for (int j = 0; j < 4; j++) {
        float v = t[tx][ty + j * 8];
        size_t o = (size_t)(bn + ty + j * 8) * Dn + bk + tx;
        if (z < 2) {
            __nv_bfloat16 h = __float2bfloat16(v);
            __nv_bfloat16 l = __float2bfloat16(v - __bfloat162float(h));
            hiT[(size_t)z * Dn * Dn + o] = h;
            loT[(size_t)z * Dn * Dn + o] = l;
        } else {
            fT[(size_t)(z - 2) * Dn * Dn + o] = __float2half_rn(v);
        }
    }
}

// ---------------------------------------------------------------------------
// Shared GEMM constants.
// ---------------------------------------------------------------------------
#define BK        32
#define NSTAGE    (Dn / BK)          // 32
#define ROW_B     80                 // bytes per smem row (32 elems + 8 pad)
#define ARR_SZ    (128 * ROW_B)      // 10240 bytes per array tile
#define BUF_SZ    (4 * ARR_SZ)       // bf16 body stage (Ahi,Alo,Bhi,Blo)
#define FBUF_SZ   (3 * ARR_SZ)       // fp16 body stage (Ahi,Alo,Bf)
#define GEMM_SMEM (3 * FBUF_SZ)      // 92160 (covers bf16's 2*BUF_SZ=81920)

// ---------------------------------------------------------------------------
// bf16 3-term GEMM body (Q/K projections), 2-stage double buffer.
// ---------------------------------------------------------------------------
__device__ __forceinline__ void gemm_bf16_body(
    const __nv_bfloat16* __restrict__ Ahi, const __nv_bfloat16* __restrict__ Alo,
    const __nv_bfloat16* __restrict__ Bhi, const __nv_bfloat16* __restrict__ Blo,
    __nv_bfloat16* __restrict__ Chi, __nv_bfloat16* __restrict__ Clo, float scale,
    int m0, int n0)
{
    extern __shared__ char smem[];
    const uint32_t sb = smem_u32(smem);
    const int tid  = threadIdx.x;
    const int wid  = tid >> 5;
    const int lane = tid & 31;
    const int m0w = (wid & 1) * 64;
    const int n0w = (wid >> 1) * 32;

    const char* src[4] = {(const char*)Ahi, (const char*)Alo,
                          (const char*)Bhi, (const char*)Blo};

    const int r0c = tid >> 2;
    const int c16 = tid & 3;
    size_t goff[4][2];
#pragma unroll
    for (int arr = 0; arr < 4; arr++) {
        const int tb = (arr < 2) ? m0 : n0;
#pragma unroll
        for (int it = 0; it < 2; it++)
            goff[arr][it] = (size_t)(tb + r0c + it * 64) * 2048 + c16 * 16;
    }
    const uint32_t soff0 = r0c * ROW_B + c16 * 16;
    const uint32_t soff1 = (r0c + 64) * ROW_B + c16 * 16;

    float acc[4][4][4];
#pragma unroll
    for (int i = 0; i < 4; i++)
#pragma unroll
        for (int j = 0; j < 4; j++)
#pragma unroll
            for (int k = 0; k < 4; k++) acc[i][j][k] = 0.f;

    const int lrow = lane & 15;
    const int lch  = lane >> 4;
    const uint32_t a_lbase = (uint32_t)(m0w + lrow) * ROW_B + lch * 16;
    const uint32_t b_lbase = (uint32_t)(n0w + lrow) * ROW_B + lch * 16;

#pragma unroll
    for (int arr = 0; arr < 4; arr++) {
        cp16(sb + arr * ARR_SZ + soff0, src[arr] + goff[arr][0]);
        cp16(sb + arr * ARR_SZ + soff1, src[arr] + goff[arr][1]);
    }
    CP_COMMIT();
    CP_WAIT0();
    __syncthreads();

    for (int kc = 0; kc < NSTAGE; kc++) {
        const int cb = kc & 1;
        if (kc + 1 < NSTAGE) {
            const size_t kb = (size_t)(kc + 1) * 64;
            const uint32_t db = sb + (cb ^ 1) * BUF_SZ;
#pragma unroll
            for (int arr = 0; arr < 4; arr++) {
                cp16(db + arr * ARR_SZ + soff0, src[arr] + goff[arr][0] + kb);
                cp16(db + arr * ARR_SZ + soff1, src[arr] + goff[arr][1] + kb);
            }
            CP_COMMIT();
        }

        const uint32_t bufb = sb + cb * BUF_SZ;
#pragma unroll
        for (int ks = 0; ks < 2; ks++) {
            uint32_t ah[4][4], bh[2][4];
#pragma unroll
            for (int mi = 0; mi < 4; mi++)
                ldm_x4(ah[mi], bufb + 0 * ARR_SZ + a_lbase
                                 + mi * (16 * ROW_B) + ks * 32);
#pragma unroll
            for (int ni = 0; ni < 2; ni++)
                ldm_x4(bh[ni], bufb + 2 * ARR_SZ + b_lbase
                                 + ni * (16 * ROW_B) + ks * 32);
#pragma unroll
            for (int mi = 0; mi < 4; mi++)
#pragma unroll
                for (int ni = 0; ni < 2; ni++) {
                    mma_bf16(acc[mi][ni * 2 + 0], ah[mi], bh[ni][0], bh[ni][2]);
                    mma_bf16(acc[mi][ni * 2 + 1], ah[mi], bh[ni][1], bh[ni][3]);
                }
            {
                uint32_t bl[2][4];
#pragma unroll
                for (int ni = 0; ni < 2; ni++)
                    ldm_x4(bl[ni], bufb + 3 * ARR_SZ + b_lbase
                                     + ni * (16 * ROW_B) + ks * 32);
#pragma unroll
                for (int mi = 0; mi < 4; mi++)
#pragma unroll
                    for (int ni = 0; ni < 2; ni++) {
                        mma_bf16(acc[mi][ni * 2 + 0], ah[mi], bl[ni][0], bl[ni][2]);
                        mma_bf16(acc[mi][ni * 2 + 1], ah[mi], bl[ni][1], bl[ni][3]);
                    }
            }
            {
                uint32_t al[4][4];
#pragma unroll
                for (int mi = 0; mi < 4; mi++)
                    ldm_x4(al[mi], bufb + 1 * ARR_SZ + a_lbase
                                     + mi * (16 * ROW_B) + ks * 32);
#pragma unroll
                for (int mi = 0; mi < 4; mi++)
#pragma unroll
                    for (int ni = 0; ni < 2; ni++) {
                        mma_bf16(acc[mi][ni * 2 + 0], al[mi], bh[ni][0], bh[ni][2]);
                        mma_bf16(acc[mi][ni * 2 + 1], al[mi], bh[ni][1], bh[ni][3]);
                    }
            }
        }

        CP_WAIT0();
        __syncthreads();
    }

    const int erow = lane >> 2;
    const int ecol = (lane & 3) * 2;
#pragma unroll
    for (int mi = 0; mi < 4; mi++) {
#pragma unroll
        for (int nj = 0; nj < 4; nj++) {
            size_t base0 = (size_t)(m0 + m0w + mi * 16 + erow) * Dn
                         + n0 + n0w + nj * 8 + ecol;
#pragma unroll
            for (int half = 0; half < 2; half++) {
                size_t b = base0 + half * 8 * Dn;
                float v0 = acc[mi][nj][half * 2 + 0] * scale;
                float v1 = acc[mi][nj][half * 2 + 1] * scale;
                __nv_bfloat16 h0 = __float2bfloat16(v0);
                __nv_bfloat16 h1 = __float2bfloat16(v1);
                __nv_bfloat16 l0 = __float2bfloat16(v0 - __bfloat162float(h0));
                __nv_bfloat16 l1 = __float2bfloat16(v1 - __bfloat162float(h1));
                *(__nv_bfloat162*)(Chi + b) = __nv_bfloat162(h0, h1);
                *(__nv_bfloat162*)(Clo + b) = __nv_bfloat162(l0, l1);
            }
        }
    }
}

// ---------------------------------------------------------------------------
// fp16 2-term GEMM body (V and O projections), 3-stage cp.async ring.
// EPI = 0: fp32 output C.  EPI = 2: fp16 single output Cf.
// ---------------------------------------------------------------------------
template <int EPI>
__device__ __forceinline__ void gemm_fp16_body(
    const __half* __restrict__ Ahi, const __half* __restrict__ Alo,
    const __half* __restrict__ Bf,
    float* __restrict__ C, __half* __restrict__ Cf,
    int m0, int n0)
{
    extern __shared__ char smem[];
    const uint32_t sb = smem_u32(smem);
    const int tid  = threadIdx.x;
    const int wid  = tid >> 5;
    const int lane = tid & 31;
    const int m0w = (wid & 1) * 64;
    const int n0w = (wid >> 1) * 32;

    const char* src[3] = {(const char*)Ahi, (const char*)Alo, (const char*)Bf};

    const int r0c = tid >> 2;
    const int c16 = tid & 3;
    size_t goff[3][2];
#pragma unroll
    for (int arr = 0; arr < 3; arr++) {
        const int tb = (arr < 2) ? m0 : n0;
#pragma unroll
        for (int it = 0; it < 2; it++)
            goff[arr][it] = (size_t)(tb + r0c + it * 64) * 2048 + c16 * 16;
    }
    const uint32_t soff0 = r0c * ROW_B + c16 * 16;
    const uint32_t soff1 = (r0c + 64) * ROW_B + c16 * 16;

    float acc[4][4][4];
#pragma unroll
    for (int i = 0; i < 4; i++)
#pragma unroll
        for (int j = 0; j < 4; j++)
#pragma unroll
            for (int k = 0; k < 4; k++) acc[i][j][k] = 0.f;

    const int lrow = lane & 15;
    const int lch  = lane >> 4;
    const uint32_t a_lbase = (uint32_t)(m0w + lrow) * ROW_B + lch * 16;
    const uint32_t b_lbase = (uint32_t)(n0w + lrow) * ROW_B + lch * 16;

    // Issue stages 0 and 1
#pragma unroll
    for (int st = 0; st < 2; st++) {
        const size_t kb = (size_t)st * 64;
        const uint32_t db = sb + st * FBUF_SZ;
#pragma unroll
        for (int arr = 0; arr < 3; arr++) {
            cp16(db + arr * ARR_SZ + soff0, src[arr] + goff[arr][0] + kb);
            cp16(db + arr * ARR_SZ + soff1, src[arr] + goff[arr][1] + kb);
        }
        CP_COMMIT();
    }
    __syncthreads();

    for (int kc = 0; kc < NSTAGE; kc++) {
        if (kc + 1 < NSTAGE) { CP_WAIT1(); } else { CP_WAIT0(); }
        __syncthreads();

        if (kc + 2 < NSTAGE) {
            const size_t kb = (size_t)(kc + 2) * 64;
            const uint32_t db = sb + ((kc + 2) % 3) * FBUF_SZ;
#pragma unroll
            for (int arr = 0; arr < 3; arr++) {
                cp16(db + arr * ARR_SZ + soff0, src[arr] + goff[arr][0] + kb);
                cp16(db + arr * ARR_SZ + soff1, src[arr] + goff[arr][1] + kb);
            }
            CP_COMMIT();
        }

        const uint32_t bufb = sb + (kc % 3) * FBUF_SZ;
#pragma unroll
        for (int ks = 0; ks < 2; ks++) {
            uint32_t ah[4][4], bf_[2][4];
#pragma unroll
            for (int mi = 0; mi < 4; mi++)
                ldm_x4(ah[mi], bufb + 0 * ARR_SZ + a_lbase
                                 + mi * (16 * ROW_B) + ks * 32);
#pragma unroll
            for (int ni = 0; ni < 2; ni++)
                ldm_x4(bf_[ni], bufb + 2 * ARR_SZ + b_lbase
                                  + ni * (16 * ROW_B) + ks * 32);
#pragma unroll
            for (int mi = 0; mi < 4; mi++)
#pragma unroll
                for (int ni = 0; ni < 2; ni++) {
                    mma_fp16(acc[mi][ni * 2 + 0], ah[mi], bf_[ni][0], bf_[ni][2]);
                    mma_fp16(acc[mi][ni * 2 + 1], ah[mi], bf_[ni][1], bf_[ni][3]);
                }
            {
                uint32_t al[4][4];
#pragma unroll
                for (int mi = 0; mi < 4; mi++)
                    ldm_x4(al[mi], bufb + 1 * ARR_SZ + a_lbase
                                     + mi * (16 * ROW_B) + ks * 32);
#pragma unroll
                for (int mi = 0; mi < 4; mi++)
#pragma unroll
                    for (int ni = 0; ni < 2; ni++) {
                        mma_fp16(acc[mi][ni * 2 + 0], al[mi], bf_[ni][0], bf_[ni][2]);
                        mma_fp16(acc[mi][ni * 2 + 1], al[mi], bf_[ni][1], bf_[ni][3]);
                    }
            }
        }
        // no trailing barrier: next iteration's top barrier protects the ring
    }

    const int erow = lane >> 2;
    const int ecol = (lane & 3) * 2;
#pragma unroll
    for (int mi = 0; mi < 4; mi++) {
#pragma unroll
        for (int nj = 0; nj < 4; nj++) {
            size_t base0 = (size_t)(m0 + m0w + mi * 16 + erow) * Dn
                         + n0 + n0w + nj * 8 + ecol;
            if (EPI == 0) {
                *(float2*)(C + base0)          = make_float2(acc[mi][nj][0], acc[mi][nj][1]);
                *(float2*)(C + base0 + 8 * Dn) = make_float2(acc[mi][nj][2], acc[mi][nj][3]);
            } else {
#pragma unroll
                for (int half = 0; half < 2; half++) {
                    size_t b = base0 + half * 8 * Dn;
                    uint32_t p = pack_f16x2(acc[mi][nj][half * 2 + 0],
                                            acc[mi][nj][half * 2 + 1]);
                    *(uint32_t*)(Cf + b) = p;
                }
            }
        }
    }
}

// Fused Q/K/V projection: grid (24, 64); blockIdx.x selects weight + outputs.
__global__ __launch_bounds__(256, 2) void gemm_qkv(
    const __nv_bfloat16* __restrict__ Ahi, const __nv_bfloat16* __restrict__ Alo,
    const __half* __restrict__ Fhi, const __half* __restrict__ Flo,
    const __nv_bfloat16* __restrict__ Whi, const __nv_bfloat16* __restrict__ Wlo,
    const __half* __restrict__ Wf,
    __nv_bfloat16* __restrict__ Qh, __nv_bfloat16* __restrict__ Ql,
    __nv_bfloat16* __restrict__ Kh, __nv_bfloat16* __restrict__ Kl,
    __half* __restrict__ Vf, float qscale)
{
    const int ng   = blockIdx.x * 128;       // 0..3071
    const int wsel = ng >> 10;               // 0=Q, 1=K, 2=V
    const int n0   = ng & 1023;
    const int m0   = blockIdx.y * 128;
    if (wsel == 0)
        gemm_bf16_body(Ahi, Alo, Whi, Wlo, Qh, Ql, qscale, m0, n0);
    else if (wsel == 1)
        gemm_bf16_body(Ahi, Alo, Whi + (size_t)Dn * Dn, Wlo + (size_t)Dn * Dn,
                       Kh, Kl, 1.0f, m0, n0);
    else
        gemm_fp16_body<2>(Fhi, Flo, Wf, nullptr, Vf, m0, n0);
}

// O projection: fp16 2-term, fp32 output
__global__ __launch_bounds__(256, 2) void gemm_o(
    const __half* __restrict__ AVhi, const __half* __restrict__ AVlo,
    const __half* __restrict__ Wof, float* __restrict__ C)
{
    gemm_fp16_body<0>(AVhi, AVlo, Wof, C, nullptr,
                      blockIdx.y * 128, blockIdx.x * 128);
}

// ---------------------------------------------------------------------------
// Flash attention: QK^T = 3-term bf16 split; P*V = single fp16 MMA.
// Grid (16, 16, 4): 128 q-rows per CTA, 256 threads (8 warps x m16).
// Ql fragments hoisted to registers (staged once through ring buffer 2).
// K (bf16 hi/lo) + V (fp16) in a 3-stage cp.async ring, 2 CTAs/SM.
// Softmax log2 domain -> MUFU ex2, single-instr f16x2 packing.
// ---------------------------------------------------------------------------
#define FROW 144
#define FARR (64 * FROW)          // 9216
#define QARR (128 * FROW)         // 18432
#define KVBUF (3 * FARR)          // Kh, Kl, Vf = 27648
#define FLASH_SMEM (QARR + 3 * KVBUF)   // 101376 -> 2 CTAs/SM

#define KV_PREFETCH(kt_, buf_) do {                                           \
    const uint32_t base_ = sb + QARR + (uint32_t)(buf_) * KVBUF;              \
    const size_t g0_ = (size_t)(bb * Sn + (kt_) * 64 + kr0) * Dn              \
                     + headoff + kch * 8;                                     \
    const size_t g1_ = g0_ + (size_t)32 * Dn;                                 \
    cp16(base_ + 0 * FARR + kso0, g_Kh + g0_);                                \
    cp16(base_ + 0 * FARR + kso1, g_Kh + g1_);                                \
    cp16(base_ + 1 * FARR + kso0, g_Kl + g0_);                                \
    cp16(base_ + 1 * FARR + kso1, g_Kl + g1_);                                \
    cp16(base_ + 2 * FARR + kso0, g_Vf + g0_);                                \
    cp16(base_ + 2 * FARR + kso1, g_Vf + g1_);                                \
    CP_COMMIT();                                                              \
} while (0)

__global__ __launch_bounds__(256, 2) void flash_mma()
{
    extern __shared__ char sm[];
    const uint32_t sb = smem_u32(sm);
    const int tid = threadIdx.x;
    const int lane = tid & 31;
    const int w = tid >> 5;
    const int qt = blockIdx.x, hh = blockIdx.y, bb = blockIdx.z;

    const size_t headoff = (size_t)hh * 64;

    const int kr0 = tid >> 3;
    const int kch = tid & 7;
    const uint32_t kso0 = (uint32_t)kr0 * FROW + kch * 16;
    const uint32_t kso1 = (uint32_t)(kr0 + 32) * FROW + kch * 16;

    // Prologue: Qh -> [0,QARR); Ql staged into ring buffer 2 area.
    const uint32_t qlbase = QARR + 2 * KVBUF;
#pragma unroll
    for (int i = 0; i < 4; i++) {
        const int idx = tid + 256 * i;
        const int r = idx >> 3, ch = idx & 7;
        const size_t g = (size_t)(bb * Sn + qt * 128 + r) * Dn + headoff + ch * 8;
        const uint32_t so = r * FROW + ch * 16;
        *(uint4*)(sm + so)          = *(const uint4*)(g_Qh + g);
        *(uint4*)(sm + qlbase + so) = *(const uint4*)(g_Ql + g);
    }
    // Kick KV stages 0,1 (buffers 0,1 — no conflict with Ql in buffer 2)
    KV_PREFETCH(0, 0);
    KV_PREFETCH(1, 1);
    __syncthreads();

    const int lrow = lane & 15;
    const int lch  = lane >> 4;
    const uint32_t aoff = (uint32_t)(w * 16 + lrow) * FROW + lch * 16;
    uint32_t boff[4];
#pragma unroll
    for (int np = 0; np < 4; np++)
        boff[np] = (uint32_t)(np * 16 + lrow) * FROW + lch * 16;

    // Hoist Ql fragments to registers (read from buffer-2 staging area).
    uint32_t qlf[4][4];
#pragma unroll
    for (int ks = 0; ks < 4; ks++)
        ldm_x4(qlf[ks], sb + qlbase + aoff + ks * 32);

    float o[8][4];
#pragma unroll
    for (int j = 0; j < 8; j++)
#pragma unroll
        for (int k = 0; k < 4; k++) o[j][k] = 0.f;
    float m0r = -1e30f, m1r = -1e30f, l0r = 0.f, l1r = 0.f;

    for (int kt = 0; kt < Sn / 64; kt++) {
        if (kt + 1 < Sn / 64) { CP_WAIT1(); } else { CP_WAIT0(); }
        __syncthreads();   // stage kt resident; all prior reads (incl. qlf) done

        if (kt + 2 < Sn / 64)
            KV_PREFETCH(kt + 2, (kt + 2) % 3);

        const uint32_t kvb = sb + QARR + (uint32_t)(kt % 3) * KVBUF;

        // ---- S = Q*K^T (3 split terms), n=64 keys ----
        float s[8][4];
#pragma unroll
        for (int j = 0; j < 8; j++)
#pragma unroll
            for (int k = 0; k < 4; k++) s[j][k] = 0.f;

#pragma unroll
        for (int ks = 0; ks < 4; ks++) {
            uint32_t qh[4];
            ldm_x4(qh, sb + aoff + ks * 32);
#pragma unroll
            for (int np = 0; np < 4; np++) {
                uint32_t kh[4], kl[4];
                ldm_x4(kh, kvb + 0 * FARR + boff[np] + ks * 32);
                ldm_x4(kl, kvb + 1 * FARR + boff[np] + ks * 32);
                mma_bf16(s[2 * np + 0], qh, kh[0], kh[2]);
                mma_bf16(s[2 * np + 1], qh, kh[1], kh[3]);
                mma_bf16(s[2 * np + 0], qh, kl[0], kl[2]);
                mma_bf16(s[2 * np + 1], qh, kl[1], kl[3]);
                mma_bf16(s[2 * np + 0], qlf[ks], kh[0], kh[2]);
                mma_bf16(s[2 * np + 1], qlf[ks], kh[1], kh[3]);
            }
        }

        // ---- Online softmax, log2 domain ----
        float mx0 = -1e30f, mx1 = -1e30f;
#pragma unroll
        for (int j = 0; j < 8; j++) {
            mx0 = fmaxf(mx0, fmaxf(s[j][0], s[j][1]));
            mx1 = fmaxf(mx1, fmaxf(s[j][2], s[j][3]));
        }
        mx0 = fmaxf(mx0, __shfl_xor_sync(0xffffffffu, mx0, 1));
        mx0 = fmaxf(mx0, __shfl_xor_sync(0xffffffffu, mx0, 2));
        mx1 = fmaxf(mx1, __shfl_xor_sync(0xffffffffu, mx1, 1));
        mx1 = fmaxf(mx1, __shfl_xor_sync(0xffffffffu, mx1, 2));

        const float mn0 = fmaxf(m0r, mx0);
        const float mn1 = fmaxf(m1r, mx1);
        const float a0 = fast_ex2(m0r - mn0);
        const float a1 = fast_ex2(m1r - mn1);
        m0r = mn0; m1r = mn1;

        uint32_t pf[8][2];
        float sum0 = 0.f, sum1 = 0.f;
#pragma unroll
        for (int j = 0; j < 8; j++) {
            float p00 = fast_ex2(s[j][0] - mn0);
            float p01 = fast_ex2(s[j][1] - mn0);
            float p10 = fast_ex2(s[j][2] - mn1);
            float p11 = fast_ex2(s[j][3] - mn1);
            sum0 += p00 + p01;
            sum1 += p10 + p11;
            pf[j][0] = pack_f16x2(p00, p01);
            pf[j][1] = pack_f16x2(p10, p11);
        }
        sum0 += __shfl_xor_sync(0xffffffffu, sum0, 1);
        sum0 += __shfl_xor_sync(0xffffffffu, sum0, 2);
        sum1 += __shfl_xor_sync(0xffffffffu, sum1, 1);
        sum1 += __shfl_xor_sync(0xffffffffu, sum1, 2);
        l0r = l0r * a0 + sum0;
        l1r = l1r * a1 + sum1;

#pragma unroll
        for (int j = 0; j < 8; j++) {
            o[j][0] *= a0; o[j][1] *= a0;
            o[j][2] *= a1; o[j][3] *= a1;
        }

        // ---- O += P * V (single fp16 term), V via ldmatrix.trans ----
#pragma unroll
        for (int ks = 0; ks < 4; ks++) {
            uint32_t ap[4] = {pf[2 * ks][0], pf[2 * ks][1],
                              pf[2 * ks + 1][0], pf[2 * ks + 1][1]};
            const uint32_t vbase = (uint32_t)(ks * 16 + lrow) * FROW + lch * 16;
#pragma unroll
            for (int np = 0; np < 4; np++) {
                uint32_t vf[4];
                ldm_x4t(vf, kvb + 2 * FARR + vbase + np * 32);
                mma_fp16(o[2 * np + 0], ap, vf[0], vf[1]);
                mma_fp16(o[2 * np + 1], ap, vf[2], vf[3]);
            }
        }
        // no trailing barrier: next iteration's top barrier protects the ring
    }

    // Epilogue: normalize, split to fp16 hi/lo, write AV
    const float inv0 = 1.0f / l0r;
    const float inv1 = 1.0f / l1r;
    const size_t row0 = (size_t)(bb * Sn + qt * 128 + w * 16 + (lane >> 2));
    const size_t row1 = row0 + 8;
    const size_t colb = headoff + (lane & 3) * 2;
#pragma unroll
    for (int j = 0; j < 8; j++) {
        float v0 = o[j][0] * inv0, v1 = o[j][1] * inv0;
        float v2 = o[j][2] * inv1, v3 = o[j][3] * inv1;
        __half h0 = __float2half_rn(v0);
        __half h1 = __float2half_rn(v1);
        __half h2 = __float2half_rn(v2);
        __half h3 = __float2half_rn(v3);
        size_t b0 = row0 * Dn + colb + j * 8;
        size_t b1 = row1 * Dn + colb + j * 8;
        *(__half2*)(g_AVfh + b0) = __halves2half2(h0, h1);
        *(__half2*)(g_AVfh + b1) = __halves2half2(h2, h3);
        *(__half2*)(g_AVfl + b0) =
            __halves2half2(__float2half_rn(v0 - __half2float(h0)),
                           __float2half_rn(v1 - __half2float(h1)));
        *(__half2*)(g_AVfl + b1) =
            __halves2half2(__float2half_rn(v2 - __half2float(h2)),
                           __float2half_rn(v3 - __half2float(h3)));
    }
}

// ---------------------------------------------------------------------------
// Residual + LayerNorm
// ---------------------------------------------------------------------------
__global__ __launch_bounds__(256) void ln_residual(
    const float* __restrict__ h, const float* __restrict__ gamma,
    const float* __restrict__ beta, float* __restrict__ out)
{
    const int row = blockIdx.x;
    const int tid = threadIdx.x;

    const float4 hv = *(const float4*)(h + row * Dn + tid * 4);
    const float4 av = *(const float4*)(g_AO + row * Dn + tid * 4);
    float4 x = make_float4(hv.x + av.x, hv.y + av.y, hv.z + av.z, hv.w + av.w);

    float s  = x.x + x.y + x.z + x.w;
    float ss = x.x * x.x + x.y * x.y + x.z * x.z + x.w * x.w;
#pragma unroll
    for (int off = 16; off > 0; off >>= 1) {
        s  += __shfl_xor_sync(0xffffffffu, s, off);
        ss += __shfl_xor_sync(0xffffffffu, ss, off);
    }
    __shared__ float rs[8], rss[8];
    if ((tid & 31) == 0) { rs[tid >> 5] = s; rss[tid >> 5] = ss; }
    __syncthreads();
    s = 0.f; ss = 0.f;
#pragma unroll
    for (int w = 0; w < 8; w++) { s += rs[w]; ss += rss[w]; }

    const float mu  = s * (1.0f / Dn);
    const float var = ss * (1.0f / Dn) - mu * mu;
    const float inv = rsqrtf(var + 1e-5f);

    const float4 g4 = *(const float4*)(gamma + tid * 4);
    const float4 b4 = *(const float4*)(beta + tid * 4);
    float4 r;
    r.x = g4.x * (x.x - mu) * inv + b4.x;
    r.y = g4.y * (x.y - mu) * inv + b4.y;
    r.z = g4.z * (x.z - mu) * inv + b4.z;
    r.w = g4.w * (x.w - mu) * inv + b4.w;
    *(float4*)(out + row * Dn + tid * 4) = r;
}

// ---------------------------------------------------------------------------
extern "C" void kernel_launch(void* const* d_in, const int* in_sizes, int n_in,
                              void* d_out, int out_size)
{
    (void)in_sizes; (void)n_in; (void)out_size;
    const float* h     = (const float*)d_in[0];
    const float* Wq    = (const float*)d_in[1];
    const float* Wk    = (const float*)d_in[2];
    const float* Wv    = (const float*)d_in[3];
    const float* Wo    = (const float*)d_in[4];
    const float* gamma = (const float*)d_in[5];
    const float* beta  = (const float*)d_in[6];
    float* out = (float*)d_out;

    float* AOp;
    __nv_bfloat16 *hAhi, *hAlo, *Whi, *Wlo, *Qh, *Ql, *Kh, *Kl;
    __half *hFhi, *hFlo, *Wf, *Vf, *AVfh, *AVfl;
    cudaGetSymbolAddress((void**)&AOp,  g_AO);
    cudaGetSymbolAddress((void**)&hAhi, g_hA_hi);
    cudaGetSymbolAddress((void**)&hAlo, g_hA_lo);
    cudaGetSymbolAddress((void**)&hFhi, g_hF_hi);
    cudaGetSymbolAddress((void**)&hFlo, g_hF_lo);
    cudaGetSymbolAddress((void**)&Whi,  g_W_hi);
    cudaGetSymbolAddress((void**)&Wlo,  g_W_lo);
    cudaGetSymbolAddress((void**)&Wf,   g_Wf);
    cudaGetSymbolAddress((void**)&Qh,   g_Qh);
    cudaGetSymbolAddress((void**)&Ql,   g_Ql);
    cudaGetSymbolAddress((void**)&Kh,   g_Kh);
    cudaGetSymbolAddress((void**)&Kl,   g_Kl);
    cudaGetSymbolAddress((void**)&Vf,   g_Vf);
    cudaGetSymbolAddress((void**)&AVfh, g_AVfh);
    cudaGetSymbolAddress((void**)&AVfl, g_AVfl);

    cudaFuncSetAttribute(gemm_qkv, cudaFuncAttributeMaxDynamicSharedMemorySize,
                         GEMM_SMEM);
    cudaFuncSetAttribute(gemm_o, cudaFuncAttributeMaxDynamicSharedMemorySize,
                         GEMM_SMEM);
    cudaFuncSetAttribute(flash_mma, cudaFuncAttributeMaxDynamicSharedMemorySize,
                         FLASH_SMEM);

    // Split h (bf16 + fp16 pairs) and weights
    split_h<<<Mn * Dn / 1024, 256>>>(h, hAhi, hAlo, hFhi, hFlo);
    split_T4<<<dim3(32, 32, 4), dim3(32, 8)>>>(Wq, Wk, Wv, Wo, Whi, Wlo, Wf);

    // Fused Q/K/V projections (Q pre-scaled by 1/8 * log2(e); V 2-term fp16)
    const float QSCALE = 0.125f * 1.4426950408889634f;
    gemm_qkv<<<dim3(24, Mn / 128), 256, GEMM_SMEM>>>(
        hAhi, hAlo, hFhi, hFlo, Whi, Wlo, Wf, Qh, Ql, Kh, Kl, Vf, QSCALE);

    // Attention (tensorized flash, 3-stage KV ring, fp16 PV)
    flash_mma<<<dim3(Sn / 128, Hn, Bn), 256, FLASH_SMEM>>>();

    // Output projection (2-term fp16, 3-stage ring)
    gemm_o<<<dim3(Dn / 128, Mn / 128), 256, GEMM_SMEM>>>(
        AVfh, AVfl, Wf + (size_t)Dn * Dn, AOp);

    ln_residual<<<Mn, 256>>>(h, gamma, beta, out);
}

// round 13
// speedup vs baseline: 1.4675x; 1.0415x over previous
#include <cuda_runtime.h>
#include <cuda_bf16.h>
#include <cuda_fp16.h>
#include <cstdint>
#include <math.h>

#define Bn 4
#define Sn 2048
#define Dn 1024
#define Hn 16
#define DHn 64
#define Mn (Bn * Sn)   // 8192

// ---------------------------------------------------------------------------
// Device scratch
// ---------------------------------------------------------------------------
__device__ float g_AO[Mn * Dn];

__device__ __nv_bfloat16 g_hA_hi[Mn * Dn];
__device__ __nv_bfloat16 g_hA_lo[Mn * Dn];
__device__ __half        g_hF_hi[Mn * Dn];   // fp16 split of h (for V gemm)
__device__ __half        g_hF_lo[Mn * Dn];
__device__ __nv_bfloat16 g_W_hi[2 * Dn * Dn];   // bf16 [N,K]: q, k
__device__ __nv_bfloat16 g_W_lo[2 * Dn * Dn];
__device__ __half        g_Wf[2 * Dn * Dn];     // fp16 [N,K]: v, o

__device__ __nv_bfloat16 g_Qh[Mn * Dn];  // pre-scaled by 0.125*log2(e)
__device__ __nv_bfloat16 g_Ql[Mn * Dn];
__device__ __nv_bfloat16 g_Kh[Mn * Dn];
__device__ __nv_bfloat16 g_Kl[Mn * Dn];
__device__ __half        g_Vf[Mn * Dn];  // V in single fp16
__device__ __half        g_AVfh[Mn * Dn];   // AV fp16 hi/lo split
__device__ __half        g_AVfl[Mn * Dn];

// ---------------------------------------------------------------------------
__device__ __forceinline__ uint32_t smem_u32(const void* p) {
    uint32_t a;
    asm("{ .reg .u64 t; cvta.to.shared.u64 t, %1; cvt.u32.u64 %0, t; }"
        : "=r"(a) : "l"(p));
    return a;
}

__device__ __forceinline__ float fast_ex2(float x) {
    float r;
    asm("ex2.approx.ftz.f32 %0, %1;" : "=f"(r) : "f"(x));
    return r;
}

__device__ __forceinline__ uint32_t pack_f16x2(float lo, float hi) {
    uint32_t d;
    asm("cvt.rn.f16x2.f32 %0, %1, %2;" : "=r"(d) : "f"(hi), "f"(lo));
    return d;
}

__device__ __forceinline__ void ldm_x4(uint32_t* r, uint32_t addr) {
    asm volatile("ldmatrix.sync.aligned.m8n8.x4.shared.b16 {%0,%1,%2,%3}, [%4];"
                 : "=r"(r[0]), "=r"(r[1]), "=r"(r[2]), "=r"(r[3]) : "r"(addr));
}
__device__ __forceinline__ void ldm_x4t(uint32_t* r, uint32_t addr) {
    asm volatile("ldmatrix.sync.aligned.m8n8.x4.trans.shared.b16 {%0,%1,%2,%3}, [%4];"
                 : "=r"(r[0]), "=r"(r[1]), "=r"(r[2]), "=r"(r[3]) : "r"(addr));
}

__device__ __forceinline__ void mma_bf16(float* c, const uint32_t* a,
                                         uint32_t b0, uint32_t b1) {
    asm volatile(
        "mma.sync.aligned.m16n8k16.row.col.f32.bf16.bf16.f32 "
        "{%0,%1,%2,%3}, {%4,%5,%6,%7}, {%8,%9}, {%0,%1,%2,%3};"
        : "+f"(c[0]), "+f"(c[1]), "+f"(c[2]), "+f"(c[3])
        : "r"(a[0]), "r"(a[1]), "r"(a[2]), "r"(a[3]), "r"(b0), "r"(b1));
}

__device__ __forceinline__ void mma_fp16(float* c, const uint32_t* a,
                                         uint32_t b0, uint32_t b1) {
    asm volatile(
        "mma.sync.aligned.m16n8k16.row.col.f32.f16.f16.f32 "
        "{%0,%1,%2,%3}, {%4,%5,%6,%7}, {%8,%9}, {%0,%1,%2,%3};"
        : "+f"(c[0]), "+f"(c[1]), "+f"(c[2]), "+f"(c[3])
        : "r"(a[0]), "r"(a[1]), "r"(a[2]), "r"(a[3]), "r"(b0), "r"(b1));
}

__device__ __forceinline__ void cp16(uint32_t s, const void* g) {
    asm volatile("cp.async.cg.shared.global [%0], [%1], 16;" :: "r"(s), "l"(g));
}
#define CP_COMMIT() asm volatile("cp.async.commit_group;" ::: "memory")
#define CP_WAIT0()  asm volatile("cp.async.wait_group 0;" ::: "memory")
#define CP_WAIT1()  asm volatile("cp.async.wait_group 1;" ::: "memory")

// ---------------------------------------------------------------------------
// Split fp32 h -> bf16 (hi,lo) AND fp16 (hi,lo)
// ---------------------------------------------------------------------------
__global__ __launch_bounds__(256) void split_h(
    const float* __restrict__ x,
    __nv_bfloat16* __restrict__ bhi, __nv_bfloat16* __restrict__ blo,
    __half* __restrict__ fhi, __half* __restrict__ flo)
{
    const int i = (blockIdx.x * 256 + threadIdx.x) * 4;
    float4 v = *(const float4*)(x + i);
    float vv[4] = {v.x, v.y, v.z, v.w};
    __nv_bfloat16 bh[4], bl[4];
    __half fh[4], fl[4];
#pragma unroll
    for (int k = 0; k < 4; k++) {
        bh[k] = __float2bfloat16(vv[k]);
        bl[k] = __float2bfloat16(vv[k] - __bfloat162float(bh[k]));
        fh[k] = __float2half_rn(vv[k]);
        fl[k] = __float2half_rn(vv[k] - __half2float(fh[k]));
    }
    __nv_bfloat162* bhp = (__nv_bfloat162*)(bhi + i);
    __nv_bfloat162* blp = (__nv_bfloat162*)(blo + i);
    bhp[0] = __nv_bfloat162(bh[0], bh[1]); bhp[1] = __nv_bfloat162(bh[2], bh[3]);
    blp[0] = __nv_bfloat162(bl[0], bl[1]); blp[1] = __nv_bfloat162(bl[2], bl[3]);
    __half2* fhp = (__half2*)(fhi + i);
    __half2* flp = (__half2*)(flo + i);
    fhp[0] = __halves2half2(fh[0], fh[1]); fhp[1] = __halves2half2(fh[2], fh[3]);
    flp[0] = __halves2half2(fl[0], fl[1]); flp[1] = __halves2half2(fl[2], fl[3]);
}

// ---------------------------------------------------------------------------
// Split + transpose weights: z=0,1 (Wq,Wk) -> bf16 hi/lo [N,K];
//                            z=2,3 (Wv,Wo) -> fp16 single [N,K].
// ---------------------------------------------------------------------------
__global__ __launch_bounds__(256) void split_T4(
    const float* __restrict__ W0, const float* __restrict__ W1,
    const float* __restrict__ W2, const float* __restrict__ W3,
    __nv_bfloat16* __restrict__ hiT, __nv_bfloat16* __restrict__ loT,
    __half* __restrict__ fT)
{
    const int z = blockIdx.z;
    const float* W = (z == 0) ? W0 : (z == 1) ? W1 : (z == 2) ? W2 : W3;

    __shared__ float t[32][33];
    const int tx = threadIdx.x, ty = threadIdx.y;
    const int bn = blockIdx.x * 32, bk = blockIdx.y * 32;
#pragma unroll
    for (int j = 0; j < 4; j++)
        t[ty + j * 8][tx] = W[(size_t)(bk + ty + j * 8) * Dn + bn + tx];
    __syncthreads();
#pragma unroll
    for (int j = 0; j < 4; j++) {
        float v = t[tx][ty + j * 8];
        size_t o = (size_t)(bn + ty + j * 8) * Dn + bk + tx;
        if (z < 2) {
            __nv_bfloat16 h = __float2bfloat16(v);
            __nv_bfloat16 l = __float2bfloat16(v - __bfloat162float(h));
            hiT[(size_t)z * Dn * Dn + o] = h;
            loT[(size_t)z * Dn * Dn + o] = l;
        } else {
            fT[(size_t)(z - 2) * Dn * Dn + o] = __float2half_rn(v);
        }
    }
}

// ---------------------------------------------------------------------------
// Shared GEMM constants.
// bf16 body: UNPADDED 64B rows with XOR chunk swizzle -> 32 KB/stage, 3-stage.
// fp16 body: 80B padded rows (as before), 3-stage.
// ---------------------------------------------------------------------------
#define BK        32
#define NSTAGE    (Dn / BK)          // 32

// bf16 body layout
#define B_ROW     64                 // bytes per row, no padding
#define B_ARR     (128 * B_ROW)      // 8192 per array
#define B_STAGE   (4 * B_ARR)        // 32768 (Ahi,Alo,Bhi,Blo)

// fp16 body layout
#define ROW_B     80
#define ARR_SZ    (128 * ROW_B)      // 10240
#define FBUF_SZ   (3 * ARR_SZ)       // 30720 (Ahi,Alo,Bf)

#define GEMM_SMEM (3 * B_STAGE)      // 98304 (covers fp16's 3*FBUF=92160)

// XOR swizzle: chunk' = chunk ^ ((row>>1)&3); offset = row*64 + chunk'*16
__device__ __forceinline__ uint32_t bswz(int row, int chunk) {
    return (uint32_t)(row * B_ROW) + (uint32_t)((chunk ^ ((row >> 1) & 3)) << 4);
}

// ---------------------------------------------------------------------------
// bf16 3-term GEMM body (Q/K projections), 3-stage cp.async ring.
// ---------------------------------------------------------------------------
__device__ __forceinline__ void gemm_bf16_body(
    const __nv_bfloat16* __restrict__ Ahi, const __nv_bfloat16* __restrict__ Alo,
    const __nv_bfloat16* __restrict__ Bhi, const __nv_bfloat16* __restrict__ Blo,
    __nv_bfloat16* __restrict__ Chi, __nv_bfloat16* __restrict__ Clo, float scale,
    int m0, int n0)
{
    extern __shared__ char smem[];
    const uint32_t sb = smem_u32(smem);
    const int tid  = threadIdx.x;
    const int wid  = tid >> 5;
    const int lane = tid & 31;
    const int m0w = (wid & 1) * 64;
    const int n0w = (wid >> 1) * 32;

    // Loader mapping: row r = tid>>2 (0..63) and r+64; chunk c = tid&3.
    const int lr = tid >> 2;
    const int lc = tid & 3;
    const uint32_t s0 = bswz(lr, lc);         // row+64 keeps same XOR
    const uint32_t s1 = s0 + 64 * B_ROW;
    const size_t gA0 = (size_t)(m0 + lr) * 2048 + lc * 16;
    const size_t gA1 = gA0 + (size_t)64 * 2048;
    const size_t gB0 = (size_t)(n0 + lr) * 2048 + lc * 16;
    const size_t gB1 = gB0 + (size_t)64 * 2048;
    const char* pAhi = (const char*)Ahi;
    const char* pAlo = (const char*)Alo;
    const char* pBhi = (const char*)Bhi;
    const char* pBlo = (const char*)Blo;

    float acc[4][4][4];
#pragma unroll
    for (int i = 0; i < 4; i++)
#pragma unroll
        for (int j = 0; j < 4; j++)
#pragma unroll
            for (int k = 0; k < 4; k++) acc[i][j][k] = 0.f;

    const int lrow = lane & 15;
    const int lch  = lane >> 4;
    // Per m-tile / n-tile row bases + XOR keys
    uint32_t a_rb[4], b_rb[2];
    int a_x[4], b_x[2];
#pragma unroll
    for (int mi = 0; mi < 4; mi++) {
        int r = m0w + mi * 16 + lrow;
        a_rb[mi] = (uint32_t)r * B_ROW;
        a_x[mi]  = (r >> 1) & 3;
    }
#pragma unroll
    for (int ni = 0; ni < 2; ni++) {
        int r = n0w + ni * 16 + lrow;
        b_rb[ni] = (uint32_t)r * B_ROW;
        b_x[ni]  = (r >> 1) & 3;
    }

#define B_LD_STAGE(st_, kc_) do {                                             \
    const size_t kb_ = (size_t)(kc_) * 64;                                    \
    const uint32_t db_ = sb + (uint32_t)(st_) * B_STAGE;                      \
    cp16(db_ + 0 * B_ARR + s0, pAhi + gA0 + kb_);                             \
    cp16(db_ + 0 * B_ARR + s1, pAhi + gA1 + kb_);                             \
    cp16(db_ + 1 * B_ARR + s0, pAlo + gA0 + kb_);                             \
    cp16(db_ + 1 * B_ARR + s1, pAlo + gA1 + kb_);                             \
    cp16(db_ + 2 * B_ARR + s0, pBhi + gB0 + kb_);                             \
    cp16(db_ + 2 * B_ARR + s1, pBhi + gB1 + kb_);                             \
    cp16(db_ + 3 * B_ARR + s0, pBlo + gB0 + kb_);                             \
    cp16(db_ + 3 * B_ARR + s1, pBlo + gB1 + kb_);                             \
    CP_COMMIT();                                                              \
} while (0)

    B_LD_STAGE(0, 0);
    B_LD_STAGE(1, 1);
    __syncthreads();

    for (int kc = 0; kc < NSTAGE; kc++) {
        if (kc + 1 < NSTAGE) { CP_WAIT1(); } else { CP_WAIT0(); }
        __syncthreads();

        if (kc + 2 < NSTAGE)
            B_LD_STAGE((kc + 2) % 3, kc + 2);

        const uint32_t bufb = sb + (uint32_t)(kc % 3) * B_STAGE;
#pragma unroll
        for (int ks = 0; ks < 2; ks++) {
            uint32_t ah[4][4], bh[2][4];
#pragma unroll
            for (int mi = 0; mi < 4; mi++)
                ldm_x4(ah[mi], bufb + 0 * B_ARR + a_rb[mi]
                                 + (uint32_t)(((ks * 2 + lch) ^ a_x[mi]) << 4));
#pragma unroll
            for (int ni = 0; ni < 2; ni++)
                ldm_x4(bh[ni], bufb + 2 * B_ARR + b_rb[ni]
                                 + (uint32_t)(((ks * 2 + lch) ^ b_x[ni]) << 4));
#pragma unroll
            for (int mi = 0; mi < 4; mi++)
#pragma unroll
                for (int ni = 0; ni < 2; ni++) {
                    mma_bf16(acc[mi][ni * 2 + 0], ah[mi], bh[ni][0], bh[ni][2]);
                    mma_bf16(acc[mi][ni * 2 + 1], ah[mi], bh[ni][1], bh[ni][3]);
                }
            {
                uint32_t bl[2][4];
#pragma unroll
                for (int ni = 0; ni < 2; ni++)
                    ldm_x4(bl[ni], bufb + 3 * B_ARR + b_rb[ni]
                                     + (uint32_t)(((ks * 2 + lch) ^ b_x[ni]) << 4));
#pragma unroll
                for (int mi = 0; mi < 4; mi++)
#pragma unroll
                    for (int ni = 0; ni < 2; ni++) {
                        mma_bf16(acc[mi][ni * 2 + 0], ah[mi], bl[ni][0], bl[ni][2]);
                        mma_bf16(acc[mi][ni * 2 + 1], ah[mi], bl[ni][1], bl[ni][3]);
                    }
            }
            {
                uint32_t al[4][4];
#pragma unroll
                for (int mi = 0; mi < 4; mi++)
                    ldm_x4(al[mi], bufb + 1 * B_ARR + a_rb[mi]
                                     + (uint32_t)(((ks * 2 + lch) ^ a_x[mi]) << 4));
#pragma unroll
                for (int mi = 0; mi < 4; mi++)
#pragma unroll
                    for (int ni = 0; ni < 2; ni++) {
                        mma_bf16(acc[mi][ni * 2 + 0], al[mi], bh[ni][0], bh[ni][2]);
                        mma_bf16(acc[mi][ni * 2 + 1], al[mi], bh[ni][1], bh[ni][3]);
                    }
            }
        }
        // ring: next iteration's top barrier protects reuse
    }
#undef B_LD_STAGE

    const int erow = lane >> 2;
    const int ecol = (lane & 3) * 2;
#pragma unroll
    for (int mi = 0; mi < 4; mi++) {
#pragma unroll
        for (int nj = 0; nj < 4; nj++) {
            size_t base0 = (size_t)(m0 + m0w + mi * 16 + erow) * Dn
                         + n0 + n0w + nj * 8 + ecol;
#pragma unroll
            for (int half = 0; half < 2; half++) {
                size_t b = base0 + half * 8 * Dn;
                float v0 = acc[mi][nj][half * 2 + 0] * scale;
                float v1 = acc[mi][nj][half * 2 + 1] * scale;
                __nv_bfloat16 h0 = __float2bfloat16(v0);
                __nv_bfloat16 h1 = __float2bfloat16(v1);
                __nv_bfloat16 l0 = __float2bfloat16(v0 - __bfloat162float(h0));
                __nv_bfloat16 l1 = __float2bfloat16(v1 - __bfloat162float(h1));
                *(__nv_bfloat162*)(Chi + b) = __nv_bfloat162(h0, h1);
                *(__nv_bfloat162*)(Clo + b) = __nv_bfloat162(l0, l1);
            }
        }
    }
}

// ---------------------------------------------------------------------------
// fp16 2-term GEMM body (V and O projections), 3-stage cp.async ring.
// EPI = 0: fp32 output C.  EPI = 2: fp16 single output Cf.
// ---------------------------------------------------------------------------
template <int EPI>
__device__ __forceinline__ void gemm_fp16_body(
    const __half* __restrict__ Ahi, const __half* __restrict__ Alo,
    const __half* __restrict__ Bf,
    float* __restrict__ C, __half* __restrict__ Cf,
    int m0, int n0)
{
    extern __shared__ char smem[];
    const uint32_t sb = smem_u32(smem);
    const int tid  = threadIdx.x;
    const int wid  = tid >> 5;
    const int lane = tid & 31;
    const int m0w = (wid & 1) * 64;
    const int n0w = (wid >> 1) * 32;

    const int lr = tid >> 2;
    const int lc = tid & 3;
    const uint32_t soff0 = lr * ROW_B + lc * 16;
    const uint32_t soff1 = (lr + 64) * ROW_B + lc * 16;
    const size_t gA0 = (size_t)(m0 + lr) * 2048 + lc * 16;
    const size_t gA1 = gA0 + (size_t)64 * 2048;
    const size_t gB0 = (size_t)(n0 + lr) * 2048 + lc * 16;
    const size_t gB1 = gB0 + (size_t)64 * 2048;
    const char* pAhi = (const char*)Ahi;
    const char* pAlo = (const char*)Alo;
    const char* pBf  = (const char*)Bf;

    float acc[4][4][4];
#pragma unroll
    for (int i = 0; i < 4; i++)
#pragma unroll
        for (int j = 0; j < 4; j++)
#pragma unroll
            for (int k = 0; k < 4; k++) acc[i][j][k] = 0.f;

    const int lrow = lane & 15;
    const int lch  = lane >> 4;
    const uint32_t a_lbase = (uint32_t)(m0w + lrow) * ROW_B + lch * 16;
    const uint32_t b_lbase = (uint32_t)(n0w + lrow) * ROW_B + lch * 16;

#define F_LD_STAGE(st_, kc_) do {                                             \
    const size_t kb_ = (size_t)(kc_) * 64;                                    \
    const uint32_t db_ = sb + (uint32_t)(st_) * FBUF_SZ;                      \
    cp16(db_ + 0 * ARR_SZ + soff0, pAhi + gA0 + kb_);                         \
    cp16(db_ + 0 * ARR_SZ + soff1, pAhi + gA1 + kb_);                         \
    cp16(db_ + 1 * ARR_SZ + soff0, pAlo + gA0 + kb_);                         \
    cp16(db_ + 1 * ARR_SZ + soff1, pAlo + gA1 + kb_);                         \
    cp16(db_ + 2 * ARR_SZ + soff0, pBf + gB0 + kb_);                          \
    cp16(db_ + 2 * ARR_SZ + soff1, pBf + gB1 + kb_);                          \
    CP_COMMIT();                                                              \
} while (0)

    F_LD_STAGE(0, 0);
    F_LD_STAGE(1, 1);
    __syncthreads();

    for (int kc = 0; kc < NSTAGE; kc++) {
        if (kc + 1 < NSTAGE) { CP_WAIT1(); } else { CP_WAIT0(); }
        __syncthreads();

        if (kc + 2 < NSTAGE)
            F_LD_STAGE((kc + 2) % 3, kc + 2);

        const uint32_t bufb = sb + (uint32_t)(kc % 3) * FBUF_SZ;
#pragma unroll
        for (int ks = 0; ks < 2; ks++) {
            uint32_t ah[4][4], bf_[2][4];
#pragma unroll
            for (int mi = 0; mi < 4; mi++)
                ldm_x4(ah[mi], bufb + 0 * ARR_SZ + a_lbase
                                 + mi * (16 * ROW_B) + ks * 32);
#pragma unroll
            for (int ni = 0; ni < 2; ni++)
                ldm_x4(bf_[ni], bufb + 2 * ARR_SZ + b_lbase
                                  + ni * (16 * ROW_B) + ks * 32);
#pragma unroll
            for (int mi = 0; mi < 4; mi++)
#pragma unroll
                for (int ni = 0; ni < 2; ni++) {
                    mma_fp16(acc[mi][ni * 2 + 0], ah[mi], bf_[ni][0], bf_[ni][2]);
                    mma_fp16(acc[mi][ni * 2 + 1], ah[mi], bf_[ni][1], bf_[ni][3]);
                }
            {
                uint32_t al[4][4];
#pragma unroll
                for (int mi = 0; mi < 4; mi++)
                    ldm_x4(al[mi], bufb + 1 * ARR_SZ + a_lbase
                                     + mi * (16 * ROW_B) + ks * 32);
#pragma unroll
                for (int mi = 0; mi < 4; mi++)
#pragma unroll
                    for (int ni = 0; ni < 2; ni++) {
                        mma_fp16(acc[mi][ni * 2 + 0], al[mi], bf_[ni][0], bf_[ni][2]);
                        mma_fp16(acc[mi][ni * 2 + 1], al[mi], bf_[ni][1], bf_[ni][3]);
                    }
            }
        }
    }
#undef F_LD_STAGE

    const int erow = lane >> 2;
    const int ecol = (lane & 3) * 2;
#pragma unroll
    for (int mi = 0; mi < 4; mi++) {
#pragma unroll
        for (int nj = 0; nj < 4; nj++) {
            size_t base0 = (size_t)(m0 + m0w + mi * 16 + erow) * Dn
                         + n0 + n0w + nj * 8 + ecol;
            if (EPI == 0) {
                *(float2*)(C + base0)          = make_float2(acc[mi][nj][0], acc[mi][nj][1]);
                *(float2*)(C + base0 + 8 * Dn) = make_float2(acc[mi][nj][2], acc[mi][nj][3]);
            } else {
#pragma unroll
                for (int half = 0; half < 2; half++) {
                    size_t b = base0 + half * 8 * Dn;
                    uint32_t p = pack_f16x2(acc[mi][nj][half * 2 + 0],
                                            acc[mi][nj][half * 2 + 1]);
                    *(uint32_t*)(Cf + b) = p;
                }
            }
        }
    }
}

// Fused Q/K/V projection: grid (24, 64); blockIdx.x selects weight + outputs.
__global__ __launch_bounds__(256, 2) void gemm_qkv(
    const __nv_bfloat16* __restrict__ Ahi, const __nv_bfloat16* __restrict__ Alo,
    const __half* __restrict__ Fhi, const __half* __restrict__ Flo,
    const __nv_bfloat16* __restrict__ Whi, const __nv_bfloat16* __restrict__ Wlo,
    const __half* __restrict__ Wf,
    __nv_bfloat16* __restrict__ Qh, __nv_bfloat16* __restrict__ Ql,
    __nv_bfloat16* __restrict__ Kh, __nv_bfloat16* __restrict__ Kl,
    __half* __restrict__ Vf, float qscale)
{
    const int ng   = blockIdx.x * 128;       // 0..3071
    const int wsel = ng >> 10;               // 0=Q, 1=K, 2=V
    const int n0   = ng & 1023;
    const int m0   = blockIdx.y * 128;
    if (wsel == 0)
        gemm_bf16_body(Ahi, Alo, Whi, Wlo, Qh, Ql, qscale, m0, n0);
    else if (wsel == 1)
        gemm_bf16_body(Ahi, Alo, Whi + (size_t)Dn * Dn, Wlo + (size_t)Dn * Dn,
                       Kh, Kl, 1.0f, m0, n0);
    else
        gemm_fp16_body<2>(Fhi, Flo, Wf, nullptr, Vf, m0, n0);
}

// O projection: fp16 2-term, fp32 output
__global__ __launch_bounds__(256, 2) void gemm_o(
    const __half* __restrict__ AVhi, const __half* __restrict__ AVlo,
    const __half* __restrict__ Wof, float* __restrict__ C)
{
    gemm_fp16_body<0>(AVhi, AVlo, Wof, C, nullptr,
                      blockIdx.y * 128, blockIdx.x * 128);
}

// ---------------------------------------------------------------------------
// Flash attention: QK^T = 3-term bf16 split; P*V = single fp16 MMA.
// (unchanged from R12)
// ---------------------------------------------------------------------------
#define FROW 144
#define FARR (64 * FROW)          // 9216
#define QARR (128 * FROW)         // 18432
#define KVBUF (3 * FARR)          // Kh, Kl, Vf = 27648
#define FLASH_SMEM (QARR + 3 * KVBUF)   // 101376 -> 2 CTAs/SM

#define KV_PREFETCH(kt_, buf_) do {                                           \
    const uint32_t base_ = sb + QARR + (uint32_t)(buf_) * KVBUF;              \
    const size_t g0_ = (size_t)(bb * Sn + (kt_) * 64 + kr0) * Dn              \
                     + headoff + kch * 8;                                     \
    const size_t g1_ = g0_ + (size_t)32 * Dn;                                 \
    cp16(base_ + 0 * FARR + kso0, g_Kh + g0_);                                \
    cp16(base_ + 0 * FARR + kso1, g_Kh + g1_);                                \
    cp16(base_ + 1 * FARR + kso0, g_Kl + g0_);                                \
    cp16(base_ + 1 * FARR + kso1, g_Kl + g1_);                                \
    cp16(base_ + 2 * FARR + kso0, g_Vf + g0_);                                \
    cp16(base_ + 2 * FARR + kso1, g_Vf + g1_);                                \
    CP_COMMIT();                                                              \
} while (0)

__global__ __launch_bounds__(256, 2) void flash_mma()
{
    extern __shared__ char sm[];
    const uint32_t sb = smem_u32(sm);
    const int tid = threadIdx.x;
    const int lane = tid & 31;
    const int w = tid >> 5;
    const int qt = blockIdx.x, hh = blockIdx.y, bb = blockIdx.z;

    const size_t headoff = (size_t)hh * 64;

    const int kr0 = tid >> 3;
    const int kch = tid & 7;
    const uint32_t kso0 = (uint32_t)kr0 * FROW + kch * 16;
    const uint32_t kso1 = (uint32_t)(kr0 + 32) * FROW + kch * 16;

    const uint32_t qlbase = QARR + 2 * KVBUF;
#pragma unroll
    for (int i = 0; i < 4; i++) {
        const int idx = tid + 256 * i;
        const int r = idx >> 3, ch = idx & 7;
        const size_t g = (size_t)(bb * Sn + qt * 128 + r) * Dn + headoff + ch * 8;
        const uint32_t so = r * FROW + ch * 16;
        *(uint4*)(sm + so)          = *(const uint4*)(g_Qh + g);
        *(uint4*)(sm + qlbase + so) = *(const uint4*)(g_Ql + g);
    }
    KV_PREFETCH(0, 0);
    KV_PREFETCH(1, 1);
    __syncthreads();

    const int lrow = lane & 15;
    const int lch  = lane >> 4;
    const uint32_t aoff = (uint32_t)(w * 16 + lrow) * FROW + lch * 16;
    uint32_t boff[4];
#pragma unroll
    for (int np = 0; np < 4; np++)
        boff[np] = (uint32_t)(np * 16 + lrow) * FROW + lch * 16;

    uint32_t qlf[4][4];
#pragma unroll
    for (int ks = 0; ks < 4; ks++)
        ldm_x4(qlf[ks], sb + qlbase + aoff + ks * 32);

    float o[8][4];
#pragma unroll
    for (int j = 0; j < 8; j++)
#pragma unroll
        for (int k = 0; k < 4; k++) o[j][k] = 0.f;
    float m0r = -1e30f, m1r = -1e30f, l0r = 0.f, l1r = 0.f;

    for (int kt = 0; kt < Sn / 64; kt++) {
        if (kt + 1 < Sn / 64) { CP_WAIT1(); } else { CP_WAIT0(); }
        __syncthreads();

        if (kt + 2 < Sn / 64)
            KV_PREFETCH(kt + 2, (kt + 2) % 3);

        const uint32_t kvb = sb + QARR + (uint32_t)(kt % 3) * KVBUF;

        float s[8][4];
#pragma unroll
        for (int j = 0; j < 8; j++)
#pragma unroll
            for (int k = 0; k < 4; k++) s[j][k] = 0.f;

#pragma unroll
        for (int ks = 0; ks < 4; ks++) {
            uint32_t qh[4];
            ldm_x4(qh, sb + aoff + ks * 32);
#pragma unroll
            for (int np = 0; np < 4; np++) {
                uint32_t kh[4], kl[4];
                ldm_x4(kh, kvb + 0 * FARR + boff[np] + ks * 32);
                ldm_x4(kl, kvb + 1 * FARR + boff[np] + ks * 32);
                mma_bf16(s[2 * np + 0], qh, kh[0], kh[2]);
                mma_bf16(s[2 * np + 1], qh, kh[1], kh[3]);
                mma_bf16(s[2 * np + 0], qh, kl[0], kl[2]);
                mma_bf16(s[2 * np + 1], qh, kl[1], kl[3]);
                mma_bf16(s[2 * np + 0], qlf[ks], kh[0], kh[2]);
                mma_bf16(s[2 * np + 1], qlf[ks], kh[1], kh[3]);
            }
        }

        float mx0 = -1e30f, mx1 = -1e30f;
#pragma unroll
        for (int j = 0; j < 8; j++) {
            mx0 = fmaxf(mx0, fmaxf(s[j][0], s[j][1]));
            mx1 = fmaxf(mx1, fmaxf(s[j][2], s[j][3]));
        }
        mx0 = fmaxf(mx0, __shfl_xor_sync(0xffffffffu, mx0, 1));
        mx0 = fmaxf(mx0, __shfl_xor_sync(0xffffffffu, mx0, 2));
        mx1 = fmaxf(mx1, __shfl_xor_sync(0xffffffffu, mx1, 1));
        mx1 = fmaxf(mx1, __shfl_xor_sync(0xffffffffu, mx1, 2));

        const float mn0 = fmaxf(m0r, mx0);
        const float mn1 = fmaxf(m1r, mx1);
        const float a0 = fast_ex2(m0r - mn0);
        const float a1 = fast_ex2(m1r - mn1);
        m0r = mn0; m1r = mn1;

        uint32_t pf[8][2];
        float sum0 = 0.f, sum1 = 0.f;
#pragma unroll
        for (int j = 0; j < 8; j++) {
            float p00 = fast_ex2(s[j][0] - mn0);
            float p01 = fast_ex2(s[j][1] - mn0);
            float p10 = fast_ex2(s[j][2] - mn1);
            float p11 = fast_ex2(s[j][3] - mn1);
            sum0 += p00 + p01;
            sum1 += p10 + p11;
            pf[j][0] = pack_f16x2(p00, p01);
            pf[j][1] = pack_f16x2(p10, p11);
        }
        sum0 += __shfl_xor_sync(0xffffffffu, sum0, 1);
        sum0 += __shfl_xor_sync(0xffffffffu, sum0, 2);
        sum1 += __shfl_xor_sync(0xffffffffu, sum1, 1);
        sum1 += __shfl_xor_sync(0xffffffffu, sum1, 2);
        l0r = l0r * a0 + sum0;
        l1r = l1r * a1 + sum1;

#pragma unroll
        for (int j = 0; j < 8; j++) {
            o[j][0] *= a0; o[j][1] *= a0;
            o[j][2] *= a1; o[j][3] *= a1;
        }

#pragma unroll
        for (int ks = 0; ks < 4; ks++) {
            uint32_t ap[4] = {pf[2 * ks][0], pf[2 * ks][1],
                              pf[2 * ks + 1][0], pf[2 * ks + 1][1]};
            const uint32_t vbase = (uint32_t)(ks * 16 + lrow) * FROW + lch * 16;
#pragma unroll
            for (int np = 0; np < 4; np++) {
                uint32_t vf[4];
                ldm_x4t(vf, kvb + 2 * FARR + vbase + np * 32);
                mma_fp16(o[2 * np + 0], ap, vf[0], vf[1]);
                mma_fp16(o[2 * np + 1], ap, vf[2], vf[3]);
            }
        }
    }

    const float inv0 = 1.0f / l0r;
    const float inv1 = 1.0f / l1r;
    const size_t row0 = (size_t)(bb * Sn + qt * 128 + w * 16 + (lane >> 2));
    const size_t row1 = row0 + 8;
    const size_t colb = headoff + (lane & 3) * 2;
#pragma unroll
    for (int j = 0; j < 8; j++) {
        float v0 = o[j][0] * inv0, v1 = o[j][1] * inv0;
        float v2 = o[j][2] * inv1, v3 = o[j][3] * inv1;
        __half h0 = __float2half_rn(v0);
        __half h1 = __float2half_rn(v1);
        __half h2 = __float2half_rn(v2);
        __half h3 = __float2half_rn(v3);
        size_t b0 = row0 * Dn + colb + j * 8;
        size_t b1 = row1 * Dn + colb + j * 8;
        *(__half2*)(g_AVfh + b0) = __halves2half2(h0, h1);
        *(__half2*)(g_AVfh + b1) = __halves2half2(h2, h3);
        *(__half2*)(g_AVfl + b0) =
            __halves2half2(__float2half_rn(v0 - __half2float(h0)),
                           __float2half_rn(v1 - __half2float(h1)));
        *(__half2*)(g_AVfl + b1) =
            __halves2half2(__float2half_rn(v2 - __half2float(h2)),
                           __float2half_rn(v3 - __half2float(h3)));
    }
}

// ---------------------------------------------------------------------------
// Residual + LayerNorm
// ---------------------------------------------------------------------------
__global__ __launch_bounds__(256) void ln_residual(
    const float* __restrict__ h, const float* __restrict__ gamma,
    const float* __restrict__ beta, float* __restrict__ out)
{
    const int row = blockIdx.x;
    const int tid = threadIdx.x;

    const float4 hv = *(const float4*)(h + row * Dn + tid * 4);
    const float4 av = *(const float4*)(g_AO + row * Dn + tid * 4);
    float4 x = make_float4(hv.x + av.x, hv.y + av.y, hv.z + av.z, hv.w + av.w);

    float s  = x.x + x.y + x.z + x.w;
    float ss = x.x * x.x + x.y * x.y + x.z * x.z + x.w * x.w;
#pragma unroll
    for (int off = 16; off > 0; off >>= 1) {
        s  += __shfl_xor_sync(0xffffffffu, s, off);
        ss += __shfl_xor_sync(0xffffffffu, ss, off);
    }
    __shared__ float rs[8], rss[8];
    if ((tid & 31) == 0) { rs[tid >> 5] = s; rss[tid >> 5] = ss; }
    __syncthreads();
    s = 0.f; ss = 0.f;
#pragma unroll
    for (int w = 0; w < 8; w++) { s += rs[w]; ss += rss[w]; }

    const float mu  = s * (1.0f / Dn);
    const float var = ss * (1.0f / Dn) - mu * mu;
    const float inv = rsqrtf(var + 1e-5f);

    const float4 g4 = *(const float4*)(gamma + tid * 4);
    const float4 b4 = *(const float4*)(beta + tid * 4);
    float4 r;
    r.x = g4.x * (x.x - mu) * inv + b4.x;
    r.y = g4.y * (x.y - mu) * inv + b4.y;
    r.z = g4.z * (x.z - mu) * inv + b4.z;
    r.w = g4.w * (x.w - mu) * inv + b4.w;
    *(float4*)(out + row * Dn + tid * 4) = r;
}

// ---------------------------------------------------------------------------
extern "C" void kernel_launch(void* const* d_in, const int* in_sizes, int n_in,
                              void* d_out, int out_size)
{
    (void)in_sizes; (void)n_in; (void)out_size;
    const float* h     = (const float*)d_in[0];
    const float* Wq    = (const float*)d_in[1];
    const float* Wk    = (const float*)d_in[2];
    const float* Wv    = (const float*)d_in[3];
    const float* Wo    = (const float*)d_in[4];
    const float* gamma = (const float*)d_in[5];
    const float* beta  = (const float*)d_in[6];
    float* out = (float*)d_out;

    float* AOp;
    __nv_bfloat16 *hAhi, *hAlo, *Whi, *Wlo, *Qh, *Ql, *Kh, *Kl;
    __half *hFhi, *hFlo, *Wf, *Vf, *AVfh, *AVfl;
    cudaGetSymbolAddress((void**)&AOp,  g_AO);
    cudaGetSymbolAddress((void**)&hAhi, g_hA_hi);
    cudaGetSymbolAddress((void**)&hAlo, g_hA_lo);
    cudaGetSymbolAddress((void**)&hFhi, g_hF_hi);
    cudaGetSymbolAddress((void**)&hFlo, g_hF_lo);
    cudaGetSymbolAddress((void**)&Whi,  g_W_hi);
    cudaGetSymbolAddress((void**)&Wlo,  g_W_lo);
    cudaGetSymbolAddress((void**)&Wf,   g_Wf);
    cudaGetSymbolAddress((void**)&Qh,   g_Qh);
    cudaGetSymbolAddress((void**)&Ql,   g_Ql);
    cudaGetSymbolAddress((void**)&Kh,   g_Kh);
    cudaGetSymbolAddress((void**)&Kl,   g_Kl);
    cudaGetSymbolAddress((void**)&Vf,   g_Vf);
    cudaGetSymbolAddress((void**)&AVfh, g_AVfh);
    cudaGetSymbolAddress((void**)&AVfl, g_AVfl);

    cudaFuncSetAttribute(gemm_qkv, cudaFuncAttributeMaxDynamicSharedMemorySize,
                         GEMM_SMEM);
    cudaFuncSetAttribute(gemm_o, cudaFuncAttributeMaxDynamicSharedMemorySize,
                         GEMM_SMEM);
    cudaFuncSetAttribute(flash_mma, cudaFuncAttributeMaxDynamicSharedMemorySize,
                         FLASH_SMEM);

    // Split h (bf16 + fp16 pairs) and weights
    split_h<<<Mn * Dn / 1024, 256>>>(h, hAhi, hAlo, hFhi, hFlo);
    split_T4<<<dim3(32, 32, 4), dim3(32, 8)>>>(Wq, Wk, Wv, Wo, Whi, Wlo, Wf);

    // Fused Q/K/V projections (Q pre-scaled by 1/8 * log2(e); V 2-term fp16)
    const float QSCALE = 0.125f * 1.4426950408889634f;
    gemm_qkv<<<dim3(24, Mn / 128), 256, GEMM_SMEM>>>(
        hAhi, hAlo, hFhi, hFlo, Whi, Wlo, Wf, Qh, Ql, Kh, Kl, Vf, QSCALE);

    // Attention (tensorized flash, 3-stage KV ring, fp16 PV)
    flash_mma<<<dim3(Sn / 128, Hn, Bn), 256, FLASH_SMEM>>>();

    // Output projection (2-term fp16, 3-stage ring)
    gemm_o<<<dim3(Dn / 128, Mn / 128), 256, GEMM_SMEM>>>(
        AVfh, AVfl, Wf + (size_t)Dn * Dn, AOp);

    ln_residual<<<Mn, 256>>>(h, gamma, beta, out);
}

// round 14
// speedup vs baseline: 1.4755x; 1.0054x over previous
#include <cuda_runtime.h>
#include <cuda_bf16.h>
#include <cuda_fp16.h>
#include <cstdint>
#include <math.h>

#define Bn 4
#define Sn 2048
#define Dn 1024
#define Hn 16
#define DHn 64
#define Mn (Bn * Sn)   // 8192

// ---------------------------------------------------------------------------
// Device scratch
// ---------------------------------------------------------------------------
__device__ float g_AO[Mn * Dn];

__device__ __nv_bfloat16 g_hA_hi[Mn * Dn];
__device__ __nv_bfloat16 g_hA_lo[Mn * Dn];
__device__ __half        g_hF_hi[Mn * Dn];   // fp16 split of h (for V gemm)
__device__ __half        g_hF_lo[Mn * Dn];
__device__ __nv_bfloat16 g_W_hi[2 * Dn * Dn];   // bf16 [N,K]: q, k
__device__ __nv_bfloat16 g_W_lo[2 * Dn * Dn];
__device__ __half        g_Wf[2 * Dn * Dn];     // fp16 [N,K]: v, o

__device__ __nv_bfloat16 g_Qh[Mn * Dn];  // pre-scaled by 0.125*log2(e)
__device__ __nv_bfloat16 g_Ql[Mn * Dn];
__device__ __nv_bfloat16 g_Kh[Mn * Dn];
__device__ __nv_bfloat16 g_Kl[Mn * Dn];
__device__ __half        g_Vf[Mn * Dn];  // V in single fp16
__device__ __half        g_AVfh[Mn * Dn];   // AV fp16 hi/lo split
__device__ __half        g_AVfl[Mn * Dn];

// ---------------------------------------------------------------------------
__device__ __forceinline__ uint32_t smem_u32(const void* p) {
    uint32_t a;
    asm("{ .reg .u64 t; cvta.to.shared.u64 t, %1; cvt.u32.u64 %0, t; }"
        : "=r"(a) : "l"(p));
    return a;
}

__device__ __forceinline__ float fast_ex2(float x) {
    float r;
    asm("ex2.approx.ftz.f32 %0, %1;" : "=f"(r) : "f"(x));
    return r;
}

__device__ __forceinline__ uint32_t pack_f16x2(float lo, float hi) {
    uint32_t d;
    asm("cvt.rn.f16x2.f32 %0, %1, %2;" : "=r"(d) : "f"(hi), "f"(lo));
    return d;
}

__device__ __forceinline__ void ldm_x4(uint32_t* r, uint32_t addr) {
    asm volatile("ldmatrix.sync.aligned.m8n8.x4.shared.b16 {%0,%1,%2,%3}, [%4];"
                 : "=r"(r[0]), "=r"(r[1]), "=r"(r[2]), "=r"(r[3]) : "r"(addr));
}
__device__ __forceinline__ void ldm_x4t(uint32_t* r, uint32_t addr) {
    asm volatile("ldmatrix.sync.aligned.m8n8.x4.trans.shared.b16 {%0,%1,%2,%3}, [%4];"
                 : "=r"(r[0]), "=r"(r[1]), "=r"(r[2]), "=r"(r[3]) : "r"(addr));
}

__device__ __forceinline__ void mma_bf16(float* c, const uint32_t* a,
                                         uint32_t b0, uint32_t b1) {
    asm volatile(
        "mma.sync.aligned.m16n8k16.row.col.f32.bf16.bf16.f32 "
        "{%0,%1,%2,%3}, {%4,%5,%6,%7}, {%8,%9}, {%0,%1,%2,%3};"
        : "+f"(c[0]), "+f"(c[1]), "+f"(c[2]), "+f"(c[3])
        : "r"(a[0]), "r"(a[1]), "r"(a[2]), "r"(a[3]), "r"(b0), "r"(b1));
}

__device__ __forceinline__ void mma_fp16(float* c, const uint32_t* a,
                                         uint32_t b0, uint32_t b1) {
    asm volatile(
        "mma.sync.aligned.m16n8k16.row.col.f32.f16.f16.f32 "
        "{%0,%1,%2,%3}, {%4,%5,%6,%7}, {%8,%9}, {%0,%1,%2,%3};"
        : "+f"(c[0]), "+f"(c[1]), "+f"(c[2]), "+f"(c[3])
        : "r"(a[0]), "r"(a[1]), "r"(a[2]), "r"(a[3]), "r"(b0), "r"(b1));
}

__device__ __forceinline__ void cp16(uint32_t s, const void* g) {
    asm volatile("cp.async.cg.shared.global [%0], [%1], 16;" :: "r"(s), "l"(g));
}
#define CP_COMMIT() asm volatile("cp.async.commit_group;" ::: "memory")
#define CP_WAIT0()  asm volatile("cp.async.wait_group 0;" ::: "memory")
#define CP_WAIT1()  asm volatile("cp.async.wait_group 1;" ::: "memory")

// ---------------------------------------------------------------------------
// Split fp32 h -> bf16 (hi,lo) AND fp16 (hi,lo)
// ---------------------------------------------------------------------------
__global__ __launch_bounds__(256) void split_h(
    const float* __restrict__ x,
    __nv_bfloat16* __restrict__ bhi, __nv_bfloat16* __restrict__ blo,
    __half* __restrict__ fhi, __half* __restrict__ flo)
{
    const int i = (blockIdx.x * 256 + threadIdx.x) * 4;
    float4 v = *(const float4*)(x + i);
    float vv[4] = {v.x, v.y, v.z, v.w};
    __nv_bfloat16 bh[4], bl[4];
    __half fh[4], fl[4];
#pragma unroll
    for (int k = 0; k < 4; k++) {
        bh[k] = __float2bfloat16(vv[k]);
        bl[k] = __float2bfloat16(vv[k] - __bfloat162float(bh[k]));
        fh[k] = __float2half_rn(vv[k]);
        fl[k] = __float2half_rn(vv[k] - __half2float(fh[k]));
    }
    __nv_bfloat162* bhp = (__nv_bfloat162*)(bhi + i);
    __nv_bfloat162* blp = (__nv_bfloat162*)(blo + i);
    bhp[0] = __nv_bfloat162(bh[0], bh[1]); bhp[1] = __nv_bfloat162(bh[2], bh[3]);
    blp[0] = __nv_bfloat162(bl[0], bl[1]); blp[1] = __nv_bfloat162(bl[2], bl[3]);
    __half2* fhp = (__half2*)(fhi + i);
    __half2* flp = (__half2*)(flo + i);
    fhp[0] = __halves2half2(fh[0], fh[1]); fhp[1] = __halves2half2(fh[2], fh[3]);
    flp[0] = __halves2half2(fl[0], fl[1]); flp[1] = __halves2half2(fl[2], fl[3]);
}

// ---------------------------------------------------------------------------
// Split + transpose weights: z=0,1 (Wq,Wk) -> bf16 hi/lo [N,K];
//                            z=2,3 (Wv,Wo) -> fp16 single [N,K].
// ---------------------------------------------------------------------------
__global__ __launch_bounds__(256) void split_T4(
    const float* __restrict__ W0, const float* __restrict__ W1,
    const float* __restrict__ W2, const float* __restrict__ W3,
    __nv_bfloat16* __restrict__ hiT, __nv_bfloat16* __restrict__ loT,
    __half* __restrict__ fT)
{
    const int z = blockIdx.z;
    const float* W = (z == 0) ? W0 : (z == 1) ? W1 : (z == 2) ? W2 : W3;

    __shared__ float t[32][33];
    const int tx = threadIdx.x, ty = threadIdx.y;
    const int bn = blockIdx.x * 32, bk = blockIdx.y * 32;
#pragma unroll
    for (int j = 0; j < 4; j++)
        t[ty + j * 8][tx] = W[(size_t)(bk + ty + j * 8) * Dn + bn + tx];
    __syncthreads();
#pragma unroll
    for (int j = 0; j < 4; j++) {
        float v = t[tx][ty + j * 8];
        size_t o = (size_t)(bn + ty + j * 8) * Dn + bk + tx;
        if (z < 2) {
            __nv_bfloat16 h = __float2bfloat16(v);
            __nv_bfloat16 l = __float2bfloat16(v - __bfloat162float(h));
            hiT[(size_t)z * Dn * Dn + o] = h;
            loT[(size_t)z * Dn * Dn + o] = l;
        } else {
            fT[(size_t)(z - 2) * Dn * Dn + o] = __float2half_rn(v);
        }
    }
}

// ---------------------------------------------------------------------------
// Shared GEMM constants.
// ---------------------------------------------------------------------------
#define BK        32
#define NSTAGE    (Dn / BK)          // 32

#define B_ROW     64
#define B_ARR     (128 * B_ROW)      // 8192
#define B_STAGE   (4 * B_ARR)        // 32768

#define ROW_B     80
#define ARR_SZ    (128 * ROW_B)      // 10240
#define FBUF_SZ   (3 * ARR_SZ)       // 30720

#define GEMM_SMEM (3 * B_STAGE)      // 98304

__device__ __forceinline__ uint32_t bswz(int row, int chunk) {
    return (uint32_t)(row * B_ROW) + (uint32_t)((chunk ^ ((row >> 1) & 3)) << 4);
}

// ---------------------------------------------------------------------------
// bf16 3-term GEMM body (Q/K projections), 3-stage cp.async ring.
// ---------------------------------------------------------------------------
__device__ __forceinline__ void gemm_bf16_body(
    const __nv_bfloat16* __restrict__ Ahi, const __nv_bfloat16* __restrict__ Alo,
    const __nv_bfloat16* __restrict__ Bhi, const __nv_bfloat16* __restrict__ Blo,
    __nv_bfloat16* __restrict__ Chi, __nv_bfloat16* __restrict__ Clo, float scale,
    int m0, int n0)
{
    extern __shared__ char smem[];
    const uint32_t sb = smem_u32(smem);
    const int tid  = threadIdx.x;
    const int wid  = tid >> 5;
    const int lane = tid & 31;
    const int m0w = (wid & 1) * 64;
    const int n0w = (wid >> 1) * 32;

    const int lr = tid >> 2;
    const int lc = tid & 3;
    const uint32_t s0 = bswz(lr, lc);
    const uint32_t s1 = s0 + 64 * B_ROW;
    const size_t gA0 = (size_t)(m0 + lr) * 2048 + lc * 16;
    const size_t gA1 = gA0 + (size_t)64 * 2048;
    const size_t gB0 = (size_t)(n0 + lr) * 2048 + lc * 16;
    const size_t gB1 = gB0 + (size_t)64 * 2048;
    const char* pAhi = (const char*)Ahi;
    const char* pAlo = (const char*)Alo;
    const char* pBhi = (const char*)Bhi;
    const char* pBlo = (const char*)Blo;

    float acc[4][4][4];
#pragma unroll
    for (int i = 0; i < 4; i++)
#pragma unroll
        for (int j = 0; j < 4; j++)
#pragma unroll
            for (int k = 0; k < 4; k++) acc[i][j][k] = 0.f;

    const int lrow = lane & 15;
    const int lch  = lane >> 4;
    uint32_t a_rb[4], b_rb[2];
    int a_x[4], b_x[2];
#pragma unroll
    for (int mi = 0; mi < 4; mi++) {
        int r = m0w + mi * 16 + lrow;
        a_rb[mi] = (uint32_t)r * B_ROW;
        a_x[mi]  = (r >> 1) & 3;
    }
#pragma unroll
    for (int ni = 0; ni < 2; ni++) {
        int r = n0w + ni * 16 + lrow;
        b_rb[ni] = (uint32_t)r * B_ROW;
        b_x[ni]  = (r >> 1) & 3;
    }

#define B_LD_STAGE(st_, kc_) do {                                             \
    const size_t kb_ = (size_t)(kc_) * 64;                                    \
    const uint32_t db_ = sb + (uint32_t)(st_) * B_STAGE;                      \
    cp16(db_ + 0 * B_ARR + s0, pAhi + gA0 + kb_);                             \
    cp16(db_ + 0 * B_ARR + s1, pAhi + gA1 + kb_);                             \
    cp16(db_ + 1 * B_ARR + s0, pAlo + gA0 + kb_);                             \
    cp16(db_ + 1 * B_ARR + s1, pAlo + gA1 + kb_);                             \
    cp16(db_ + 2 * B_ARR + s0, pBhi + gB0 + kb_);                             \
    cp16(db_ + 2 * B_ARR + s1, pBhi + gB1 + kb_);                             \
    cp16(db_ + 3 * B_ARR + s0, pBlo + gB0 + kb_);                             \
    cp16(db_ + 3 * B_ARR + s1, pBlo + gB1 + kb_);                             \
    CP_COMMIT();                                                              \
} while (0)

    B_LD_STAGE(0, 0);
    B_LD_STAGE(1, 1);
    __syncthreads();

    for (int kc = 0; kc < NSTAGE; kc++) {
        if (kc + 1 < NSTAGE) { CP_WAIT1(); } else { CP_WAIT0(); }
        __syncthreads();

        if (kc + 2 < NSTAGE)
            B_LD_STAGE((kc + 2) % 3, kc + 2);

        const uint32_t bufb = sb + (uint32_t)(kc % 3) * B_STAGE;
#pragma unroll
        for (int ks = 0; ks < 2; ks++) {
            uint32_t ah[4][4], bh[2][4];
#pragma unroll
            for (int mi = 0; mi < 4; mi++)
                ldm_x4(ah[mi], bufb + 0 * B_ARR + a_rb[mi]
                                 + (uint32_t)(((ks * 2 + lch) ^ a_x[mi]) << 4));
#pragma unroll
            for (int ni = 0; ni < 2; ni++)
                ldm_x4(bh[ni], bufb + 2 * B_ARR + b_rb[ni]
                                 + (uint32_t)(((ks * 2 + lch) ^ b_x[ni]) << 4));
#pragma unroll
            for (int mi = 0; mi < 4; mi++)
#pragma unroll
                for (int ni = 0; ni < 2; ni++) {
                    mma_bf16(acc[mi][ni * 2 + 0], ah[mi], bh[ni][0], bh[ni][2]);
                    mma_bf16(acc[mi][ni * 2 + 1], ah[mi], bh[ni][1], bh[ni][3]);
                }
            {
                uint32_t bl[2][4];
#pragma unroll
                for (int ni = 0; ni < 2; ni++)
                    ldm_x4(bl[ni], bufb + 3 * B_ARR + b_rb[ni]
                                     + (uint32_t)(((ks * 2 + lch) ^ b_x[ni]) << 4));
#pragma unroll
                for (int mi = 0; mi < 4; mi++)
#pragma unroll
                    for (int ni = 0; ni < 2; ni++) {
                        mma_bf16(acc[mi][ni * 2 + 0], ah[mi], bl[ni][0], bl[ni][2]);
                        mma_bf16(acc[mi][ni * 2 + 1], ah[mi], bl[ni][1], bl[ni][3]);
                    }
            }
            {
                uint32_t al[4][4];
#pragma unroll
                for (int mi = 0; mi < 4; mi++)
                    ldm_x4(al[mi], bufb + 1 * B_ARR + a_rb[mi]
                                     + (uint32_t)(((ks * 2 + lch) ^ a_x[mi]) << 4));
#pragma unroll
                for (int mi = 0; mi < 4; mi++)
#pragma unroll
                    for (int ni = 0; ni < 2; ni++) {
                        mma_bf16(acc[mi][ni * 2 + 0], al[mi], bh[ni][0], bh[ni][2]);
                        mma_bf16(acc[mi][ni * 2 + 1], al[mi], bh[ni][1], bh[ni][3]);
                    }
            }
        }
    }
#undef B_LD_STAGE

    const int erow = lane >> 2;
    const int ecol = (lane & 3) * 2;
#pragma unroll
    for (int mi = 0; mi < 4; mi++) {
#pragma unroll
        for (int nj = 0; nj < 4; nj++) {
            size_t base0 = (size_t)(m0 + m0w + mi * 16 + erow) * Dn
                         + n0 + n0w + nj * 8 + ecol;
#pragma unroll
            for (int half = 0; half < 2; half++) {
                size_t b = base0 + half * 8 * Dn;
                float v0 = acc[mi][nj][half * 2 + 0] * scale;
                float v1 = acc[mi][nj][half * 2 + 1] * scale;
                __nv_bfloat16 h0 = __float2bfloat16(v0);
                __nv_bfloat16 h1 = __float2bfloat16(v1);
                __nv_bfloat16 l0 = __float2bfloat16(v0 - __bfloat162float(h0));
                __nv_bfloat16 l1 = __float2bfloat16(v1 - __bfloat162float(h1));
                *(__nv_bfloat162*)(Chi + b) = __nv_bfloat162(h0, h1);
                *(__nv_bfloat162*)(Clo + b) = __nv_bfloat162(l0, l1);
            }
        }
    }
}

// ---------------------------------------------------------------------------
// fp16 2-term GEMM body (V and O projections), 3-stage cp.async ring.
// ---------------------------------------------------------------------------
template <int EPI>
__device__ __forceinline__ void gemm_fp16_body(
    const __half* __restrict__ Ahi, const __half* __restrict__ Alo,
    const __half* __restrict__ Bf,
    float* __restrict__ C, __half* __restrict__ Cf,
    int m0, int n0)
{
    extern __shared__ char smem[];
    const uint32_t sb = smem_u32(smem);
    const int tid  = threadIdx.x;
    const int wid  = tid >> 5;
    const int lane = tid & 31;
    const int m0w = (wid & 1) * 64;
    const int n0w = (wid >> 1) * 32;

    const int lr = tid >> 2;
    const int lc = tid & 3;
    const uint32_t soff0 = lr * ROW_B + lc * 16;
    const uint32_t soff1 = (lr + 64) * ROW_B + lc * 16;
    const size_t gA0 = (size_t)(m0 + lr) * 2048 + lc * 16;
    const size_t gA1 = gA0 + (size_t)64 * 2048;
    const size_t gB0 = (size_t)(n0 + lr) * 2048 + lc * 16;
    const size_t gB1 = gB0 + (size_t)64 * 2048;
    const char* pAhi = (const char*)Ahi;
    const char* pAlo = (const char*)Alo;
    const char* pBf  = (const char*)Bf;

    float acc[4][4][4];
#pragma unroll
    for (int i = 0; i < 4; i++)
#pragma unroll
        for (int j = 0; j < 4; j++)
#pragma unroll
            for (int k = 0; k < 4; k++) acc[i][j][k] = 0.f;

    const int lrow = lane & 15;
    const int lch  = lane >> 4;
    const uint32_t a_lbase = (uint32_t)(m0w + lrow) * ROW_B + lch * 16;
    const uint32_t b_lbase = (uint32_t)(n0w + lrow) * ROW_B + lch * 16;

#define F_LD_STAGE(st_, kc_) do {                                             \
    const size_t kb_ = (size_t)(kc_) * 64;                                    \
    const uint32_t db_ = sb + (uint32_t)(st_) * FBUF_SZ;                      \
    cp16(db_ + 0 * ARR_SZ + soff0, pAhi + gA0 + kb_);                         \
    cp16(db_ + 0 * ARR_SZ + soff1, pAhi + gA1 + kb_);                         \
    cp16(db_ + 1 * ARR_SZ + soff0, pAlo + gA0 + kb_);                         \
    cp16(db_ + 1 * ARR_SZ + soff1, pAlo + gA1 + kb_);                         \
    cp16(db_ + 2 * ARR_SZ + soff0, pBf + gB0 + kb_);                          \
    cp16(db_ + 2 * ARR_SZ + soff1, pBf + gB1 + kb_);                          \
    CP_COMMIT();                                                              \
} while (0)

    F_LD_STAGE(0, 0);
    F_LD_STAGE(1, 1);
    __syncthreads();

    for (int kc = 0; kc < NSTAGE; kc++) {
        if (kc + 1 < NSTAGE) { CP_WAIT1(); } else { CP_WAIT0(); }
        __syncthreads();

        if (kc + 2 < NSTAGE)
            F_LD_STAGE((kc + 2) % 3, kc + 2);

        const uint32_t bufb = sb + (uint32_t)(kc % 3) * FBUF_SZ;
#pragma unroll
        for (int ks = 0; ks < 2; ks++) {
            uint32_t ah[4][4], bf_[2][4];
#pragma unroll
            for (int mi = 0; mi < 4; mi++)
                ldm_x4(ah[mi], bufb + 0 * ARR_SZ + a_lbase
                                 + mi * (16 * ROW_B) + ks * 32);
#pragma unroll
            for (int ni = 0; ni < 2; ni++)
                ldm_x4(bf_[ni], bufb + 2 * ARR_SZ + b_lbase
                                  + ni * (16 * ROW_B) + ks * 32);
#pragma unroll
            for (int mi = 0; mi < 4; mi++)
#pragma unroll
                for (int ni = 0; ni < 2; ni++) {
                    mma_fp16(acc[mi][ni * 2 + 0], ah[mi], bf_[ni][0], bf_[ni][2]);
                    mma_fp16(acc[mi][ni * 2 + 1], ah[mi], bf_[ni][1], bf_[ni][3]);
                }
            {
                uint32_t al[4][4];
#pragma unroll
                for (int mi = 0; mi < 4; mi++)
                    ldm_x4(al[mi], bufb + 1 * ARR_SZ + a_lbase
                                     + mi * (16 * ROW_B) + ks * 32);
#pragma unroll
                for (int mi = 0; mi < 4; mi++)
#pragma unroll
                    for (int ni = 0; ni < 2; ni++) {
                        mma_fp16(acc[mi][ni * 2 + 0], al[mi], bf_[ni][0], bf_[ni][2]);
                        mma_fp16(acc[mi][ni * 2 + 1], al[mi], bf_[ni][1], bf_[ni][3]);
                    }
            }
        }
    }
#undef F_LD_STAGE

    const int erow = lane >> 2;
    const int ecol = (lane & 3) * 2;
#pragma unroll
    for (int mi = 0; mi < 4; mi++) {
#pragma unroll
        for (int nj = 0; nj < 4; nj++) {
            size_t base0 = (size_t)(m0 + m0w + mi * 16 + erow) * Dn
                         + n0 + n0w + nj * 8 + ecol;
            if (EPI == 0) {
                *(float2*)(C + base0)          = make_float2(acc[mi][nj][0], acc[mi][nj][1]);
                *(float2*)(C + base0 + 8 * Dn) = make_float2(acc[mi][nj][2], acc[mi][nj][3]);
            } else {
#pragma unroll
                for (int half = 0; half < 2; half++) {
                    size_t b = base0 + half * 8 * Dn;
                    uint32_t p = pack_f16x2(acc[mi][nj][half * 2 + 0],
                                            acc[mi][nj][half * 2 + 1]);
                    *(uint32_t*)(Cf + b) = p;
                }
            }
        }
    }
}

// Fused Q/K/V projection
__global__ __launch_bounds__(256, 2) void gemm_qkv(
    const __nv_bfloat16* __restrict__ Ahi, const __nv_bfloat16* __restrict__ Alo,
    const __half* __restrict__ Fhi, const __half* __restrict__ Flo,
    const __nv_bfloat16* __restrict__ Whi, const __nv_bfloat16* __restrict__ Wlo,
    const __half* __restrict__ Wf,
    __nv_bfloat16* __restrict__ Qh, __nv_bfloat16* __restrict__ Ql,
    __nv_bfloat16* __restrict__ Kh, __nv_bfloat16* __restrict__ Kl,
    __half* __restrict__ Vf, float qscale)
{
    const int ng   = blockIdx.x * 128;
    const int wsel = ng >> 10;
    const int n0   = ng & 1023;
    const int m0   = blockIdx.y * 128;
    if (wsel == 0)
        gemm_bf16_body(Ahi, Alo, Whi, Wlo, Qh, Ql, qscale, m0, n0);
    else if (wsel == 1)
        gemm_bf16_body(Ahi, Alo, Whi + (size_t)Dn * Dn, Wlo + (size_t)Dn * Dn,
                       Kh, Kl, 1.0f, m0, n0);
    else
        gemm_fp16_body<2>(Fhi, Flo, Wf, nullptr, Vf, m0, n0);
}

// O projection: fp16 2-term, fp32 output
__global__ __launch_bounds__(256, 2) void gemm_o(
    const __half* __restrict__ AVhi, const __half* __restrict__ AVlo,
    const __half* __restrict__ Wof, float* __restrict__ C)
{
    gemm_fp16_body<0>(AVhi, AVlo, Wof, C, nullptr,
                      blockIdx.y * 128, blockIdx.x * 128);
}

// ---------------------------------------------------------------------------
// Flash attention: QK^T = 3-term bf16 split; P*V = single fp16 MMA.
// Qh AND Ql fragments hoisted to registers. JIT exp+pack inside PV loop.
// Warp-uniform rescale skip when no row in the warp saw a new max.
// ---------------------------------------------------------------------------
#define FROW 144
#define FARR (64 * FROW)          // 9216
#define QARR (128 * FROW)         // 18432
#define KVBUF (3 * FARR)          // Kh, Kl, Vf = 27648
#define FLASH_SMEM (QARR + 3 * KVBUF)   // 101376 -> 2 CTAs/SM

#define KV_PREFETCH(kt_, buf_) do {                                           \
    const uint32_t base_ = sb + QARR + (uint32_t)(buf_) * KVBUF;              \
    const size_t g0_ = (size_t)(bb * Sn + (kt_) * 64 + kr0) * Dn              \
                     + headoff + kch * 8;                                     \
    const size_t g1_ = g0_ + (size_t)32 * Dn;                                 \
    cp16(base_ + 0 * FARR + kso0, g_Kh + g0_);                                \
    cp16(base_ + 0 * FARR + kso1, g_Kh + g1_);                                \
    cp16(base_ + 1 * FARR + kso0, g_Kl + g0_);                                \
    cp16(base_ + 1 * FARR + kso1, g_Kl + g1_);                                \
    cp16(base_ + 2 * FARR + kso0, g_Vf + g0_);                                \
    cp16(base_ + 2 * FARR + kso1, g_Vf + g1_);                                \
    CP_COMMIT();                                                              \
} while (0)

__global__ __launch_bounds__(256, 2) void flash_mma()
{
    extern __shared__ char sm[];
    const uint32_t sb = smem_u32(sm);
    const int tid = threadIdx.x;
    const int lane = tid & 31;
    const int w = tid >> 5;
    const int qt = blockIdx.x, hh = blockIdx.y, bb = blockIdx.z;

    const size_t headoff = (size_t)hh * 64;

    const int kr0 = tid >> 3;
    const int kch = tid & 7;
    const uint32_t kso0 = (uint32_t)kr0 * FROW + kch * 16;
    const uint32_t kso1 = (uint32_t)(kr0 + 32) * FROW + kch * 16;

    // Prologue: stage Qh in [0,QARR), Ql in ring buffer 2 area.
    const uint32_t qlbase = QARR + 2 * KVBUF;
#pragma unroll
    for (int i = 0; i < 4; i++) {
        const int idx = tid + 256 * i;
        const int r = idx >> 3, ch = idx & 7;
        const size_t g = (size_t)(bb * Sn + qt * 128 + r) * Dn + headoff + ch * 8;
        const uint32_t so = r * FROW + ch * 16;
        *(uint4*)(sm + so)          = *(const uint4*)(g_Qh + g);
        *(uint4*)(sm + qlbase + so) = *(const uint4*)(g_Ql + g);
    }
    KV_PREFETCH(0, 0);
    KV_PREFETCH(1, 1);
    __syncthreads();

    const int lrow = lane & 15;
    const int lch  = lane >> 4;
    const uint32_t aoff = (uint32_t)(w * 16 + lrow) * FROW + lch * 16;
    uint32_t boff[4];
#pragma unroll
    for (int np = 0; np < 4; np++)
        boff[np] = (uint32_t)(np * 16 + lrow) * FROW + lch * 16;

    // Hoist BOTH Q hi and lo fragments to registers.
    uint32_t qhf[4][4], qlf[4][4];
#pragma unroll
    for (int ks = 0; ks < 4; ks++) {
        ldm_x4(qhf[ks], sb + aoff + ks * 32);
        ldm_x4(qlf[ks], sb + qlbase + aoff + ks * 32);
    }

    float o[8][4];
#pragma unroll
    for (int j = 0; j < 8; j++)
#pragma unroll
        for (int k = 0; k < 4; k++) o[j][k] = 0.f;
    float m0r = -1e30f, m1r = -1e30f, l0r = 0.f, l1r = 0.f;

    for (int kt = 0; kt < Sn / 64; kt++) {
        if (kt + 1 < Sn / 64) { CP_WAIT1(); } else { CP_WAIT0(); }
        __syncthreads();   // stage kt resident; prior reads (incl. q frags) done

        if (kt + 2 < Sn / 64)
            KV_PREFETCH(kt + 2, (kt + 2) % 3);

        const uint32_t kvb = sb + QARR + (uint32_t)(kt % 3) * KVBUF;

        // ---- S = Q*K^T (3 split terms), n=64 keys ----
        float s[8][4];
#pragma unroll
        for (int j = 0; j < 8; j++)
#pragma unroll
            for (int k = 0; k < 4; k++) s[j][k] = 0.f;

#pragma unroll
        for (int ks = 0; ks < 4; ks++) {
#pragma unroll
            for (int np = 0; np < 4; np++) {
                uint32_t kh[4], kl[4];
                ldm_x4(kh, kvb + 0 * FARR + boff[np] + ks * 32);
                ldm_x4(kl, kvb + 1 * FARR + boff[np] + ks * 32);
                mma_bf16(s[2 * np + 0], qhf[ks], kh[0], kh[2]);
                mma_bf16(s[2 * np + 1], qhf[ks], kh[1], kh[3]);
                mma_bf16(s[2 * np + 0], qhf[ks], kl[0], kl[2]);
                mma_bf16(s[2 * np + 1], qhf[ks], kl[1], kl[3]);
                mma_bf16(s[2 * np + 0], qlf[ks], kh[0], kh[2]);
                mma_bf16(s[2 * np + 1], qlf[ks], kh[1], kh[3]);
            }
        }

        // ---- Online softmax, log2 domain ----
        float mx0 = -1e30f, mx1 = -1e30f;
#pragma unroll
        for (int j = 0; j < 8; j++) {
            mx0 = fmaxf(mx0, fmaxf(s[j][0], s[j][1]));
            mx1 = fmaxf(mx1, fmaxf(s[j][2], s[j][3]));
        }
        mx0 = fmaxf(mx0, __shfl_xor_sync(0xffffffffu, mx0, 1));
        mx0 = fmaxf(mx0, __shfl_xor_sync(0xffffffffu, mx0, 2));
        mx1 = fmaxf(mx1, __shfl_xor_sync(0xffffffffu, mx1, 1));
        mx1 = fmaxf(mx1, __shfl_xor_sync(0xffffffffu, mx1, 2));

        const float mn0 = fmaxf(m0r, mx0);
        const float mn1 = fmaxf(m1r, mx1);
        float a0 = 1.0f, a1 = 1.0f;
        const bool upd = (mn0 > m0r) || (mn1 > m1r);
        if (__any_sync(0xffffffffu, upd)) {
            a0 = fast_ex2(m0r - mn0);
            a1 = fast_ex2(m1r - mn1);
#pragma unroll
            for (int j = 0; j < 8; j++) {
                o[j][0] *= a0; o[j][1] *= a0;
                o[j][2] *= a1; o[j][3] *= a1;
            }
        }
        m0r = mn0; m1r = mn1;

        // ---- PV with JIT exp + pack; accumulate prob sums in-loop ----
        float sum0 = 0.f, sum1 = 0.f;
#pragma unroll
        for (int ks = 0; ks < 4; ks++) {
            uint32_t ap[4];
#pragma unroll
            for (int jj = 0; jj < 2; jj++) {
                const int j = 2 * ks + jj;
                float p00 = fast_ex2(s[j][0] - mn0);
                float p01 = fast_ex2(s[j][1] - mn0);
                float p10 = fast_ex2(s[j][2] - mn1);
                float p11 = fast_ex2(s[j][3] - mn1);
                sum0 += p00 + p01;
                sum1 += p10 + p11;
                ap[jj * 2 + 0] = pack_f16x2(p00, p01);
                ap[jj * 2 + 1] = pack_f16x2(p10, p11);
            }
            const uint32_t vbase = (uint32_t)(ks * 16 + lrow) * FROW + lch * 16;
#pragma unroll
            for (int np = 0; np < 4; np++) {
                uint32_t vf[4];
                ldm_x4t(vf, kvb + 2 * FARR + vbase + np * 32);
                mma_fp16(o[2 * np + 0], ap, vf[0], vf[1]);
                mma_fp16(o[2 * np + 1], ap, vf[2], vf[3]);
            }
        }
        sum0 += __shfl_xor_sync(0xffffffffu, sum0, 1);
        sum0 += __shfl_xor_sync(0xffffffffu, sum0, 2);
        sum1 += __shfl_xor_sync(0xffffffffu, sum1, 1);
        sum1 += __shfl_xor_sync(0xffffffffu, sum1, 2);
        l0r = l0r * a0 + sum0;
        l1r = l1r * a1 + sum1;
    }

    // Epilogue: normalize, split to fp16 hi/lo, write AV
    const float inv0 = 1.0f / l0r;
    const float inv1 = 1.0f / l1r;
    const size_t row0 = (size_t)(bb * Sn + qt * 128 + w * 16 + (lane >> 2));
    const size_t row1 = row0 + 8;
    const size_t colb = headoff + (lane & 3) * 2;
#pragma unroll
    for (int j = 0; j < 8; j++) {
        float v0 = o[j][0] * inv0, v1 = o[j][1] * inv0;
        float v2 = o[j][2] * inv1, v3 = o[j][3] * inv1;
        __half h0 = __float2half_rn(v0);
        __half h1 = __float2half_rn(v1);
        __half h2 = __float2half_rn(v2);
        __half h3 = __float2half_rn(v3);
        size_t b0 = row0 * Dn + colb + j * 8;
        size_t b1 = row1 * Dn + colb + j * 8;
        *(__half2*)(g_AVfh + b0) = __halves2half2(h0, h1);
        *(__half2*)(g_AVfh + b1) = __halves2half2(h2, h3);
        *(__half2*)(g_AVfl + b0) =
            __halves2half2(__float2half_rn(v0 - __half2float(h0)),
                           __float2half_rn(v1 - __half2float(h1)));
        *(__half2*)(g_AVfl + b1) =
            __halves2half2(__float2half_rn(v2 - __half2float(h2)),
                           __float2half_rn(v3 - __half2float(h3)));
    }
}

// ---------------------------------------------------------------------------
// Residual + LayerNorm
// ---------------------------------------------------------------------------
__global__ __launch_bounds__(256) void ln_residual(
    const float* __restrict__ h, const float* __restrict__ gamma,
    const float* __restrict__ beta, float* __restrict__ out)
{
    const int row = blockIdx.x;
    const int tid = threadIdx.x;

    const float4 hv = *(const float4*)(h + row * Dn + tid * 4);
    const float4 av = *(const float4*)(g_AO + row * Dn + tid * 4);
    float4 x = make_float4(hv.x + av.x, hv.y + av.y, hv.z + av.z, hv.w + av.w);

    float s  = x.x + x.y + x.z + x.w;
    float ss = x.x * x.x + x.y * x.y + x.z * x.z + x.w * x.w;
#pragma unroll
    for (int off = 16; off > 0; off >>= 1) {
        s  += __shfl_xor_sync(0xffffffffu, s, off);
        ss += __shfl_xor_sync(0xffffffffu, ss, off);
    }
    __shared__ float rs[8], rss[8];
    if ((tid & 31) == 0) { rs[tid >> 5] = s; rss[tid >> 5] = ss; }
    __syncthreads();
    s = 0.f; ss = 0.f;
#pragma unroll
    for (int w = 0; w < 8; w++) { s += rs[w]; ss += rss[w]; }

    const float mu  = s * (1.0f / Dn);
    const float var = ss * (1.0f / Dn) - mu * mu;
    const float inv = rsqrtf(var + 1e-5f);

    const float4 g4 = *(const float4*)(gamma + tid * 4);
    const float4 b4 = *(const float4*)(beta + tid * 4);
    float4 r;
    r.x = g4.x * (x.x - mu) * inv + b4.x;
    r.y = g4.y * (x.y - mu) * inv + b4.y;
    r.z = g4.z * (x.z - mu) * inv + b4.z;
    r.w = g4.w * (x.w - mu) * inv + b4.w;
    *(float4*)(out + row * Dn + tid * 4) = r;
}

// ---------------------------------------------------------------------------
extern "C" void kernel_launch(void* const* d_in, const int* in_sizes, int n_in,
                              void* d_out, int out_size)
{
    (void)in_sizes; (void)n_in; (void)out_size;
    const float* h     = (const float*)d_in[0];
    const float* Wq    = (const float*)d_in[1];
    const float* Wk    = (const float*)d_in[2];
    const float* Wv    = (const float*)d_in[3];
    const float* Wo    = (const float*)d_in[4];
    const float* gamma = (const float*)d_in[5];
    const float* beta  = (const float*)d_in[6];
    float* out = (float*)d_out;

    float* AOp;
    __nv_bfloat16 *hAhi, *hAlo, *Whi, *Wlo, *Qh, *Ql, *Kh, *Kl;
    __half *hFhi, *hFlo, *Wf, *Vf, *AVfh, *AVfl;
    cudaGetSymbolAddress((void**)&AOp,  g_AO);
    cudaGetSymbolAddress((void**)&hAhi, g_hA_hi);
    cudaGetSymbolAddress((void**)&hAlo, g_hA_lo);
    cudaGetSymbolAddress((void**)&hFhi, g_hF_hi);
    cudaGetSymbolAddress((void**)&hFlo, g_hF_lo);
    cudaGetSymbolAddress((void**)&Whi,  g_W_hi);
    cudaGetSymbolAddress((void**)&Wlo,  g_W_lo);
    cudaGetSymbolAddress((void**)&Wf,   g_Wf);
    cudaGetSymbolAddress((void**)&Qh,   g_Qh);
    cudaGetSymbolAddress((void**)&Ql,   g_Ql);
    cudaGetSymbolAddress((void**)&Kh,   g_Kh);
    cudaGetSymbolAddress((void**)&Kl,   g_Kl);
    cudaGetSymbolAddress((void**)&Vf,   g_Vf);
    cudaGetSymbolAddress((void**)&AVfh, g_AVfh);
    cudaGetSymbolAddress((void**)&AVfl, g_AVfl);

    cudaFuncSetAttribute(gemm_qkv, cudaFuncAttributeMaxDynamicSharedMemorySize,
                         GEMM_SMEM);
    cudaFuncSetAttribute(gemm_o, cudaFuncAttributeMaxDynamicSharedMemorySize,
                         GEMM_SMEM);
    cudaFuncSetAttribute(flash_mma, cudaFuncAttributeMaxDynamicSharedMemorySize,
                         FLASH_SMEM);

    // Split h (bf16 + fp16 pairs) and weights
    split_h<<<Mn * Dn / 1024, 256>>>(h, hAhi, hAlo, hFhi, hFlo);
    split_T4<<<dim3(32, 32, 4), dim3(32, 8)>>>(Wq, Wk, Wv, Wo, Whi, Wlo, Wf);

    // Fused Q/K/V projections (Q pre-scaled by 1/8 * log2(e); V 2-term fp16)
    const float QSCALE = 0.125f * 1.4426950408889634f;
    gemm_qkv<<<dim3(24, Mn / 128), 256, GEMM_SMEM>>>(
        hAhi, hAlo, hFhi, hFlo, Whi, Wlo, Wf, Qh, Ql, Kh, Kl, Vf, QSCALE);

    // Attention (tensorized flash, 3-stage KV ring, fp16 PV)
    flash_mma<<<dim3(Sn / 128, Hn, Bn), 256, FLASH_SMEM>>>();

    // Output projection (2-term fp16, 3-stage ring)
    gemm_o<<<dim3(Dn / 128, Mn / 128), 256, GEMM_SMEM>>>(
        AVfh, AVfl, Wf + (size_t)Dn * Dn, AOp);

    ln_residual<<<Mn, 256>>>(h, gamma, beta, out);
}